// round 8
// baseline (speedup 1.0000x reference)
#include <cuda_runtime.h>
#include <cuda_fp16.h>
#include <math.h>
#include <stdint.h>

#define Bv  4
#define Tv  1024
#define Cv  1024
#define NH  16
#define NKV 4
#define HD  64
#define FFH 4096
#define MT  (Bv*Tv)

typedef __half h16;

// ---------------- fp32 scratch ----------------
__device__ float g_xn  [MT*Cv];
__device__ float g_qkv [MT*1536];
__device__ float g_attn[MT*Cv];
__device__ float g_ca  [MT*Cv];
__device__ float g_cah [MT*32];
__device__ float g_cah2[MT*32];
__device__ float g_x1  [MT*Cv];
__device__ float g_mlp [MT*Cv];
__device__ float g_gate[MT*Cv];
__device__ float g_vit32[MT*32];
__device__ float g_vitv[MT];
__device__ float g_vitf[MT];

// ---------------- fp16 scratch (all single-precision-split-free) ----------------
__device__ h16 g_xn_h[MT*Cv];
__device__ h16 g_xm_h[MT*Cv];
__device__ h16 g_y_h [MT*Cv];
__device__ h16 g_q_h [MT*1024];                  // (b,t,h,d)
__device__ h16 g_k_h [MT*256];                   // (b,t,kv,d)
__device__ h16 g_v_h [MT*256];                   // (b,kv,d,t)
__device__ h16 g_hf  [(size_t)MT*FFH];           // (b,f,t)
__device__ h16 g_hs  [(size_t)MT*FFH];           // (b,t,f)
__device__ h16 g_wqkv[1536*1024];
__device__ h16 g_wo  [1024*1024];
__device__ h16 g_fin [FFH*1024];
__device__ h16 g_fout[1024*FFH];
__device__ h16 g_fgt [1024*1024];

// =================== helpers ===================
__device__ __forceinline__ uint32_t smem_u32(const void* p){
    uint32_t a;
    asm("{ .reg .u64 t; cvta.to.shared.u64 t, %1; cvt.u32.u64 %0, t; }" : "=r"(a) : "l"(p));
    return a;
}
__device__ __forceinline__ void mma16816(float* c, const uint32_t* a, uint32_t b0, uint32_t b1){
    asm volatile("mma.sync.aligned.m16n8k16.row.col.f32.f16.f16.f32 "
        "{%0,%1,%2,%3}, {%4,%5,%6,%7}, {%8,%9}, {%0,%1,%2,%3};"
        : "+f"(c[0]), "+f"(c[1]), "+f"(c[2]), "+f"(c[3])
        : "r"(a[0]), "r"(a[1]), "r"(a[2]), "r"(a[3]), "r"(b0), "r"(b1));
}
__device__ __forceinline__ void ldsm4(uint32_t* r, uint32_t addr){
    asm volatile("ldmatrix.sync.aligned.m8n8.x4.shared.b16 {%0,%1,%2,%3}, [%4];"
        : "=r"(r[0]), "=r"(r[1]), "=r"(r[2]), "=r"(r[3]) : "r"(addr));
}
__device__ __forceinline__ void cpa16(uint32_t saddr, const void* g){
    asm volatile("cp.async.cg.shared.global [%0], [%1], 16;" :: "r"(saddr), "l"(g));
}
__device__ __forceinline__ void cpa4z(uint32_t saddr, const void* g, int srcsz){
    asm volatile("cp.async.ca.shared.global [%0], [%1], 4, %2;" :: "r"(saddr), "l"(g), "r"(srcsz));
}
#define CPA_COMMIT() asm volatile("cp.async.commit_group;" ::: "memory")
#define CPA_WAIT(n)  asm volatile("cp.async.wait_group %0;" :: "n"(n) : "memory")

__device__ __forceinline__ uint32_t sw_off(int row, int k){
    int chunk = (k >> 3) ^ ((row >> 1) & 3);
    return (uint32_t)(row*64 + chunk*16 + (k & 7)*2);
}
__device__ __forceinline__ uint32_t sw128(int row, int k){
    return (uint32_t)(row*128 + ((((k>>3) ^ (row & 7)) << 4) | ((k & 7) << 1)));
}
__device__ __forceinline__ uint32_t pack2(h16 a, h16 b){
    return ((uint32_t)__half_as_ushort(b) << 16) | __half_as_ushort(a);
}

// ---------------- fp32 -> fp16 convert ----------------
__global__ void cvt_kernel(const float* __restrict__ src, h16* __restrict__ dst, int n4){
    int i0 = blockIdx.x*1024 + threadIdx.x;
    #pragma unroll
    for (int j = 0; j < 4; j++){
        int i = i0 + (j << 8);
        if (i < n4){
            float4 v = ((const float4*)src)[i];
            ((uint2*)dst)[i] = make_uint2(
                pack2(__float2half_rn(v.x), __float2half_rn(v.y)),
                pack2(__float2half_rn(v.z), __float2half_rn(v.w)));
        }
    }
}

// ---------------- rmsnorm (fp32 + fp16) ----------------
template<int WF32>
__global__ void rms_kernel(const float* __restrict__ x, float* __restrict__ o32,
                           h16* __restrict__ ohi){
    int row = blockIdx.x;
    const float* xr = x + (size_t)row*Cv;
    float ss = 0.f;
    float v[4];
    #pragma unroll
    for (int j=0;j<4;j++){ v[j] = xr[threadIdx.x + (j<<8)]; ss += v[j]*v[j]; }
    __shared__ float red[8];
    for (int off=16; off>0; off>>=1) ss += __shfl_xor_sync(0xffffffffu, ss, off);
    if ((threadIdx.x & 31) == 0) red[threadIdx.x>>5] = ss;
    __syncthreads();
    if (threadIdx.x < 8){
        float t = red[threadIdx.x];
        for (int off=4; off>0; off>>=1) t += __shfl_xor_sync(0x000000ffu, t, off);
        if (threadIdx.x == 0) red[0] = t;
    }
    __syncthreads();
    float r = rsqrtf(red[0]*(1.0f/Cv) + 1e-6f);
    #pragma unroll
    for (int j=0;j<4;j++){
        int i = threadIdx.x + (j<<8);
        float vv = v[j]*r;
        if (WF32) o32[(size_t)row*Cv + i] = vv;
        ohi[(size_t)row*Cv + i] = __float2half_rn(vv);
    }
}

// ---------------- fused x1 + rmsnorm ----------------
__global__ void x1rms_kernel(const float* __restrict__ x, const float* __restrict__ attn,
                             const float* __restrict__ ca, float* __restrict__ x1,
                             h16* __restrict__ ohi){
    int row = blockIdx.x;
    size_t base = (size_t)row*Cv;
    float v[4]; float ss = 0.f;
    #pragma unroll
    for (int j=0;j<4;j++){
        int i = threadIdx.x + (j<<8);
        float vv = x[base+i] + attn[base+i]*(1.f + 0.1f*tanhf(ca[base+i]));
        v[j] = vv; ss += vv*vv;
    }
    __shared__ float red[8];
    for (int off=16; off>0; off>>=1) ss += __shfl_xor_sync(0xffffffffu, ss, off);
    if ((threadIdx.x & 31) == 0) red[threadIdx.x>>5] = ss;
    __syncthreads();
    if (threadIdx.x < 8){
        float t = red[threadIdx.x];
        for (int off=4; off>0; off>>=1) t += __shfl_xor_sync(0x000000ffu, t, off);
        if (threadIdx.x == 0) red[0] = t;
    }
    __syncthreads();
    float r = rsqrtf(red[0]*(1.0f/Cv) + 1e-6f);
    #pragma unroll
    for (int j=0;j<4;j++){
        int i = threadIdx.x + (j<<8);
        x1[base+i] = v[j];
        ohi[base+i] = __float2half_rn(v[j]*r);
    }
}

// =================== fp16 GEMM: C = A*B^T; tile 128x256, 4-stage cp.async ===================
// stage: A 8K @0, B 16K @8192 => 24KB, 4 stages
#define GSTG 24576
#define GEMM_SMEM (4*GSTG)
template<int EPI>
__global__ void __launch_bounds__(512,1)
gemm_f16(const h16* __restrict__ Ah, const h16* __restrict__ Bh,
         float* __restrict__ Cg, h16* __restrict__ Chf, int N, int K){
    extern __shared__ char smem[];
    const int tid = threadIdx.x, lane = tid & 31, wid = tid >> 5;
    const int warpM = wid & 3, warpN = wid >> 2;
    const int m0 = blockIdx.y << 7, n0 = blockIdx.x << 8;
    const int b = m0 >> 10, tb = m0 & 1023;
    uint32_t sb = smem_u32(smem);

    const int r = tid >> 2, kc = tid & 3;
    const h16* aP  = Ah + (size_t)(m0+r)*K + (kc<<3);
    const h16* bP0 = Bh + (size_t)(n0+r)*K + (kc<<3);
    const h16* bP1 = Bh + (size_t)(n0+r+128)*K + (kc<<3);
    const uint32_t dA  = sw_off(r, kc<<3);
    const uint32_t dB1 = sw_off(r+128, kc<<3);

    auto ISSUE = [&](int c, int s){
        int k0 = c << 5;
        uint32_t st = sb + s*GSTG;
        cpa16(st + dA,         aP + k0);
        cpa16(st + 8192 + dA,  bP0 + k0);
        cpa16(st + 8192 + dB1, bP1 + k0);
        CPA_COMMIT();
    };

    float acc[2][8][4];
    #pragma unroll
    for (int i=0;i<2;i++)
        #pragma unroll
        for (int j=0;j<8;j++)
            #pragma unroll
            for (int q=0;q<4;q++) acc[i][j][q]=0.f;

    const int NC = K >> 5;
    ISSUE(0,0); ISSUE(1,1); ISSUE(2,2);
    const int lr = lane & 15, lc = (lane < 16) ? 0 : 8;
    for (int c = 0; c < NC; c++){
        int rem = NC - 1 - c;
        if (rem >= 2) { CPA_WAIT(2); } else if (rem == 1) { CPA_WAIT(1); } else { CPA_WAIT(0); }
        __syncthreads();
        if (c + 3 < NC) ISSUE(c+3, (c+3)&3);
        uint32_t sA = sb + (c&3)*GSTG;
        #pragma unroll
        for (int kk = 0; kk < 32; kk += 16){
            uint32_t ah[2][4];
            #pragma unroll
            for (int mt=0; mt<2; mt++)
                ldsm4(ah[mt], sA + sw_off(warpM*32 + mt*16 + lr, kk + lc));
            #pragma unroll
            for (int nb=0; nb<4; nb++){
                uint32_t bh[4];
                ldsm4(bh, sA + 8192 + sw_off(warpN*64 + nb*16 + lr, kk + lc));
                #pragma unroll
                for (int mt=0; mt<2; mt++){
                    mma16816(acc[mt][nb*2+0], ah[mt], bh[0], bh[2]);
                    mma16816(acc[mt][nb*2+1], ah[mt], bh[1], bh[3]);
                }
            }
        }
    }

    const int g = lane >> 2, t2 = (lane & 3) << 1;
    if (EPI == 0){
        #pragma unroll
        for (int mt=0; mt<2; mt++){
            int m = m0 + warpM*32 + mt*16 + g;
            #pragma unroll
            for (int ni=0; ni<8; ni++){
                int n = n0 + warpN*64 + ni*8 + t2;
                *(float2*)(Cg + (size_t)m*N + n) = make_float2(acc[mt][ni][0], acc[mt][ni][1]);
                *(float2*)(Cg + (size_t)(m+8)*N + n) = make_float2(acc[mt][ni][2], acc[mt][ni][3]);
            }
        }
    } else {
        float* ep = (float*)smem;   // 64 x 136
        #pragma unroll
        for (int slab=0; slab<4; slab++){
            __syncthreads();
            if (warpN == slab){
                #pragma unroll
                for (int mt=0; mt<2; mt++){
                    int mloc = warpM*32 + mt*16 + g;
                    #pragma unroll
                    for (int ni=0; ni<8; ni++){
                        int nL = ni*8 + t2;
                        ep[nL*136 + mloc]         = acc[mt][ni][0];
                        ep[(nL+1)*136 + mloc]     = acc[mt][ni][1];
                        ep[nL*136 + mloc + 8]     = acc[mt][ni][2];
                        ep[(nL+1)*136 + mloc + 8] = acc[mt][ni][3];
                    }
                }
            }
            __syncthreads();
            #pragma unroll
            for (int i=0;i<4;i++){
                int idx = tid + (i << 9);
                int nr = idx >> 5, t4 = (idx & 31) << 2;
                float a0 = fmaxf(ep[nr*136 + t4 + 0], 0.f);
                float a1 = fmaxf(ep[nr*136 + t4 + 1], 0.f);
                float a2 = fmaxf(ep[nr*136 + t4 + 2], 0.f);
                float a3 = fmaxf(ep[nr*136 + t4 + 3], 0.f);
                int n = n0 + slab*64 + nr;
                size_t o = ((size_t)b*N + n)*1024 + tb + t4;
                *(uint2*)(Chf + o) = make_uint2(
                    pack2(__float2half_rn(a0*a0), __float2half_rn(a1*a1)),
                    pack2(__float2half_rn(a2*a2), __float2half_rn(a3*a3)));
            }
        }
    }
}

// ---------------- small-N (=32) GEMM ----------------
template<int EPI>
__global__ void __launch_bounds__(256)
gemm32_kernel(const float* __restrict__ A, const float* __restrict__ W, float* __restrict__ Cg){
    __shared__ float xs[8*1024];
    int row0 = blockIdx.x << 3;
    #pragma unroll
    for (int i = 0; i < 8; i++){
        int f4 = threadIdx.x + (i << 8);
        ((float4*)xs)[f4] = ((const float4*)(A + ((size_t)row0 << 10)))[f4];
    }
    __syncthreads();
    int w = threadIdx.x >> 5, n = threadIdx.x & 31;
    const float4* Wr = (const float4*)(W + (size_t)n*1024);
    const float4* xr = (const float4*)(xs + (w << 10));
    float acc = 0.f;
    #pragma unroll 4
    for (int k = 0; k < 256; k++){
        float4 a = xr[k], b = Wr[k];
        acc += a.x*b.x + a.y*b.y + a.z*b.z + a.w*b.w;
    }
    if (EPI == 2) acc = 0.5f*acc*(1.f + erff(acc*0.70710678118f));
    Cg[((size_t)(row0 + w) << 5) + n] = acc;
}

// ---------------- FFMA GEMM (ca_po, K=32) ----------------
__global__ void __launch_bounds__(256,2)
gemm_k32(const float* __restrict__ A, const float* __restrict__ W,
         float* __restrict__ Cg, int N){
    __shared__ float As[32*132];
    __shared__ float Ws[32*132];
    const int tx = threadIdx.x & 15, ty = threadIdx.x >> 4;
    const int m0 = blockIdx.y << 7, n0 = blockIdx.x << 7;
    float acc[8][8];
    #pragma unroll
    for (int i=0;i<8;i++)
        #pragma unroll
        for (int j=0;j<8;j++) acc[i][j]=0.f;
    const int r = threadIdx.x >> 1;
    const int c4 = (threadIdx.x & 1) << 4;
    #pragma unroll
    for (int q=0;q<4;q++){
        float4 a0 = *(const float4*)(A + (size_t)(m0+r)*32 + c4 + q*4);
        As[(c4+q*4+0)*132 + r] = a0.x; As[(c4+q*4+1)*132 + r] = a0.y;
        As[(c4+q*4+2)*132 + r] = a0.z; As[(c4+q*4+3)*132 + r] = a0.w;
        float4 w0 = *(const float4*)(W + (size_t)(n0+r)*32 + c4 + q*4);
        Ws[(c4+q*4+0)*132 + r] = w0.x; Ws[(c4+q*4+1)*132 + r] = w0.y;
        Ws[(c4+q*4+2)*132 + r] = w0.z; Ws[(c4+q*4+3)*132 + r] = w0.w;
    }
    __syncthreads();
    #pragma unroll
    for (int kk=0; kk<32; kk++){
        float av[8], bv[8];
        *(float4*)&av[0] = *(const float4*)(As + kk*132 + (ty<<3));
        *(float4*)&av[4] = *(const float4*)(As + kk*132 + (ty<<3) + 4);
        *(float4*)&bv[0] = *(const float4*)(Ws + kk*132 + (tx<<3));
        *(float4*)&bv[4] = *(const float4*)(Ws + kk*132 + (tx<<3) + 4);
        #pragma unroll
        for (int i=0;i<8;i++)
            #pragma unroll
            for (int j=0;j<8;j++) acc[i][j] += av[i]*bv[j];
    }
    #pragma unroll
    for (int i=0;i<8;i++){
        int mg = m0 + (ty<<3) + i;
        #pragma unroll
        for (int j=0;j<8;j++)
            Cg[(size_t)mg*N + n0 + (tx<<3) + j] = acc[i][j];
    }
}

// ---------------- VE gate + V -> transposed fp16 ----------------
__global__ void vgate_kernel(const float* __restrict__ xn, const float* __restrict__ ve,
                             const float* __restrict__ wg, const float* __restrict__ qkv,
                             h16* __restrict__ vhi){
    int row = blockIdx.x;
    __shared__ float gs[4];
    if (threadIdx.x < 4){
        float s = 0.f;
        #pragma unroll
        for (int c=0;c<12;c++) s += xn[(size_t)row*Cv + c]*wg[threadIdx.x*12 + c];
        gs[threadIdx.x] = 3.f/(1.f + expf(-s));
    }
    __syncthreads();
    int i = threadIdx.x;
    int kv = i >> 6, d = i & 63;
    float vv = qkv[(size_t)row*1536 + 1280 + i] + gs[kv]*ve[(size_t)row*256 + i];
    size_t o = ((size_t)((row>>10)*4 + kv)*64 + d)*1024 + (row & 1023);
    vhi[o] = __float2half_rn(vv);
}

// ---------------- rope + per-head rmsnorm*1.2 -> fp16 ----------------
__global__ void ropeRms_kernel(const float* __restrict__ src, int srcStride, int srcOff,
                               h16* __restrict__ dhi,
                               const float* __restrict__ cosb, const float* __restrict__ sinb,
                               int nheads){
    int row  = blockIdx.x;
    int t    = row & (Tv-1);
    int head = blockIdx.y*4 + (threadIdx.x >> 5);
    if (head >= nheads) return;
    int lane = threadIdx.x & 31;
    const float* p = src + (size_t)row*srcStride + srcOff + head*HD;
    float x1 = p[lane], x2 = p[lane+32];
    float cc = cosb[t*32 + lane], sn = sinb[t*32 + lane];
    float o1 =  x1*cc + x2*sn;
    float o2 = -x1*sn + x2*cc;
    float ss = o1*o1 + o2*o2;
    for (int off=16; off>0; off>>=1) ss += __shfl_xor_sync(0xffffffffu, ss, off);
    float rr = rsqrtf(ss*(1.0f/HD) + 1e-6f)*1.2f;
    size_t base = ((size_t)row*nheads + head)*HD;
    dhi[base+lane]    = __float2half_rn(o1*rr);
    dhi[base+lane+32] = __float2half_rn(o2*rr);
}

// =================== flash attention: single-fp16 QK and PV ===================
#define SM_Q    0
#define SM_KV0  8192
#define SM_KV1  24576
#define SM_PP0  40960
#define SM_PP1  58752
#define SM_S    76544
#define SM_PHI  95488
#define SM_CORR 103680
#define SM_LINV 103936
#define ATTN_SMEM 104192

__global__ void __launch_bounds__(256)
attn_kernel(const h16* __restrict__ qhi,
            const h16* __restrict__ khi, const h16* __restrict__ vhi,
            const float* __restrict__ prev, const float* __restrict__ rw,
            const float* __restrict__ alphap,
            h16* __restrict__ yh){
    extern __shared__ char smc[];
    uint32_t sb = smem_u32(smc);
    float* S      = (float*)(smc + SM_S);
    float* corr_s = (float*)(smc + SM_CORR);
    float* linv   = (float*)(smc + SM_LINV);

    const int tid = threadIdx.x, lane = tid & 31, wid = tid >> 5;
    const int warpM = wid & 3, warpN = wid >> 2;
    const int row = tid >> 2, quad = tid & 3, c0 = quad << 4;
    const int qt = blockIdx.x, h = blockIdx.y, b = blockIdx.z;
    const int q0 = qt << 6;
    const int kvh = h >> 2;
    const int lr = lane & 15, lc = (lane < 16) ? 0 : 8;
    const int g = lane >> 2, t2 = (lane & 3) << 1;

    const float alpha = alphap[0];
    float w9[9];
    #pragma unroll
    for (int i=0;i<9;i++) w9[i] = alpha*rw[h*9 + i];

    const float* prevB = prev + ((size_t)(b*NH + h))*Tv*Tv;

    auto issueKV = [&](int kt, int s){
        int k0 = kt << 6;
        uint32_t kvb = sb + SM_KV0 + s*16384;
        #pragma unroll
        for (int i=0;i<4;i++){
            int idx = tid + (i << 8);
            int arr = idx >> 9, rr = (idx >> 3) & 63, kc = idx & 7;
            const h16* src;
            if (arr == 0) src = khi + ((((size_t)(b*Tv + k0 + rr))*NKV + kvh) << 6) + (kc << 3);
            else          src = vhi + (((size_t)((b*NKV + kvh)*64 + rr)) << 10) + k0 + (kc << 3);
            cpa16(kvb + arr*8192 + sw128(rr, kc << 3), src);
        }
    };
    auto issuePP = [&](int kt, int s){
        int k0 = kt << 6;
        uint32_t ppb = sb + SM_PP0 + s*17792;
        for (int idx = tid; idx < 66*66; idx += 256){
            int i = idx/66, j = idx - i*66;
            int rr = q0 - 1 + i, cg = k0 - 1 + j;
            int ok = (rr >= 0 && rr < Tv && cg >= 0 && cg < Tv) ? 4 : 0;
            int rrc = rr < 0 ? 0 : (rr > 1023 ? 1023 : rr);
            int cgc = cg < 0 ? 0 : (cg > 1023 ? 1023 : cg);
            cpa4z(ppb + (uint32_t)(i*67 + j)*4, prevB + (size_t)rrc*Tv + cgc, ok);
        }
    };

    {
        #pragma unroll
        for (int i=0;i<2;i++){
            int idx = tid + (i << 8);
            int rr = idx >> 3, kc = idx & 7;
            const h16* src = qhi + ((((size_t)(b*Tv + q0 + rr))*NH + h) << 6) + (kc << 3);
            cpa16(sb + SM_Q + sw128(rr, kc << 3), src);
        }
        CPA_COMMIT();
        issueKV(0,0); issuePP(0,0);
        CPA_COMMIT();
    }

    float o[4][4];
    #pragma unroll
    for (int i=0;i<4;i++)
        #pragma unroll
        for (int j=0;j<4;j++) o[i][j]=0.f;
    float m = -1e30f, l = 0.f;

    for (int kt = 0; kt <= qt; kt++){
        int s = kt & 1;
        CPA_WAIT(0);
        __syncthreads();
        if (kt < qt){ issueKV(kt+1, s^1); issuePP(kt+1, s^1); CPA_COMMIT(); }
        uint32_t kvb = sb + SM_KV0 + s*16384;
        float* PP = (float*)(smc + SM_PP0 + s*17792);

        // ---- QK^T ----
        float c[4][4];
        #pragma unroll
        for (int i=0;i<4;i++)
            #pragma unroll
            for (int j=0;j<4;j++) c[i][j]=0.f;
        #pragma unroll
        for (int k16 = 0; k16 < 4; k16++){
            uint32_t qh_[4];
            ldsm4(qh_, sb + SM_Q + sw128(warpM*16 + lr, k16*16 + lc));
            #pragma unroll
            for (int nb=0; nb<2; nb++){
                uint32_t kh_[4];
                ldsm4(kh_, kvb + sw128(warpN*32 + nb*16 + lr, k16*16 + lc));
                mma16816(c[nb*2+0], qh_, kh_[0], kh_[2]);
                mma16816(c[nb*2+1], qh_, kh_[1], kh_[3]);
            }
        }
        #pragma unroll
        for (int ni=0; ni<4; ni++){
            int col = warpN*32 + ni*8 + t2;
            int r0 = warpM*16 + g;
            *(float2*)(S + r0*74 + col)     = make_float2(c[ni][0], c[ni][1]);
            *(float2*)(S + (r0+8)*74 + col) = make_float2(c[ni][2], c[ni][3]);
        }
        __syncthreads();

        // ---- conv (register-cached halo) + mask + online softmax ----
        float p[3][18];
        #pragma unroll
        for (int i=0;i<3;i++)
            #pragma unroll
            for (int e=0;e<18;e++) p[i][e] = PP[(row+i)*67 + c0 + e];
        float sr[16];
        #pragma unroll
        for (int j=0;j<16;j++){
            float cv = w9[0]*p[0][j] + w9[1]*p[0][j+1] + w9[2]*p[0][j+2]
                     + w9[3]*p[1][j] + w9[4]*p[1][j+1] + w9[5]*p[1][j+2]
                     + w9[6]*p[2][j] + w9[7]*p[2][j+1] + w9[8]*p[2][j+2];
            int col = c0 + j;
            sr[j] = S[row*74 + col]*0.125f + cv;
            if (kt == qt && col > row) sr[j] = -1e30f;
        }
        float mt = sr[0];
        #pragma unroll
        for (int j=1;j<16;j++) mt = fmaxf(mt, sr[j]);
        for (int off=1; off<4; off<<=1) mt = fmaxf(mt, __shfl_xor_sync(0xffffffffu, mt, off));
        float mnew = fmaxf(m, mt);
        float corrv = __expf(m - mnew);
        float ls = 0.f;
        #pragma unroll
        for (int j=0;j<16;j++){ sr[j] = __expf(sr[j] - mnew); ls += sr[j]; }
        for (int off=1; off<4; off<<=1) ls += __shfl_xor_sync(0xffffffffu, ls, off);
        l = l*corrv + ls;
        m = mnew;
        if (quad == 0) corr_s[row] = corrv;
        #pragma unroll
        for (int j=0;j<16;j+=2){
            int col = c0 + j;
            *(uint32_t*)(smc + SM_PHI + sw128(row, col)) =
                pack2(__float2half_rn(sr[j]), __float2half_rn(sr[j+1]));
        }
        __syncthreads();

        // ---- PV ----
        float cr0 = corr_s[warpM*16 + g], cr1 = corr_s[warpM*16 + g + 8];
        #pragma unroll
        for (int ni=0; ni<4; ni++){
            o[ni][0] *= cr0; o[ni][1] *= cr0;
            o[ni][2] *= cr1; o[ni][3] *= cr1;
        }
        #pragma unroll
        for (int k16 = 0; k16 < 4; k16++){
            uint32_t ph_[4];
            ldsm4(ph_, sb + SM_PHI + sw128(warpM*16 + lr, k16*16 + lc));
            #pragma unroll
            for (int nb=0; nb<2; nb++){
                uint32_t vh_[4];
                ldsm4(vh_, kvb + 8192 + sw128(warpN*32 + nb*16 + lr, k16*16 + lc));
                mma16816(o[nb*2+0], ph_, vh_[0], vh_[2]);
                mma16816(o[nb*2+1], ph_, vh_[1], vh_[3]);
            }
        }
    }

    if (quad == 0) linv[row] = 1.f/l;
    __syncthreads();
    float i0 = linv[warpM*16 + g], i1 = linv[warpM*16 + g + 8];
    #pragma unroll
    for (int ni=0; ni<4; ni++){
        int col = warpN*32 + ni*8 + t2;
        size_t base0 = ((((size_t)(b*Tv + q0 + warpM*16 + g))*NH + h) << 6) + col;
        size_t base1 = ((((size_t)(b*Tv + q0 + warpM*16 + g + 8))*NH + h) << 6) + col;
        *(uint32_t*)(yh + base0) = pack2(__float2half_rn(o[ni][0]*i0), __float2half_rn(o[ni][1]*i0));
        *(uint32_t*)(yh + base1) = pack2(__float2half_rn(o[ni][2]*i1), __float2half_rn(o[ni][3]*i1));
    }
}

// ---------------- CA conv + gelu ----------------
__global__ void caconv_kernel(const float* __restrict__ hin, const float* __restrict__ cw,
                              float* __restrict__ hout){
    int ch = blockIdx.x, b = blockIdx.y;
    __shared__ float s[Tv+2];
    for (int t = threadIdx.x; t < Tv; t += 256) s[1+t] = hin[((size_t)b*Tv + t)*32 + ch];
    if (threadIdx.x == 0){ s[0] = 0.f; s[Tv+1] = 0.f; }
    __syncthreads();
    float w0 = cw[ch*3], w1 = cw[ch*3+1], w2 = cw[ch*3+2];
    for (int t = threadIdx.x; t < Tv; t += 256){
        float vv = s[1+t] + 0.1f*(w0*s[t] + w1*s[1+t] + w2*s[2+t]);
        hout[((size_t)b*Tv + t)*32 + ch] = 0.5f*vv*(1.f + erff(vv*0.70710678118f));
    }
}

// ---------------- FFN conv x4 ----------------
#define FFNC_SMEM (2*16*1026*4)
__global__ void __launch_bounds__(256)
ffnconvT_kernel(const h16* __restrict__ hf, const float* __restrict__ cw,
                h16* __restrict__ hs){
    extern __shared__ float fs[];
    float (*buf0)[1026] = (float(*)[1026])fs;
    float (*buf1)[1026] = (float(*)[1026])(fs + 16*1026);
    int f0 = blockIdx.x << 4, b = blockIdx.y;
    for (int idx4 = threadIdx.x; idx4 < 16*256; idx4 += 256){
        int cch = idx4 >> 8, t4 = (idx4 & 255) << 2;
        size_t o = ((size_t)(b*FFH + f0 + cch))*Tv + t4;
        uint2 u = *(const uint2*)(hf + o);
        const h16* ph = (const h16*)&u;
        #pragma unroll
        for (int e=0;e<4;e++) buf0[cch][1+t4+e] = __half2float(ph[e]);
    }
    if (threadIdx.x < 16){
        buf0[threadIdx.x][0] = 0.f; buf0[threadIdx.x][1025] = 0.f;
        buf1[threadIdx.x][0] = 0.f; buf1[threadIdx.x][1025] = 0.f;
    }
    int cch = threadIdx.x >> 4, j = threadIdx.x & 15;
    float w0 = cw[(f0+cch)*3], w1 = cw[(f0+cch)*3+1], w2 = cw[(f0+cch)*3+2];
    float (*cur)[1026] = buf0; float (*nxt)[1026] = buf1;
    #pragma unroll
    for (int it=0; it<4; it++){
        __syncthreads();
        #pragma unroll 4
        for (int t = j*64; t < j*64 + 64; t++)
            nxt[cch][1+t] = cur[cch][1+t] + 0.1f*(w0*cur[cch][t] + w1*cur[cch][1+t] + w2*cur[cch][2+t]);
        float (*tmp)[1026] = cur; cur = nxt; nxt = tmp;
    }
    __syncthreads();
    for (int t = threadIdx.x; t < Tv; t += 256){
        uint32_t wv[8];
        #pragma unroll
        for (int cc = 0; cc < 16; cc += 2)
            wv[cc>>1] = pack2(__float2half_rn(cur[cc][1+t]), __float2half_rn(cur[cc+1][1+t]));
        size_t o = ((size_t)(b*Tv + t))*FFH + f0;
        *(uint4*)(hs + o)     = make_uint4(wv[0],wv[1],wv[2],wv[3]);
        *(uint4*)(hs + o + 8) = make_uint4(wv[4],wv[5],wv[6],wv[7]);
    }
}

// ---------------- elementwise ----------------
__global__ void vit2_kernel(const float* __restrict__ h32, const float* __restrict__ w2,
                            float* __restrict__ out){
    int row  = blockIdx.x*8 + (threadIdx.x >> 5);
    int lane = threadIdx.x & 31;
    float vv = h32[(size_t)row*32 + lane]*w2[lane];
    for (int off=16; off>0; off>>=1) vv += __shfl_xor_sync(0xffffffffu, vv, off);
    if (lane == 0) out[row] = 1.f/(1.f + expf(-vv));
}
__global__ void vitsmooth_kernel(const float* __restrict__ vin, float* __restrict__ vout){
    int b = blockIdx.x;
    __shared__ float s[Tv+4];
    for (int t = threadIdx.x; t < Tv; t += 256) s[2+t] = vin[b*Tv + t];
    if (threadIdx.x < 2){ s[threadIdx.x] = 0.f; s[Tv+2+threadIdx.x] = 0.f; }
    __syncthreads();
    for (int t = threadIdx.x; t < Tv; t += 256){
        float vs = (s[t] + s[t+1] + s[t+2] + s[t+3] + s[t+4])*0.2f;
        float vv = 0.7f*s[2+t] + 0.3f*vs;
        vout[b*Tv + t] = (vv > 0.3f) ? vv : 0.1f*vv;
    }
}
__global__ void final_kernel(const float* __restrict__ x1, const float* __restrict__ mlp,
                             const float* __restrict__ gate, const float* __restrict__ ca,
                             const float* __restrict__ vitf, float* __restrict__ out, int n){
    for (int i = blockIdx.x*blockDim.x + threadIdx.x; i < n; i += gridDim.x*blockDim.x){
        int row = i >> 10;
        float gg = 1.f/(1.f + expf(-gate[i]));
        out[i] = x1[i] + mlp[i]*gg*(1.f + 0.1f*tanhf(ca[i]))*vitf[row];
    }
}

// ---------------- launch ----------------
extern "C" void kernel_launch(void* const* d_in, const int* in_sizes, int n_in,
                              void* d_out, int out_size){
    const float* x     = (const float*)d_in[0];
    const float* ve    = (const float*)d_in[1];
    const float* cosp  = (const float*)d_in[2];
    const float* sinp  = (const float*)d_in[3];
    const float* prev  = (const float*)d_in[4];
    const float* w_q   = (const float*)d_in[5];
    const float* w_k   = (const float*)d_in[6];
    const float* w_v   = (const float*)d_in[7];
    const float* w_o   = (const float*)d_in[8];
    const float* w_veg = (const float*)d_in[9];
    const float* rfw   = (const float*)d_in[10];
    const float* ralpha= (const float*)d_in[11];
    const float* ca_pi = (const float*)d_in[12];
    const float* ca_cw = (const float*)d_in[13];
    const float* ca_po = (const float*)d_in[14];
    const float* ffn_in= (const float*)d_in[15];
    const float* ffn_cw= (const float*)d_in[16];
    const float* ffn_outw=(const float*)d_in[17];
    const float* ffn_gt= (const float*)d_in[18];
    const float* vit_w1= (const float*)d_in[19];
    const float* vit_w2= (const float*)d_in[20];
    float* out = (float*)d_out;

    float *xn,*qkv,*attn,*ca,*cah,*cah2,*x1,*mlp,*gate,*vit32,*vitv,*vitf;
    h16 *xnh,*xmh,*yh,*qh,*kh,*vh,*hf,*hs;
    h16 *wqkv,*wo,*fin,*fout,*fgt;
    cudaGetSymbolAddress((void**)&xn, g_xn);     cudaGetSymbolAddress((void**)&qkv, g_qkv);
    cudaGetSymbolAddress((void**)&attn, g_attn); cudaGetSymbolAddress((void**)&ca, g_ca);
    cudaGetSymbolAddress((void**)&cah, g_cah);   cudaGetSymbolAddress((void**)&cah2, g_cah2);
    cudaGetSymbolAddress((void**)&x1, g_x1);
    cudaGetSymbolAddress((void**)&mlp, g_mlp);   cudaGetSymbolAddress((void**)&gate, g_gate);
    cudaGetSymbolAddress((void**)&vit32, g_vit32); cudaGetSymbolAddress((void**)&vitv, g_vitv);
    cudaGetSymbolAddress((void**)&vitf, g_vitf);
    cudaGetSymbolAddress((void**)&xnh, g_xn_h);
    cudaGetSymbolAddress((void**)&xmh, g_xm_h);
    cudaGetSymbolAddress((void**)&yh, g_y_h);
    cudaGetSymbolAddress((void**)&qh, g_q_h);
    cudaGetSymbolAddress((void**)&kh, g_k_h);
    cudaGetSymbolAddress((void**)&vh, g_v_h);
    cudaGetSymbolAddress((void**)&hf, g_hf);     cudaGetSymbolAddress((void**)&hs, g_hs);
    cudaGetSymbolAddress((void**)&wqkv, g_wqkv);
    cudaGetSymbolAddress((void**)&wo, g_wo);
    cudaGetSymbolAddress((void**)&fin, g_fin);
    cudaGetSymbolAddress((void**)&fout, g_fout);
    cudaGetSymbolAddress((void**)&fgt, g_fgt);

    cudaFuncSetAttribute(attn_kernel, cudaFuncAttributeMaxDynamicSharedMemorySize, ATTN_SMEM);
    cudaFuncSetAttribute(gemm_f16<0>, cudaFuncAttributeMaxDynamicSharedMemorySize, GEMM_SMEM);
    cudaFuncSetAttribute(gemm_f16<1>, cudaFuncAttributeMaxDynamicSharedMemorySize, GEMM_SMEM);
    cudaFuncSetAttribute(ffnconvT_kernel, cudaFuncAttributeMaxDynamicSharedMemorySize, FFNC_SMEM);

    cvt_kernel<<<256,256>>>(w_q, wqkv, 262144);
    cvt_kernel<<<64,256>>>(w_k, wqkv + 1024*1024, 65536);
    cvt_kernel<<<64,256>>>(w_v, wqkv + 1280*1024, 65536);
    rms_kernel<1><<<MT,256>>>(x, xn, xnh);
    cvt_kernel<<<256,256>>>(w_o, wo, 262144);
    gemm_f16<0><<<dim3(6,32),512,GEMM_SMEM>>>(xnh, wqkv, qkv, 0, 1536, 1024);

    vgate_kernel<<<MT,256>>>(xn, ve, w_veg, qkv, vh);
    ropeRms_kernel<<<dim3(MT,4),128>>>(qkv, 1536, 0,    qh, cosp, sinp, NH);
    ropeRms_kernel<<<dim3(MT,1),128>>>(qkv, 1536, 1024, kh, cosp, sinp, NKV);

    attn_kernel<<<dim3(16,NH,Bv),256,ATTN_SMEM>>>(qh, kh, vh, prev, rfw, ralpha, yh);
    gemm_f16<0><<<dim3(4,32),512,GEMM_SMEM>>>(yh, wo, attn, 0, 1024, 1024);

    cvt_kernel<<<1024,256>>>(ffn_in, fin, 1048576);
    cvt_kernel<<<1024,256>>>(ffn_outw, fout, 1048576);
    cvt_kernel<<<256,256>>>(ffn_gt, fgt, 262144);

    gemm32_kernel<0><<<512,256>>>(x, ca_pi, cah);
    caconv_kernel<<<dim3(32,Bv),256>>>(cah, ca_cw, cah2);
    gemm_k32<<<dim3(8,32),256>>>(cah2, ca_po, ca, 1024);
    x1rms_kernel<<<MT,256>>>(x, attn, ca, x1, xmh);

    gemm_f16<1><<<dim3(16,32),512,GEMM_SMEM>>>(xmh, fin, 0, hf, FFH, 1024);
    ffnconvT_kernel<<<dim3(256,Bv),256,FFNC_SMEM>>>(hf, ffn_cw, hs);
    gemm_f16<0><<<dim3(4,32),512,GEMM_SMEM>>>(hs, fout, mlp, 0, 1024, 4096);
    gemm_f16<0><<<dim3(4,32),512,GEMM_SMEM>>>(xmh, fgt, gate, 0, 1024, 1024);

    gemm32_kernel<0><<<512,256>>>(x1, ca_pi, cah);
    caconv_kernel<<<dim3(32,Bv),256>>>(cah, ca_cw, cah2);
    gemm_k32<<<dim3(8,32),256>>>(cah2, ca_po, ca, 1024);

    gemm32_kernel<2><<<512,256>>>(x1, vit_w1, vit32);
    vit2_kernel<<<512,256>>>(vit32, vit_w2, vitv);
    vitsmooth_kernel<<<Bv,256>>>(vitv, vitf);

    final_kernel<<<4096,256>>>(x1, mlp, gate, ca, vitf, out, MT*Cv);
}

// round 9
// speedup vs baseline: 1.5959x; 1.5959x over previous
#include <cuda_runtime.h>
#include <cuda_fp16.h>
#include <math.h>
#include <stdint.h>

#define Bv  4
#define Tv  1024
#define Cv  1024
#define NH  16
#define NKV 4
#define HD  64
#define FFH 4096
#define MT  (Bv*Tv)

typedef __half h16;

// ---------------- fp32 scratch ----------------
__device__ float g_xn  [MT*Cv];
__device__ float g_qkv [MT*1536];
__device__ float g_attn[MT*Cv];
__device__ float g_ca  [MT*Cv];
__device__ float g_cah [MT*32];
__device__ float g_cah2[MT*32];
__device__ float g_x1  [MT*Cv];
__device__ float g_mlp [MT*Cv];
__device__ float g_gate[MT*Cv];
__device__ float g_vit32[MT*32];
__device__ float g_vitv[MT];
__device__ float g_vitf[MT];

// ---------------- fp16 scratch ----------------
__device__ h16 g_xn_h[MT*Cv];
__device__ h16 g_xm_h[MT*Cv];
__device__ h16 g_y_h [MT*Cv];
__device__ h16 g_q_h [MT*1024];                  // (b,t,h,d)
__device__ h16 g_k_h [MT*256];                   // (b,t,kv,d)
__device__ h16 g_v_h [MT*256];                   // (b,kv,d,t)
__device__ h16 g_hf  [(size_t)MT*FFH];           // (b,f,t)
__device__ h16 g_hs  [(size_t)MT*FFH];           // (b,t,f)
__device__ h16 g_wqkv[1536*1024];
__device__ h16 g_wo  [1024*1024];
__device__ h16 g_fin [FFH*1024];
__device__ h16 g_fout[1024*FFH];
__device__ h16 g_fgt [1024*1024];

// =================== helpers ===================
__device__ __forceinline__ uint32_t smem_u32(const void* p){
    uint32_t a;
    asm("{ .reg .u64 t; cvta.to.shared.u64 t, %1; cvt.u32.u64 %0, t; }" : "=r"(a) : "l"(p));
    return a;
}
__device__ __forceinline__ void mma16816(float* c, const uint32_t* a, uint32_t b0, uint32_t b1){
    asm volatile("mma.sync.aligned.m16n8k16.row.col.f32.f16.f16.f32 "
        "{%0,%1,%2,%3}, {%4,%5,%6,%7}, {%8,%9}, {%0,%1,%2,%3};"
        : "+f"(c[0]), "+f"(c[1]), "+f"(c[2]), "+f"(c[3])
        : "r"(a[0]), "r"(a[1]), "r"(a[2]), "r"(a[3]), "r"(b0), "r"(b1));
}
__device__ __forceinline__ void ldsm4(uint32_t* r, uint32_t addr){
    asm volatile("ldmatrix.sync.aligned.m8n8.x4.shared.b16 {%0,%1,%2,%3}, [%4];"
        : "=r"(r[0]), "=r"(r[1]), "=r"(r[2]), "=r"(r[3]) : "r"(addr));
}
__device__ __forceinline__ void cpa16(uint32_t saddr, const void* g){
    asm volatile("cp.async.cg.shared.global [%0], [%1], 16;" :: "r"(saddr), "l"(g));
}
__device__ __forceinline__ void cpa4z(uint32_t saddr, const void* g, int srcsz){
    asm volatile("cp.async.ca.shared.global [%0], [%1], 4, %2;" :: "r"(saddr), "l"(g), "r"(srcsz));
}
#define CPA_COMMIT() asm volatile("cp.async.commit_group;" ::: "memory")
#define CPA_WAIT(n)  asm volatile("cp.async.wait_group %0;" :: "n"(n) : "memory")

__device__ __forceinline__ uint32_t sw_off(int row, int k){
    int chunk = (k >> 3) ^ ((row >> 1) & 3);
    return (uint32_t)(row*64 + chunk*16 + (k & 7)*2);
}
__device__ __forceinline__ uint32_t sw128(int row, int k){
    return (uint32_t)(row*128 + ((((k>>3) ^ (row & 7)) << 4) | ((k & 7) << 1)));
}
__device__ __forceinline__ uint32_t pack2(h16 a, h16 b){
    return ((uint32_t)__half_as_ushort(b) << 16) | __half_as_ushort(a);
}

// ---------------- fp32 -> fp16 convert ----------------
__global__ void cvt_kernel(const float* __restrict__ src, h16* __restrict__ dst, int n4){
    int i0 = blockIdx.x*1024 + threadIdx.x;
    #pragma unroll
    for (int j = 0; j < 4; j++){
        int i = i0 + (j << 8);
        if (i < n4){
            float4 v = ((const float4*)src)[i];
            ((uint2*)dst)[i] = make_uint2(
                pack2(__float2half_rn(v.x), __float2half_rn(v.y)),
                pack2(__float2half_rn(v.z), __float2half_rn(v.w)));
        }
    }
}

// ---------------- rmsnorm (fp32 + fp16), vectorized ----------------
template<int WF32>
__global__ void rms_kernel(const float* __restrict__ x, float* __restrict__ o32,
                           h16* __restrict__ ohi){
    int row = blockIdx.x;
    const float4* xr = (const float4*)(x + (size_t)row*Cv);
    float4 v = xr[threadIdx.x];
    float ss = v.x*v.x + v.y*v.y + v.z*v.z + v.w*v.w;
    __shared__ float red[8];
    for (int off=16; off>0; off>>=1) ss += __shfl_xor_sync(0xffffffffu, ss, off);
    if ((threadIdx.x & 31) == 0) red[threadIdx.x>>5] = ss;
    __syncthreads();
    if (threadIdx.x < 8){
        float t = red[threadIdx.x];
        for (int off=4; off>0; off>>=1) t += __shfl_xor_sync(0x000000ffu, t, off);
        if (threadIdx.x == 0) red[0] = t;
    }
    __syncthreads();
    float r = rsqrtf(red[0]*(1.0f/Cv) + 1e-6f);
    float4 o = make_float4(v.x*r, v.y*r, v.z*r, v.w*r);
    if (WF32) ((float4*)(o32 + (size_t)row*Cv))[threadIdx.x] = o;
    ((uint2*)(ohi + (size_t)row*Cv))[threadIdx.x] = make_uint2(
        pack2(__float2half_rn(o.x), __float2half_rn(o.y)),
        pack2(__float2half_rn(o.z), __float2half_rn(o.w)));
}

// ---------------- fused x1 + rmsnorm, vectorized ----------------
__global__ void x1rms_kernel(const float* __restrict__ x, const float* __restrict__ attn,
                             const float* __restrict__ ca, float* __restrict__ x1,
                             h16* __restrict__ ohi){
    int row = blockIdx.x;
    size_t base = (size_t)row*Cv;
    float4 xv = ((const float4*)(x + base))[threadIdx.x];
    float4 av = ((const float4*)(attn + base))[threadIdx.x];
    float4 cv = ((const float4*)(ca + base))[threadIdx.x];
    float4 v;
    v.x = xv.x + av.x*(1.f + 0.1f*tanhf(cv.x));
    v.y = xv.y + av.y*(1.f + 0.1f*tanhf(cv.y));
    v.z = xv.z + av.z*(1.f + 0.1f*tanhf(cv.z));
    v.w = xv.w + av.w*(1.f + 0.1f*tanhf(cv.w));
    float ss = v.x*v.x + v.y*v.y + v.z*v.z + v.w*v.w;
    __shared__ float red[8];
    for (int off=16; off>0; off>>=1) ss += __shfl_xor_sync(0xffffffffu, ss, off);
    if ((threadIdx.x & 31) == 0) red[threadIdx.x>>5] = ss;
    __syncthreads();
    if (threadIdx.x < 8){
        float t = red[threadIdx.x];
        for (int off=4; off>0; off>>=1) t += __shfl_xor_sync(0x000000ffu, t, off);
        if (threadIdx.x == 0) red[0] = t;
    }
    __syncthreads();
    float r = rsqrtf(red[0]*(1.0f/Cv) + 1e-6f);
    ((float4*)(x1 + base))[threadIdx.x] = v;
    ((uint2*)(ohi + base))[threadIdx.x] = make_uint2(
        pack2(__float2half_rn(v.x*r), __float2half_rn(v.y*r)),
        pack2(__float2half_rn(v.z*r), __float2half_rn(v.w*r)));
}

// =================== fp16 GEMM: C = A*B^T; tile 128x256, 4-stage cp.async ===================
#define GSTG 24576
#define GEMM_SMEM (4*GSTG)
template<int EPI>
__global__ void __launch_bounds__(512,1)
gemm_f16(const h16* __restrict__ Ah, const h16* __restrict__ Bh,
         float* __restrict__ Cg, h16* __restrict__ Chf, int N, int K){
    extern __shared__ char smem[];
    const int tid = threadIdx.x, lane = tid & 31, wid = tid >> 5;
    const int warpM = wid & 3, warpN = wid >> 2;
    const int m0 = blockIdx.y << 7, n0 = blockIdx.x << 8;
    const int b = m0 >> 10, tb = m0 & 1023;
    uint32_t sb = smem_u32(smem);

    const int r = tid >> 2, kc = tid & 3;
    const h16* aP  = Ah + (size_t)(m0+r)*K + (kc<<3);
    const h16* bP0 = Bh + (size_t)(n0+r)*K + (kc<<3);
    const h16* bP1 = Bh + (size_t)(n0+r+128)*K + (kc<<3);
    const uint32_t dA  = sw_off(r, kc<<3);
    const uint32_t dB1 = sw_off(r+128, kc<<3);

    auto ISSUE = [&](int c, int s){
        int k0 = c << 5;
        uint32_t st = sb + s*GSTG;
        cpa16(st + dA,         aP + k0);
        cpa16(st + 8192 + dA,  bP0 + k0);
        cpa16(st + 8192 + dB1, bP1 + k0);
        CPA_COMMIT();
    };

    float acc[2][8][4];
    #pragma unroll
    for (int i=0;i<2;i++)
        #pragma unroll
        for (int j=0;j<8;j++)
            #pragma unroll
            for (int q=0;q<4;q++) acc[i][j][q]=0.f;

    const int NC = K >> 5;
    ISSUE(0,0); ISSUE(1,1); ISSUE(2,2);
    const int lr = lane & 15, lc = (lane < 16) ? 0 : 8;
    for (int c = 0; c < NC; c++){
        int rem = NC - 1 - c;
        if (rem >= 2) { CPA_WAIT(2); } else if (rem == 1) { CPA_WAIT(1); } else { CPA_WAIT(0); }
        __syncthreads();
        if (c + 3 < NC) ISSUE(c+3, (c+3)&3);
        uint32_t sA = sb + (c&3)*GSTG;
        #pragma unroll
        for (int kk = 0; kk < 32; kk += 16){
            uint32_t ah[2][4];
            #pragma unroll
            for (int mt=0; mt<2; mt++)
                ldsm4(ah[mt], sA + sw_off(warpM*32 + mt*16 + lr, kk + lc));
            #pragma unroll
            for (int nb=0; nb<4; nb++){
                uint32_t bh[4];
                ldsm4(bh, sA + 8192 + sw_off(warpN*64 + nb*16 + lr, kk + lc));
                #pragma unroll
                for (int mt=0; mt<2; mt++){
                    mma16816(acc[mt][nb*2+0], ah[mt], bh[0], bh[2]);
                    mma16816(acc[mt][nb*2+1], ah[mt], bh[1], bh[3]);
                }
            }
        }
    }

    const int g = lane >> 2, t2 = (lane & 3) << 1;
    if (EPI == 0){
        #pragma unroll
        for (int mt=0; mt<2; mt++){
            int m = m0 + warpM*32 + mt*16 + g;
            #pragma unroll
            for (int ni=0; ni<8; ni++){
                int n = n0 + warpN*64 + ni*8 + t2;
                *(float2*)(Cg + (size_t)m*N + n) = make_float2(acc[mt][ni][0], acc[mt][ni][1]);
                *(float2*)(Cg + (size_t)(m+8)*N + n) = make_float2(acc[mt][ni][2], acc[mt][ni][3]);
            }
        }
    } else {
        float* ep = (float*)smem;   // 64 x 136
        #pragma unroll
        for (int slab=0; slab<4; slab++){
            __syncthreads();
            if (warpN == slab){
                #pragma unroll
                for (int mt=0; mt<2; mt++){
                    int mloc = warpM*32 + mt*16 + g;
                    #pragma unroll
                    for (int ni=0; ni<8; ni++){
                        int nL = ni*8 + t2;
                        ep[nL*136 + mloc]         = acc[mt][ni][0];
                        ep[(nL+1)*136 + mloc]     = acc[mt][ni][1];
                        ep[nL*136 + mloc + 8]     = acc[mt][ni][2];
                        ep[(nL+1)*136 + mloc + 8] = acc[mt][ni][3];
                    }
                }
            }
            __syncthreads();
            #pragma unroll
            for (int i=0;i<4;i++){
                int idx = tid + (i << 9);
                int nr = idx >> 5, t4 = (idx & 31) << 2;
                float a0 = fmaxf(ep[nr*136 + t4 + 0], 0.f);
                float a1 = fmaxf(ep[nr*136 + t4 + 1], 0.f);
                float a2 = fmaxf(ep[nr*136 + t4 + 2], 0.f);
                float a3 = fmaxf(ep[nr*136 + t4 + 3], 0.f);
                int n = n0 + slab*64 + nr;
                size_t o = ((size_t)b*N + n)*1024 + tb + t4;
                *(uint2*)(Chf + o) = make_uint2(
                    pack2(__float2half_rn(a0*a0), __float2half_rn(a1*a1)),
                    pack2(__float2half_rn(a2*a2), __float2half_rn(a3*a3)));
            }
        }
    }
}

// ---------------- small-N (=32) GEMM ----------------
template<int EPI>
__global__ void __launch_bounds__(256)
gemm32_kernel(const float* __restrict__ A, const float* __restrict__ W, float* __restrict__ Cg){
    __shared__ float xs[8*1024];
    int row0 = blockIdx.x << 3;
    #pragma unroll
    for (int i = 0; i < 8; i++){
        int f4 = threadIdx.x + (i << 8);
        ((float4*)xs)[f4] = ((const float4*)(A + ((size_t)row0 << 10)))[f4];
    }
    __syncthreads();
    int w = threadIdx.x >> 5, n = threadIdx.x & 31;
    const float4* Wr = (const float4*)(W + (size_t)n*1024);
    const float4* xr = (const float4*)(xs + (w << 10));
    float acc = 0.f;
    #pragma unroll 4
    for (int k = 0; k < 256; k++){
        float4 a = xr[k], b = Wr[k];
        acc += a.x*b.x + a.y*b.y + a.z*b.z + a.w*b.w;
    }
    if (EPI == 2) acc = 0.5f*acc*(1.f + erff(acc*0.70710678118f));
    Cg[((size_t)(row0 + w) << 5) + n] = acc;
}

// ---------------- FFMA GEMM (ca_po, K=32) ----------------
__global__ void __launch_bounds__(256,2)
gemm_k32(const float* __restrict__ A, const float* __restrict__ W,
         float* __restrict__ Cg, int N){
    __shared__ float As[32*132];
    __shared__ float Ws[32*132];
    const int tx = threadIdx.x & 15, ty = threadIdx.x >> 4;
    const int m0 = blockIdx.y << 7, n0 = blockIdx.x << 7;
    float acc[8][8];
    #pragma unroll
    for (int i=0;i<8;i++)
        #pragma unroll
        for (int j=0;j<8;j++) acc[i][j]=0.f;
    const int r = threadIdx.x >> 1;
    const int c4 = (threadIdx.x & 1) << 4;
    #pragma unroll
    for (int q=0;q<4;q++){
        float4 a0 = *(const float4*)(A + (size_t)(m0+r)*32 + c4 + q*4);
        As[(c4+q*4+0)*132 + r] = a0.x; As[(c4+q*4+1)*132 + r] = a0.y;
        As[(c4+q*4+2)*132 + r] = a0.z; As[(c4+q*4+3)*132 + r] = a0.w;
        float4 w0 = *(const float4*)(W + (size_t)(n0+r)*32 + c4 + q*4);
        Ws[(c4+q*4+0)*132 + r] = w0.x; Ws[(c4+q*4+1)*132 + r] = w0.y;
        Ws[(c4+q*4+2)*132 + r] = w0.z; Ws[(c4+q*4+3)*132 + r] = w0.w;
    }
    __syncthreads();
    #pragma unroll
    for (int kk=0; kk<32; kk++){
        float av[8], bv[8];
        *(float4*)&av[0] = *(const float4*)(As + kk*132 + (ty<<3));
        *(float4*)&av[4] = *(const float4*)(As + kk*132 + (ty<<3) + 4);
        *(float4*)&bv[0] = *(const float4*)(Ws + kk*132 + (tx<<3));
        *(float4*)&bv[4] = *(const float4*)(Ws + kk*132 + (tx<<3) + 4);
        #pragma unroll
        for (int i=0;i<8;i++)
            #pragma unroll
            for (int j=0;j<8;j++) acc[i][j] += av[i]*bv[j];
    }
    #pragma unroll
    for (int i=0;i<8;i++){
        int mg = m0 + (ty<<3) + i;
        #pragma unroll
        for (int j=0;j<8;j++)
            Cg[(size_t)mg*N + n0 + (tx<<3) + j] = acc[i][j];
    }
}

// ---------------- VE gate + V -> transposed fp16 ----------------
__global__ void vgate_kernel(const float* __restrict__ xn, const float* __restrict__ ve,
                             const float* __restrict__ wg, const float* __restrict__ qkv,
                             h16* __restrict__ vhi){
    int row = blockIdx.x;
    __shared__ float gs[4];
    if (threadIdx.x < 4){
        float s = 0.f;
        #pragma unroll
        for (int c=0;c<12;c++) s += xn[(size_t)row*Cv + c]*wg[threadIdx.x*12 + c];
        gs[threadIdx.x] = 3.f/(1.f + expf(-s));
    }
    __syncthreads();
    int i = threadIdx.x;
    int kv = i >> 6, d = i & 63;
    float vv = qkv[(size_t)row*1536 + 1280 + i] + gs[kv]*ve[(size_t)row*256 + i];
    size_t o = ((size_t)((row>>10)*4 + kv)*64 + d)*1024 + (row & 1023);
    vhi[o] = __float2half_rn(vv);
}

// ---------------- rope + per-head rmsnorm*1.2 -> fp16 ----------------
__global__ void ropeRms_kernel(const float* __restrict__ src, int srcStride, int srcOff,
                               h16* __restrict__ dhi,
                               const float* __restrict__ cosb, const float* __restrict__ sinb,
                               int nheads){
    int row  = blockIdx.x;
    int t    = row & (Tv-1);
    int head = blockIdx.y*4 + (threadIdx.x >> 5);
    if (head >= nheads) return;
    int lane = threadIdx.x & 31;
    const float* p = src + (size_t)row*srcStride + srcOff + head*HD;
    float x1 = p[lane], x2 = p[lane+32];
    float cc = cosb[t*32 + lane], sn = sinb[t*32 + lane];
    float o1 =  x1*cc + x2*sn;
    float o2 = -x1*sn + x2*cc;
    float ss = o1*o1 + o2*o2;
    for (int off=16; off>0; off>>=1) ss += __shfl_xor_sync(0xffffffffu, ss, off);
    float rr = rsqrtf(ss*(1.0f/HD) + 1e-6f)*1.2f;
    size_t base = ((size_t)row*nheads + head)*HD;
    dhi[base+lane]    = __float2half_rn(o1*rr);
    dhi[base+lane+32] = __float2half_rn(o2*rr);
}

// =================== flash attention: single-fp16 QK and PV ===================
#define SM_Q    0
#define SM_KV0  8192
#define SM_KV1  24576
#define SM_PP0  40960
#define SM_PP1  58752
#define SM_S    76544
#define SM_PHI  95488
#define SM_CORR 103680
#define SM_LINV 103936
#define ATTN_SMEM 104192

__global__ void __launch_bounds__(256)
attn_kernel(const h16* __restrict__ qhi,
            const h16* __restrict__ khi, const h16* __restrict__ vhi,
            const float* __restrict__ prev, const float* __restrict__ rw,
            const float* __restrict__ alphap,
            h16* __restrict__ yh){
    extern __shared__ char smc[];
    uint32_t sb = smem_u32(smc);
    float* S      = (float*)(smc + SM_S);
    float* corr_s = (float*)(smc + SM_CORR);
    float* linv   = (float*)(smc + SM_LINV);

    const int tid = threadIdx.x, lane = tid & 31, wid = tid >> 5;
    const int warpM = wid & 3, warpN = wid >> 2;
    const int row = tid >> 2, quad = tid & 3, c0 = quad << 4;
    const int qt = blockIdx.x, h = blockIdx.y, b = blockIdx.z;
    const int q0 = qt << 6;
    const int kvh = h >> 2;
    const int lr = lane & 15, lc = (lane < 16) ? 0 : 8;
    const int g = lane >> 2, t2 = (lane & 3) << 1;

    const float alpha = alphap[0];
    float w9[9];
    #pragma unroll
    for (int i=0;i<9;i++) w9[i] = alpha*rw[h*9 + i];

    const float* prevB = prev + ((size_t)(b*NH + h))*Tv*Tv;

    auto issueKV = [&](int kt, int s){
        int k0 = kt << 6;
        uint32_t kvb = sb + SM_KV0 + s*16384;
        #pragma unroll
        for (int i=0;i<4;i++){
            int idx = tid + (i << 8);
            int arr = idx >> 9, rr = (idx >> 3) & 63, kc = idx & 7;
            const h16* src;
            if (arr == 0) src = khi + ((((size_t)(b*Tv + k0 + rr))*NKV + kvh) << 6) + (kc << 3);
            else          src = vhi + (((size_t)((b*NKV + kvh)*64 + rr)) << 10) + k0 + (kc << 3);
            cpa16(kvb + arr*8192 + sw128(rr, kc << 3), src);
        }
    };
    auto issuePP = [&](int kt, int s){
        int k0 = kt << 6;
        uint32_t ppb = sb + SM_PP0 + s*17792;
        for (int idx = tid; idx < 66*66; idx += 256){
            int i = idx/66, j = idx - i*66;
            int rr = q0 - 1 + i, cg = k0 - 1 + j;
            int ok = (rr >= 0 && rr < Tv && cg >= 0 && cg < Tv) ? 4 : 0;
            int rrc = rr < 0 ? 0 : (rr > 1023 ? 1023 : rr);
            int cgc = cg < 0 ? 0 : (cg > 1023 ? 1023 : cg);
            cpa4z(ppb + (uint32_t)(i*67 + j)*4, prevB + (size_t)rrc*Tv + cgc, ok);
        }
    };

    {
        #pragma unroll
        for (int i=0;i<2;i++){
            int idx = tid + (i << 8);
            int rr = idx >> 3, kc = idx & 7;
            const h16* src = qhi + ((((size_t)(b*Tv + q0 + rr))*NH + h) << 6) + (kc << 3);
            cpa16(sb + SM_Q + sw128(rr, kc << 3), src);
        }
        CPA_COMMIT();
        issueKV(0,0); issuePP(0,0);
        CPA_COMMIT();
    }

    float o[4][4];
    #pragma unroll
    for (int i=0;i<4;i++)
        #pragma unroll
        for (int j=0;j<4;j++) o[i][j]=0.f;
    float m = -1e30f, l = 0.f;

    for (int kt = 0; kt <= qt; kt++){
        int s = kt & 1;
        CPA_WAIT(0);
        __syncthreads();
        if (kt < qt){ issueKV(kt+1, s^1); issuePP(kt+1, s^1); CPA_COMMIT(); }
        uint32_t kvb = sb + SM_KV0 + s*16384;
        float* PP = (float*)(smc + SM_PP0 + s*17792);

        float c[4][4];
        #pragma unroll
        for (int i=0;i<4;i++)
            #pragma unroll
            for (int j=0;j<4;j++) c[i][j]=0.f;
        #pragma unroll
        for (int k16 = 0; k16 < 4; k16++){
            uint32_t qh_[4];
            ldsm4(qh_, sb + SM_Q + sw128(warpM*16 + lr, k16*16 + lc));
            #pragma unroll
            for (int nb=0; nb<2; nb++){
                uint32_t kh_[4];
                ldsm4(kh_, kvb + sw128(warpN*32 + nb*16 + lr, k16*16 + lc));
                mma16816(c[nb*2+0], qh_, kh_[0], kh_[2]);
                mma16816(c[nb*2+1], qh_, kh_[1], kh_[3]);
            }
        }
        #pragma unroll
        for (int ni=0; ni<4; ni++){
            int col = warpN*32 + ni*8 + t2;
            int r0 = warpM*16 + g;
            *(float2*)(S + r0*74 + col)     = make_float2(c[ni][0], c[ni][1]);
            *(float2*)(S + (r0+8)*74 + col) = make_float2(c[ni][2], c[ni][3]);
        }
        __syncthreads();

        float p[3][18];
        #pragma unroll
        for (int i=0;i<3;i++)
            #pragma unroll
            for (int e=0;e<18;e++) p[i][e] = PP[(row+i)*67 + c0 + e];
        float sr[16];
        #pragma unroll
        for (int j=0;j<16;j++){
            float cv = w9[0]*p[0][j] + w9[1]*p[0][j+1] + w9[2]*p[0][j+2]
                     + w9[3]*p[1][j] + w9[4]*p[1][j+1] + w9[5]*p[1][j+2]
                     + w9[6]*p[2][j] + w9[7]*p[2][j+1] + w9[8]*p[2][j+2];
            int col = c0 + j;
            sr[j] = S[row*74 + col]*0.125f + cv;
            if (kt == qt && col > row) sr[j] = -1e30f;
        }
        float mt = sr[0];
        #pragma unroll
        for (int j=1;j<16;j++) mt = fmaxf(mt, sr[j]);
        for (int off=1; off<4; off<<=1) mt = fmaxf(mt, __shfl_xor_sync(0xffffffffu, mt, off));
        float mnew = fmaxf(m, mt);
        float corrv = __expf(m - mnew);
        float ls = 0.f;
        #pragma unroll
        for (int j=0;j<16;j++){ sr[j] = __expf(sr[j] - mnew); ls += sr[j]; }
        for (int off=1; off<4; off<<=1) ls += __shfl_xor_sync(0xffffffffu, ls, off);
        l = l*corrv + ls;
        m = mnew;
        if (quad == 0) corr_s[row] = corrv;
        #pragma unroll
        for (int j=0;j<16;j+=2){
            int col = c0 + j;
            *(uint32_t*)(smc + SM_PHI + sw128(row, col)) =
                pack2(__float2half_rn(sr[j]), __float2half_rn(sr[j+1]));
        }
        __syncthreads();

        float cr0 = corr_s[warpM*16 + g], cr1 = corr_s[warpM*16 + g + 8];
        #pragma unroll
        for (int ni=0; ni<4; ni++){
            o[ni][0] *= cr0; o[ni][1] *= cr0;
            o[ni][2] *= cr1; o[ni][3] *= cr1;
        }
        #pragma unroll
        for (int k16 = 0; k16 < 4; k16++){
            uint32_t ph_[4];
            ldsm4(ph_, sb + SM_PHI + sw128(warpM*16 + lr, k16*16 + lc));
            #pragma unroll
            for (int nb=0; nb<2; nb++){
                uint32_t vh_[4];
                ldsm4(vh_, kvb + 8192 + sw128(warpN*32 + nb*16 + lr, k16*16 + lc));
                mma16816(o[nb*2+0], ph_, vh_[0], vh_[2]);
                mma16816(o[nb*2+1], ph_, vh_[1], vh_[3]);
            }
        }
    }

    if (quad == 0) linv[row] = 1.f/l;
    __syncthreads();
    float i0 = linv[warpM*16 + g], i1 = linv[warpM*16 + g + 8];
    #pragma unroll
    for (int ni=0; ni<4; ni++){
        int col = warpN*32 + ni*8 + t2;
        size_t base0 = ((((size_t)(b*Tv + q0 + warpM*16 + g))*NH + h) << 6) + col;
        size_t base1 = ((((size_t)(b*Tv + q0 + warpM*16 + g + 8))*NH + h) << 6) + col;
        *(uint32_t*)(yh + base0) = pack2(__float2half_rn(o[ni][0]*i0), __float2half_rn(o[ni][1]*i0));
        *(uint32_t*)(yh + base1) = pack2(__float2half_rn(o[ni][2]*i1), __float2half_rn(o[ni][3]*i1));
    }
}

// ---------------- CA conv + gelu ----------------
__global__ void caconv_kernel(const float* __restrict__ hin, const float* __restrict__ cw,
                              float* __restrict__ hout){
    int ch = blockIdx.x, b = blockIdx.y;
    __shared__ float s[Tv+2];
    for (int t = threadIdx.x; t < Tv; t += 256) s[1+t] = hin[((size_t)b*Tv + t)*32 + ch];
    if (threadIdx.x == 0){ s[0] = 0.f; s[Tv+1] = 0.f; }
    __syncthreads();
    float w0 = cw[ch*3], w1 = cw[ch*3+1], w2 = cw[ch*3+2];
    for (int t = threadIdx.x; t < Tv; t += 256){
        float vv = s[1+t] + 0.1f*(w0*s[t] + w1*s[1+t] + w2*s[2+t]);
        hout[((size_t)b*Tv + t)*32 + ch] = 0.5f*vv*(1.f + erff(vv*0.70710678118f));
    }
}

// ---------------- FFN conv x4 ----------------
#define FFNC_SMEM (2*16*1026*4)
__global__ void __launch_bounds__(256)
ffnconvT_kernel(const h16* __restrict__ hf, const float* __restrict__ cw,
                h16* __restrict__ hs){
    extern __shared__ float fs[];
    float (*buf0)[1026] = (float(*)[1026])fs;
    float (*buf1)[1026] = (float(*)[1026])(fs + 16*1026);
    int f0 = blockIdx.x << 4, b = blockIdx.y;
    for (int idx4 = threadIdx.x; idx4 < 16*256; idx4 += 256){
        int cch = idx4 >> 8, t4 = (idx4 & 255) << 2;
        size_t o = ((size_t)(b*FFH + f0 + cch))*Tv + t4;
        uint2 u = *(const uint2*)(hf + o);
        const h16* ph = (const h16*)&u;
        #pragma unroll
        for (int e=0;e<4;e++) buf0[cch][1+t4+e] = __half2float(ph[e]);
    }
    if (threadIdx.x < 16){
        buf0[threadIdx.x][0] = 0.f; buf0[threadIdx.x][1025] = 0.f;
        buf1[threadIdx.x][0] = 0.f; buf1[threadIdx.x][1025] = 0.f;
    }
    int cch = threadIdx.x >> 4, j = threadIdx.x & 15;
    float w0 = cw[(f0+cch)*3], w1 = cw[(f0+cch)*3+1], w2 = cw[(f0+cch)*3+2];
    float (*cur)[1026] = buf0; float (*nxt)[1026] = buf1;
    #pragma unroll
    for (int it=0; it<4; it++){
        __syncthreads();
        #pragma unroll 4
        for (int t = j*64; t < j*64 + 64; t++)
            nxt[cch][1+t] = cur[cch][1+t] + 0.1f*(w0*cur[cch][t] + w1*cur[cch][1+t] + w2*cur[cch][2+t]);
        float (*tmp)[1026] = cur; cur = nxt; nxt = tmp;
    }
    __syncthreads();
    for (int t = threadIdx.x; t < Tv; t += 256){
        uint32_t wv[8];
        #pragma unroll
        for (int cc = 0; cc < 16; cc += 2)
            wv[cc>>1] = pack2(__float2half_rn(cur[cc][1+t]), __float2half_rn(cur[cc+1][1+t]));
        size_t o = ((size_t)(b*Tv + t))*FFH + f0;
        *(uint4*)(hs + o)     = make_uint4(wv[0],wv[1],wv[2],wv[3]);
        *(uint4*)(hs + o + 8) = make_uint4(wv[4],wv[5],wv[6],wv[7]);
    }
}

// ---------------- elementwise ----------------
__global__ void vit2_kernel(const float* __restrict__ h32, const float* __restrict__ w2,
                            float* __restrict__ out){
    int row  = blockIdx.x*8 + (threadIdx.x >> 5);
    int lane = threadIdx.x & 31;
    float vv = h32[(size_t)row*32 + lane]*w2[lane];
    for (int off=16; off>0; off>>=1) vv += __shfl_xor_sync(0xffffffffu, vv, off);
    if (lane == 0) out[row] = 1.f/(1.f + expf(-vv));
}
__global__ void vitsmooth_kernel(const float* __restrict__ vin, float* __restrict__ vout){
    int b = blockIdx.x;
    __shared__ float s[Tv+4];
    for (int t = threadIdx.x; t < Tv; t += 256) s[2+t] = vin[b*Tv + t];
    if (threadIdx.x < 2){ s[threadIdx.x] = 0.f; s[Tv+2+threadIdx.x] = 0.f; }
    __syncthreads();
    for (int t = threadIdx.x; t < Tv; t += 256){
        float vs = (s[t] + s[t+1] + s[t+2] + s[t+3] + s[t+4])*0.2f;
        float vv = 0.7f*s[2+t] + 0.3f*vs;
        vout[b*Tv + t] = (vv > 0.3f) ? vv : 0.1f*vv;
    }
}
__global__ void final_kernel(const float* __restrict__ x1, const float* __restrict__ mlp,
                             const float* __restrict__ gate, const float* __restrict__ ca,
                             const float* __restrict__ vitf, float* __restrict__ out, int n4){
    for (int i = blockIdx.x*blockDim.x + threadIdx.x; i < n4; i += gridDim.x*blockDim.x){
        int row = i >> 8;
        float vf = vitf[row];
        float4 xv = ((const float4*)x1)[i];
        float4 mv = ((const float4*)mlp)[i];
        float4 gv = ((const float4*)gate)[i];
        float4 cv = ((const float4*)ca)[i];
        float4 o;
        o.x = xv.x + mv.x*(1.f/(1.f + expf(-gv.x)))*(1.f + 0.1f*tanhf(cv.x))*vf;
        o.y = xv.y + mv.y*(1.f/(1.f + expf(-gv.y)))*(1.f + 0.1f*tanhf(cv.y))*vf;
        o.z = xv.z + mv.z*(1.f/(1.f + expf(-gv.z)))*(1.f + 0.1f*tanhf(cv.z))*vf;
        o.w = xv.w + mv.w*(1.f/(1.f + expf(-gv.w)))*(1.f + 0.1f*tanhf(cv.w))*vf;
        ((float4*)out)[i] = o;
    }
}

// ---------------- launch ----------------
extern "C" void kernel_launch(void* const* d_in, const int* in_sizes, int n_in,
                              void* d_out, int out_size){
    const float* x     = (const float*)d_in[0];
    const float* ve    = (const float*)d_in[1];
    const float* cosp  = (const float*)d_in[2];
    const float* sinp  = (const float*)d_in[3];
    const float* prev  = (const float*)d_in[4];
    const float* w_q   = (const float*)d_in[5];
    const float* w_k   = (const float*)d_in[6];
    const float* w_v   = (const float*)d_in[7];
    const float* w_o   = (const float*)d_in[8];
    const float* w_veg = (const float*)d_in[9];
    const float* rfw   = (const float*)d_in[10];
    const float* ralpha= (const float*)d_in[11];
    const float* ca_pi = (const float*)d_in[12];
    const float* ca_cw = (const float*)d_in[13];
    const float* ca_po = (const float*)d_in[14];
    const float* ffn_in= (const float*)d_in[15];
    const float* ffn_cw= (const float*)d_in[16];
    const float* ffn_outw=(const float*)d_in[17];
    const float* ffn_gt= (const float*)d_in[18];
    const float* vit_w1= (const float*)d_in[19];
    const float* vit_w2= (const float*)d_in[20];
    float* out = (float*)d_out;

    float *xn,*qkv,*attn,*ca,*cah,*cah2,*x1,*mlp,*gate,*vit32,*vitv,*vitf;
    h16 *xnh,*xmh,*yh,*qh,*kh,*vh,*hf,*hs;
    h16 *wqkv,*wo,*fin,*fout,*fgt;
    cudaGetSymbolAddress((void**)&xn, g_xn);     cudaGetSymbolAddress((void**)&qkv, g_qkv);
    cudaGetSymbolAddress((void**)&attn, g_attn); cudaGetSymbolAddress((void**)&ca, g_ca);
    cudaGetSymbolAddress((void**)&cah, g_cah);   cudaGetSymbolAddress((void**)&cah2, g_cah2);
    cudaGetSymbolAddress((void**)&x1, g_x1);
    cudaGetSymbolAddress((void**)&mlp, g_mlp);   cudaGetSymbolAddress((void**)&gate, g_gate);
    cudaGetSymbolAddress((void**)&vit32, g_vit32); cudaGetSymbolAddress((void**)&vitv, g_vitv);
    cudaGetSymbolAddress((void**)&vitf, g_vitf);
    cudaGetSymbolAddress((void**)&xnh, g_xn_h);
    cudaGetSymbolAddress((void**)&xmh, g_xm_h);
    cudaGetSymbolAddress((void**)&yh, g_y_h);
    cudaGetSymbolAddress((void**)&qh, g_q_h);
    cudaGetSymbolAddress((void**)&kh, g_k_h);
    cudaGetSymbolAddress((void**)&vh, g_v_h);
    cudaGetSymbolAddress((void**)&hf, g_hf);     cudaGetSymbolAddress((void**)&hs, g_hs);
    cudaGetSymbolAddress((void**)&wqkv, g_wqkv);
    cudaGetSymbolAddress((void**)&wo, g_wo);
    cudaGetSymbolAddress((void**)&fin, g_fin);
    cudaGetSymbolAddress((void**)&fout, g_fout);
    cudaGetSymbolAddress((void**)&fgt, g_fgt);

    cudaFuncSetAttribute(attn_kernel, cudaFuncAttributeMaxDynamicSharedMemorySize, ATTN_SMEM);
    cudaFuncSetAttribute(gemm_f16<0>, cudaFuncAttributeMaxDynamicSharedMemorySize, GEMM_SMEM);
    cudaFuncSetAttribute(gemm_f16<1>, cudaFuncAttributeMaxDynamicSharedMemorySize, GEMM_SMEM);
    cudaFuncSetAttribute(ffnconvT_kernel, cudaFuncAttributeMaxDynamicSharedMemorySize, FFNC_SMEM);

    cvt_kernel<<<256,256>>>(w_q, wqkv, 262144);
    cvt_kernel<<<64,256>>>(w_k, wqkv + 1024*1024, 65536);
    cvt_kernel<<<64,256>>>(w_v, wqkv + 1280*1024, 65536);
    rms_kernel<1><<<MT,256>>>(x, xn, xnh);
    cvt_kernel<<<256,256>>>(w_o, wo, 262144);
    gemm_f16<0><<<dim3(6,32),512,GEMM_SMEM>>>(xnh, wqkv, qkv, 0, 1536, 1024);

    vgate_kernel<<<MT,256>>>(xn, ve, w_veg, qkv, vh);
    ropeRms_kernel<<<dim3(MT,4),128>>>(qkv, 1536, 0,    qh, cosp, sinp, NH);
    ropeRms_kernel<<<dim3(MT,1),128>>>(qkv, 1536, 1024, kh, cosp, sinp, NKV);

    attn_kernel<<<dim3(16,NH,Bv),256,ATTN_SMEM>>>(qh, kh, vh, prev, rfw, ralpha, yh);
    gemm_f16<0><<<dim3(4,32),512,GEMM_SMEM>>>(yh, wo, attn, 0, 1024, 1024);

    cvt_kernel<<<1024,256>>>(ffn_in, fin, 1048576);
    cvt_kernel<<<1024,256>>>(ffn_outw, fout, 1048576);
    cvt_kernel<<<256,256>>>(ffn_gt, fgt, 262144);

    gemm32_kernel<0><<<512,256>>>(x, ca_pi, cah);
    caconv_kernel<<<dim3(32,Bv),256>>>(cah, ca_cw, cah2);
    gemm_k32<<<dim3(8,32),256>>>(cah2, ca_po, ca, 1024);
    x1rms_kernel<<<MT,256>>>(x, attn, ca, x1, xmh);

    gemm_f16<1><<<dim3(16,32),512,GEMM_SMEM>>>(xmh, fin, 0, hf, FFH, 1024);
    ffnconvT_kernel<<<dim3(256,Bv),256,FFNC_SMEM>>>(hf, ffn_cw, hs);
    gemm_f16<0><<<dim3(4,32),512,GEMM_SMEM>>>(hs, fout, mlp, 0, 1024, 4096);
    gemm_f16<0><<<dim3(4,32),512,GEMM_SMEM>>>(xmh, fgt, gate, 0, 1024, 1024);

    gemm32_kernel<0><<<512,256>>>(x1, ca_pi, cah);
    caconv_kernel<<<dim3(32,Bv),256>>>(cah, ca_cw, cah2);
    gemm_k32<<<dim3(8,32),256>>>(cah2, ca_po, ca, 1024);

    gemm32_kernel<2><<<512,256>>>(x1, vit_w1, vit32);
    vit2_kernel<<<512,256>>>(vit32, vit_w2, vitv);
    vitsmooth_kernel<<<Bv,256>>>(vitv, vitf);

    final_kernel<<<2048,256>>>(x1, mlp, gate, ca, vitf, out, MT*Cv/4);
}

// round 10
// speedup vs baseline: 1.6399x; 1.0276x over previous
#include <cuda_runtime.h>
#include <cuda_fp16.h>
#include <math.h>
#include <stdint.h>

#define Bv  4
#define Tv  1024
#define Cv  1024
#define NH  16
#define NKV 4
#define HD  64
#define FFH 4096
#define MT  (Bv*Tv)

typedef __half h16;

// ---------------- fp32 scratch ----------------
__device__ float g_xn  [MT*Cv];
__device__ float g_qkv [MT*1536];
__device__ float g_attn[MT*Cv];
__device__ float g_ca  [MT*Cv];
__device__ float g_cah [MT*32];
__device__ float g_cah2[MT*32];
__device__ float g_x1  [MT*Cv];
__device__ float g_mlp [MT*Cv];
__device__ float g_vit32[MT*32];
__device__ float g_vitv[MT];
__device__ float g_vitf[MT];

// ---------------- fp16 scratch ----------------
__device__ h16 g_xn_h[MT*Cv];
__device__ h16 g_xm_h[MT*Cv];
__device__ h16 g_y_h [MT*Cv];
__device__ h16 g_q_h [MT*1024];                  // (b,t,h,d)
__device__ h16 g_k_h [MT*256];                   // (b,t,kv,d)
__device__ h16 g_v_h [MT*256];                   // (b,kv,d,t)
__device__ h16 g_hf  [(size_t)MT*FFH];           // (b,f,t)
__device__ h16 g_hs  [(size_t)MT*FFH];           // (b,t,f)
__device__ h16 g_wqkv[1536*1024];
__device__ h16 g_wo  [1024*1024];
__device__ h16 g_fin [FFH*1024];
__device__ h16 g_fout[1024*FFH];
__device__ h16 g_fgt [1024*1024];

// =================== helpers ===================
__device__ __forceinline__ uint32_t smem_u32(const void* p){
    uint32_t a;
    asm("{ .reg .u64 t; cvta.to.shared.u64 t, %1; cvt.u32.u64 %0, t; }" : "=r"(a) : "l"(p));
    return a;
}
__device__ __forceinline__ void mma16816(float* c, const uint32_t* a, uint32_t b0, uint32_t b1){
    asm volatile("mma.sync.aligned.m16n8k16.row.col.f32.f16.f16.f32 "
        "{%0,%1,%2,%3}, {%4,%5,%6,%7}, {%8,%9}, {%0,%1,%2,%3};"
        : "+f"(c[0]), "+f"(c[1]), "+f"(c[2]), "+f"(c[3])
        : "r"(a[0]), "r"(a[1]), "r"(a[2]), "r"(a[3]), "r"(b0), "r"(b1));
}
__device__ __forceinline__ void ldsm4(uint32_t* r, uint32_t addr){
    asm volatile("ldmatrix.sync.aligned.m8n8.x4.shared.b16 {%0,%1,%2,%3}, [%4];"
        : "=r"(r[0]), "=r"(r[1]), "=r"(r[2]), "=r"(r[3]) : "r"(addr));
}
__device__ __forceinline__ void cpa16(uint32_t saddr, const void* g){
    asm volatile("cp.async.cg.shared.global [%0], [%1], 16;" :: "r"(saddr), "l"(g));
}
__device__ __forceinline__ void cpa4z(uint32_t saddr, const void* g, int srcsz){
    asm volatile("cp.async.ca.shared.global [%0], [%1], 4, %2;" :: "r"(saddr), "l"(g), "r"(srcsz));
}
#define CPA_COMMIT() asm volatile("cp.async.commit_group;" ::: "memory")
#define CPA_WAIT(n)  asm volatile("cp.async.wait_group %0;" :: "n"(n) : "memory")

__device__ __forceinline__ uint32_t sw_off(int row, int k){
    int chunk = (k >> 3) ^ ((row >> 1) & 3);
    return (uint32_t)(row*64 + chunk*16 + (k & 7)*2);
}
__device__ __forceinline__ uint32_t sw128(int row, int k){
    return (uint32_t)(row*128 + ((((k>>3) ^ (row & 7)) << 4) | ((k & 7) << 1)));
}
__device__ __forceinline__ uint32_t pack2(h16 a, h16 b){
    return ((uint32_t)__half_as_ushort(b) << 16) | __half_as_ushort(a);
}

// ---------------- fp32 -> fp16 convert ----------------
__global__ void cvt_kernel(const float* __restrict__ src, h16* __restrict__ dst, int n4){
    int i0 = blockIdx.x*1024 + threadIdx.x;
    #pragma unroll
    for (int j = 0; j < 4; j++){
        int i = i0 + (j << 8);
        if (i < n4){
            float4 v = ((const float4*)src)[i];
            ((uint2*)dst)[i] = make_uint2(
                pack2(__float2half_rn(v.x), __float2half_rn(v.y)),
                pack2(__float2half_rn(v.z), __float2half_rn(v.w)));
        }
    }
}

// ---------------- rmsnorm (fp32 + fp16), vectorized ----------------
template<int WF32>
__global__ void rms_kernel(const float* __restrict__ x, float* __restrict__ o32,
                           h16* __restrict__ ohi){
    int row = blockIdx.x;
    const float4* xr = (const float4*)(x + (size_t)row*Cv);
    float4 v = xr[threadIdx.x];
    float ss = v.x*v.x + v.y*v.y + v.z*v.z + v.w*v.w;
    __shared__ float red[8];
    for (int off=16; off>0; off>>=1) ss += __shfl_xor_sync(0xffffffffu, ss, off);
    if ((threadIdx.x & 31) == 0) red[threadIdx.x>>5] = ss;
    __syncthreads();
    if (threadIdx.x < 8){
        float t = red[threadIdx.x];
        for (int off=4; off>0; off>>=1) t += __shfl_xor_sync(0x000000ffu, t, off);
        if (threadIdx.x == 0) red[0] = t;
    }
    __syncthreads();
    float r = rsqrtf(red[0]*(1.0f/Cv) + 1e-6f);
    float4 o = make_float4(v.x*r, v.y*r, v.z*r, v.w*r);
    if (WF32) ((float4*)(o32 + (size_t)row*Cv))[threadIdx.x] = o;
    ((uint2*)(ohi + (size_t)row*Cv))[threadIdx.x] = make_uint2(
        pack2(__float2half_rn(o.x), __float2half_rn(o.y)),
        pack2(__float2half_rn(o.z), __float2half_rn(o.w)));
}

// ---------------- fused x1 + rmsnorm, vectorized ----------------
__global__ void x1rms_kernel(const float* __restrict__ x, const float* __restrict__ attn,
                             const float* __restrict__ ca, float* __restrict__ x1,
                             h16* __restrict__ ohi){
    int row = blockIdx.x;
    size_t base = (size_t)row*Cv;
    float4 xv = ((const float4*)(x + base))[threadIdx.x];
    float4 av = ((const float4*)(attn + base))[threadIdx.x];
    float4 cv = ((const float4*)(ca + base))[threadIdx.x];
    float4 v;
    v.x = xv.x + av.x*(1.f + 0.1f*tanhf(cv.x));
    v.y = xv.y + av.y*(1.f + 0.1f*tanhf(cv.y));
    v.z = xv.z + av.z*(1.f + 0.1f*tanhf(cv.z));
    v.w = xv.w + av.w*(1.f + 0.1f*tanhf(cv.w));
    float ss = v.x*v.x + v.y*v.y + v.z*v.z + v.w*v.w;
    __shared__ float red[8];
    for (int off=16; off>0; off>>=1) ss += __shfl_xor_sync(0xffffffffu, ss, off);
    if ((threadIdx.x & 31) == 0) red[threadIdx.x>>5] = ss;
    __syncthreads();
    if (threadIdx.x < 8){
        float t = red[threadIdx.x];
        for (int off=4; off>0; off>>=1) t += __shfl_xor_sync(0x000000ffu, t, off);
        if (threadIdx.x == 0) red[0] = t;
    }
    __syncthreads();
    float r = rsqrtf(red[0]*(1.0f/Cv) + 1e-6f);
    ((float4*)(x1 + base))[threadIdx.x] = v;
    ((uint2*)(ohi + base))[threadIdx.x] = make_uint2(
        pack2(__float2half_rn(v.x*r), __float2half_rn(v.y*r)),
        pack2(__float2half_rn(v.z*r), __float2half_rn(v.w*r)));
}

// =================== fp16 GEMM: tile 128x128, 256 thr, 2 CTA/SM, 4-stage ===================
// stage: A 8K @0, B 8K @8192 => 16KB, 4 stages = 64KB
// EPI 0: fp32 store. EPI 1: relu^2 -> fp16 (B,N,T). EPI 2: fused final output.
#define GSTG 16384
#define GEMM_SMEM (4*GSTG)
template<int EPI>
__global__ void __launch_bounds__(256,2)
gemm_f16(const h16* __restrict__ Ah, const h16* __restrict__ Bh,
         float* __restrict__ Cg, h16* __restrict__ Chf,
         const float* __restrict__ X1, const float* __restrict__ MLP,
         const float* __restrict__ CA, const float* __restrict__ VF,
         float* __restrict__ Og, int N, int K){
    extern __shared__ char smem[];
    const int tid = threadIdx.x, lane = tid & 31, wid = tid >> 5;
    const int warpM = wid & 3, warpN = wid >> 2;   // 4 x 2
    const int m0 = blockIdx.y << 7, n0 = blockIdx.x << 7;
    const int b = m0 >> 10, tb = m0 & 1023;
    uint32_t sb = smem_u32(smem);

    const int r = tid >> 2, kc = tid & 3;
    const h16* aP = Ah + (size_t)(m0+r)*K + (kc<<3);
    const h16* bP = Bh + (size_t)(n0+r)*K + (kc<<3);
    const uint32_t dA0 = sw_off(r, kc<<3);
    const uint32_t dA1 = sw_off(r+64, kc<<3);
    const size_t off64 = (size_t)64*K;

    auto ISSUE = [&](int c, int s){
        int k0 = c << 5;
        uint32_t st = sb + s*GSTG;
        cpa16(st + dA0,        aP + k0);
        cpa16(st + dA1,        aP + off64 + k0);
        cpa16(st + 8192 + dA0, bP + k0);
        cpa16(st + 8192 + dA1, bP + off64 + k0);
        CPA_COMMIT();
    };

    float acc[2][8][4];
    #pragma unroll
    for (int i=0;i<2;i++)
        #pragma unroll
        for (int j=0;j<8;j++)
            #pragma unroll
            for (int q=0;q<4;q++) acc[i][j][q]=0.f;

    const int NC = K >> 5;
    ISSUE(0,0); ISSUE(1,1); ISSUE(2,2);
    const int lr = lane & 15, lc = (lane < 16) ? 0 : 8;
    for (int c = 0; c < NC; c++){
        int rem = NC - 1 - c;
        if (rem >= 2) { CPA_WAIT(2); } else if (rem == 1) { CPA_WAIT(1); } else { CPA_WAIT(0); }
        __syncthreads();
        if (c + 3 < NC) ISSUE(c+3, (c+3)&3);
        uint32_t sA = sb + (c&3)*GSTG;
        #pragma unroll
        for (int kk = 0; kk < 32; kk += 16){
            uint32_t ah[2][4];
            #pragma unroll
            for (int mt=0; mt<2; mt++)
                ldsm4(ah[mt], sA + sw_off(warpM*32 + mt*16 + lr, kk + lc));
            #pragma unroll
            for (int nb=0; nb<4; nb++){
                uint32_t bh[4];
                ldsm4(bh, sA + 8192 + sw_off(warpN*64 + nb*16 + lr, kk + lc));
                #pragma unroll
                for (int mt=0; mt<2; mt++){
                    mma16816(acc[mt][nb*2+0], ah[mt], bh[0], bh[2]);
                    mma16816(acc[mt][nb*2+1], ah[mt], bh[1], bh[3]);
                }
            }
        }
    }

    const int g = lane >> 2, t2 = (lane & 3) << 1;
    if (EPI == 0){
        #pragma unroll
        for (int mt=0; mt<2; mt++){
            int m = m0 + warpM*32 + mt*16 + g;
            #pragma unroll
            for (int ni=0; ni<8; ni++){
                int n = n0 + warpN*64 + ni*8 + t2;
                *(float2*)(Cg + (size_t)m*N + n) = make_float2(acc[mt][ni][0], acc[mt][ni][1]);
                *(float2*)(Cg + (size_t)(m+8)*N + n) = make_float2(acc[mt][ni][2], acc[mt][ni][3]);
            }
        }
    } else if (EPI == 1){
        float* ep = (float*)smem;   // 64 x 136
        #pragma unroll
        for (int slab=0; slab<2; slab++){
            __syncthreads();
            if (warpN == slab){
                #pragma unroll
                for (int mt=0; mt<2; mt++){
                    int mloc = warpM*32 + mt*16 + g;
                    #pragma unroll
                    for (int ni=0; ni<8; ni++){
                        int nL = ni*8 + t2;
                        ep[nL*136 + mloc]         = acc[mt][ni][0];
                        ep[(nL+1)*136 + mloc]     = acc[mt][ni][1];
                        ep[nL*136 + mloc + 8]     = acc[mt][ni][2];
                        ep[(nL+1)*136 + mloc + 8] = acc[mt][ni][3];
                    }
                }
            }
            __syncthreads();
            #pragma unroll
            for (int i=0;i<8;i++){
                int idx = tid + (i << 8);
                int nr = idx >> 5, t4 = (idx & 31) << 2;
                float a0 = fmaxf(ep[nr*136 + t4 + 0], 0.f);
                float a1 = fmaxf(ep[nr*136 + t4 + 1], 0.f);
                float a2 = fmaxf(ep[nr*136 + t4 + 2], 0.f);
                float a3 = fmaxf(ep[nr*136 + t4 + 3], 0.f);
                int n = n0 + slab*64 + nr;
                size_t o = ((size_t)b*N + n)*1024 + tb + t4;
                *(uint2*)(Chf + o) = make_uint2(
                    pack2(__float2half_rn(a0*a0), __float2half_rn(a1*a1)),
                    pack2(__float2half_rn(a2*a2), __float2half_rn(a3*a3)));
            }
        }
    } else {
        // fused final: out = x1 + mlp*sigmoid(acc)*(1 + 0.1*tanh(ca))*vitf[row]
        #pragma unroll
        for (int mt=0; mt<2; mt++){
            int m = m0 + warpM*32 + mt*16 + g;
            float vf0 = VF[m], vf1 = VF[m+8];
            #pragma unroll
            for (int ni=0; ni<8; ni++){
                int n = n0 + warpN*64 + ni*8 + t2;
                size_t i0 = (size_t)m*1024 + n;
                size_t i1 = (size_t)(m+8)*1024 + n;
                float2 x0 = *(const float2*)(X1 + i0), x1v = *(const float2*)(X1 + i1);
                float2 m0v = *(const float2*)(MLP + i0), m1v = *(const float2*)(MLP + i1);
                float2 c0v = *(const float2*)(CA + i0),  c1v = *(const float2*)(CA + i1);
                float2 o0, o1;
                o0.x = x0.x + m0v.x*(1.f/(1.f + expf(-acc[mt][ni][0])))*(1.f + 0.1f*tanhf(c0v.x))*vf0;
                o0.y = x0.y + m0v.y*(1.f/(1.f + expf(-acc[mt][ni][1])))*(1.f + 0.1f*tanhf(c0v.y))*vf0;
                o1.x = x1v.x + m1v.x*(1.f/(1.f + expf(-acc[mt][ni][2])))*(1.f + 0.1f*tanhf(c1v.x))*vf1;
                o1.y = x1v.y + m1v.y*(1.f/(1.f + expf(-acc[mt][ni][3])))*(1.f + 0.1f*tanhf(c1v.y))*vf1;
                *(float2*)(Og + i0) = o0;
                *(float2*)(Og + i1) = o1;
            }
        }
    }
}

// ---------------- small-N (=32) GEMM ----------------
template<int EPI>
__global__ void __launch_bounds__(256)
gemm32_kernel(const float* __restrict__ A, const float* __restrict__ W, float* __restrict__ Cg){
    __shared__ float xs[8*1024];
    int row0 = blockIdx.x << 3;
    #pragma unroll
    for (int i = 0; i < 8; i++){
        int f4 = threadIdx.x + (i << 8);
        ((float4*)xs)[f4] = ((const float4*)(A + ((size_t)row0 << 10)))[f4];
    }
    __syncthreads();
    int w = threadIdx.x >> 5, n = threadIdx.x & 31;
    const float4* Wr = (const float4*)(W + (size_t)n*1024);
    const float4* xr = (const float4*)(xs + (w << 10));
    float acc = 0.f;
    #pragma unroll 4
    for (int k = 0; k < 256; k++){
        float4 a = xr[k], b = Wr[k];
        acc += a.x*b.x + a.y*b.y + a.z*b.z + a.w*b.w;
    }
    if (EPI == 2) acc = 0.5f*acc*(1.f + erff(acc*0.70710678118f));
    Cg[((size_t)(row0 + w) << 5) + n] = acc;
}

// ---------------- FFMA GEMM (ca_po, K=32) ----------------
__global__ void __launch_bounds__(256,2)
gemm_k32(const float* __restrict__ A, const float* __restrict__ W,
         float* __restrict__ Cg, int N){
    __shared__ float As[32*132];
    __shared__ float Ws[32*132];
    const int tx = threadIdx.x & 15, ty = threadIdx.x >> 4;
    const int m0 = blockIdx.y << 7, n0 = blockIdx.x << 7;
    float acc[8][8];
    #pragma unroll
    for (int i=0;i<8;i++)
        #pragma unroll
        for (int j=0;j<8;j++) acc[i][j]=0.f;
    const int r = threadIdx.x >> 1;
    const int c4 = (threadIdx.x & 1) << 4;
    #pragma unroll
    for (int q=0;q<4;q++){
        float4 a0 = *(const float4*)(A + (size_t)(m0+r)*32 + c4 + q*4);
        As[(c4+q*4+0)*132 + r] = a0.x; As[(c4+q*4+1)*132 + r] = a0.y;
        As[(c4+q*4+2)*132 + r] = a0.z; As[(c4+q*4+3)*132 + r] = a0.w;
        float4 w0 = *(const float4*)(W + (size_t)(n0+r)*32 + c4 + q*4);
        Ws[(c4+q*4+0)*132 + r] = w0.x; Ws[(c4+q*4+1)*132 + r] = w0.y;
        Ws[(c4+q*4+2)*132 + r] = w0.z; Ws[(c4+q*4+3)*132 + r] = w0.w;
    }
    __syncthreads();
    #pragma unroll
    for (int kk=0; kk<32; kk++){
        float av[8], bv[8];
        *(float4*)&av[0] = *(const float4*)(As + kk*132 + (ty<<3));
        *(float4*)&av[4] = *(const float4*)(As + kk*132 + (ty<<3) + 4);
        *(float4*)&bv[0] = *(const float4*)(Ws + kk*132 + (tx<<3));
        *(float4*)&bv[4] = *(const float4*)(Ws + kk*132 + (tx<<3) + 4);
        #pragma unroll
        for (int i=0;i<8;i++)
            #pragma unroll
            for (int j=0;j<8;j++) acc[i][j] += av[i]*bv[j];
    }
    #pragma unroll
    for (int i=0;i<8;i++){
        int mg = m0 + (ty<<3) + i;
        #pragma unroll
        for (int j=0;j<8;j++)
            Cg[(size_t)mg*N + n0 + (tx<<3) + j] = acc[i][j];
    }
}

// ---------------- VE gate + V -> transposed fp16 ----------------
__global__ void vgate_kernel(const float* __restrict__ xn, const float* __restrict__ ve,
                             const float* __restrict__ wg, const float* __restrict__ qkv,
                             h16* __restrict__ vhi){
    int row = blockIdx.x;
    __shared__ float gs[4];
    if (threadIdx.x < 4){
        float s = 0.f;
        #pragma unroll
        for (int c=0;c<12;c++) s += xn[(size_t)row*Cv + c]*wg[threadIdx.x*12 + c];
        gs[threadIdx.x] = 3.f/(1.f + expf(-s));
    }
    __syncthreads();
    int i = threadIdx.x;
    int kv = i >> 6, d = i & 63;
    float vv = qkv[(size_t)row*1536 + 1280 + i] + gs[kv]*ve[(size_t)row*256 + i];
    size_t o = ((size_t)((row>>10)*4 + kv)*64 + d)*1024 + (row & 1023);
    vhi[o] = __float2half_rn(vv);
}

// ---------------- rope + per-head rmsnorm*1.2 -> fp16 ----------------
__global__ void ropeRms_kernel(const float* __restrict__ src, int srcStride, int srcOff,
                               h16* __restrict__ dhi,
                               const float* __restrict__ cosb, const float* __restrict__ sinb,
                               int nheads){
    int row  = blockIdx.x;
    int t    = row & (Tv-1);
    int head = blockIdx.y*4 + (threadIdx.x >> 5);
    if (head >= nheads) return;
    int lane = threadIdx.x & 31;
    const float* p = src + (size_t)row*srcStride + srcOff + head*HD;
    float x1 = p[lane], x2 = p[lane+32];
    float cc = cosb[t*32 + lane], sn = sinb[t*32 + lane];
    float o1 =  x1*cc + x2*sn;
    float o2 = -x1*sn + x2*cc;
    float ss = o1*o1 + o2*o2;
    for (int off=16; off>0; off>>=1) ss += __shfl_xor_sync(0xffffffffu, ss, off);
    float rr = rsqrtf(ss*(1.0f/HD) + 1e-6f)*1.2f;
    size_t base = ((size_t)row*nheads + head)*HD;
    dhi[base+lane]    = __float2half_rn(o1*rr);
    dhi[base+lane+32] = __float2half_rn(o2*rr);
}

// =================== flash attention: single-fp16 QK and PV ===================
#define SM_Q    0
#define SM_KV0  8192
#define SM_KV1  24576
#define SM_PP0  40960
#define SM_PP1  58752
#define SM_S    76544
#define SM_PHI  95488
#define SM_CORR 103680
#define SM_LINV 103936
#define ATTN_SMEM 104192

__global__ void __launch_bounds__(256)
attn_kernel(const h16* __restrict__ qhi,
            const h16* __restrict__ khi, const h16* __restrict__ vhi,
            const float* __restrict__ prev, const float* __restrict__ rw,
            const float* __restrict__ alphap,
            h16* __restrict__ yh){
    extern __shared__ char smc[];
    uint32_t sb = smem_u32(smc);
    float* S      = (float*)(smc + SM_S);
    float* corr_s = (float*)(smc + SM_CORR);
    float* linv   = (float*)(smc + SM_LINV);

    const int tid = threadIdx.x, lane = tid & 31, wid = tid >> 5;
    const int warpM = wid & 3, warpN = wid >> 2;
    const int row = tid >> 2, quad = tid & 3, c0 = quad << 4;
    const int qt = (int)gridDim.x - 1 - (int)blockIdx.x;   // long CTAs first
    const int h = blockIdx.y, b = blockIdx.z;
    const int q0 = qt << 6;
    const int kvh = h >> 2;
    const int lr = lane & 15, lc = (lane < 16) ? 0 : 8;
    const int g = lane >> 2, t2 = (lane & 3) << 1;

    const float alpha = alphap[0];
    float w9[9];
    #pragma unroll
    for (int i=0;i<9;i++) w9[i] = alpha*rw[h*9 + i];

    const float* prevB = prev + ((size_t)(b*NH + h))*Tv*Tv;

    auto issueKV = [&](int kt, int s){
        int k0 = kt << 6;
        uint32_t kvb = sb + SM_KV0 + s*16384;
        #pragma unroll
        for (int i=0;i<4;i++){
            int idx = tid + (i << 8);
            int arr = idx >> 9, rr = (idx >> 3) & 63, kc = idx & 7;
            const h16* src;
            if (arr == 0) src = khi + ((((size_t)(b*Tv + k0 + rr))*NKV + kvh) << 6) + (kc << 3);
            else          src = vhi + (((size_t)((b*NKV + kvh)*64 + rr)) << 10) + k0 + (kc << 3);
            cpa16(kvb + arr*8192 + sw128(rr, kc << 3), src);
        }
    };
    auto issuePP = [&](int kt, int s){
        int k0 = kt << 6;
        uint32_t ppb = sb + SM_PP0 + s*17792;
        for (int idx = tid; idx < 66*66; idx += 256){
            int i = idx/66, j = idx - i*66;
            int rr = q0 - 1 + i, cg = k0 - 1 + j;
            int ok = (rr >= 0 && rr < Tv && cg >= 0 && cg < Tv) ? 4 : 0;
            int rrc = rr < 0 ? 0 : (rr > 1023 ? 1023 : rr);
            int cgc = cg < 0 ? 0 : (cg > 1023 ? 1023 : cg);
            cpa4z(ppb + (uint32_t)(i*67 + j)*4, prevB + (size_t)rrc*Tv + cgc, ok);
        }
    };

    {
        #pragma unroll
        for (int i=0;i<2;i++){
            int idx = tid + (i << 8);
            int rr = idx >> 3, kc = idx & 7;
            const h16* src = qhi + ((((size_t)(b*Tv + q0 + rr))*NH + h) << 6) + (kc << 3);
            cpa16(sb + SM_Q + sw128(rr, kc << 3), src);
        }
        CPA_COMMIT();
        issueKV(0,0); issuePP(0,0);
        CPA_COMMIT();
    }

    float o[4][4];
    #pragma unroll
    for (int i=0;i<4;i++)
        #pragma unroll
        for (int j=0;j<4;j++) o[i][j]=0.f;
    float m = -1e30f, l = 0.f;

    for (int kt = 0; kt <= qt; kt++){
        int s = kt & 1;
        CPA_WAIT(0);
        __syncthreads();
        if (kt < qt){ issueKV(kt+1, s^1); issuePP(kt+1, s^1); CPA_COMMIT(); }
        uint32_t kvb = sb + SM_KV0 + s*16384;
        float* PP = (float*)(smc + SM_PP0 + s*17792);

        float c[4][4];
        #pragma unroll
        for (int i=0;i<4;i++)
            #pragma unroll
            for (int j=0;j<4;j++) c[i][j]=0.f;
        #pragma unroll
        for (int k16 = 0; k16 < 4; k16++){
            uint32_t qh_[4];
            ldsm4(qh_, sb + SM_Q + sw128(warpM*16 + lr, k16*16 + lc));
            #pragma unroll
            for (int nb=0; nb<2; nb++){
                uint32_t kh_[4];
                ldsm4(kh_, kvb + sw128(warpN*32 + nb*16 + lr, k16*16 + lc));
                mma16816(c[nb*2+0], qh_, kh_[0], kh_[2]);
                mma16816(c[nb*2+1], qh_, kh_[1], kh_[3]);
            }
        }
        #pragma unroll
        for (int ni=0; ni<4; ni++){
            int col = warpN*32 + ni*8 + t2;
            int r0 = warpM*16 + g;
            *(float2*)(S + r0*74 + col)     = make_float2(c[ni][0], c[ni][1]);
            *(float2*)(S + (r0+8)*74 + col) = make_float2(c[ni][2], c[ni][3]);
        }
        __syncthreads();

        float p[3][18];
        #pragma unroll
        for (int i=0;i<3;i++)
            #pragma unroll
            for (int e=0;e<18;e++) p[i][e] = PP[(row+i)*67 + c0 + e];
        float sr[16];
        #pragma unroll
        for (int j=0;j<16;j++){
            float cv = w9[0]*p[0][j] + w9[1]*p[0][j+1] + w9[2]*p[0][j+2]
                     + w9[3]*p[1][j] + w9[4]*p[1][j+1] + w9[5]*p[1][j+2]
                     + w9[6]*p[2][j] + w9[7]*p[2][j+1] + w9[8]*p[2][j+2];
            int col = c0 + j;
            sr[j] = S[row*74 + col]*0.125f + cv;
            if (kt == qt && col > row) sr[j] = -1e30f;
        }
        float mt = sr[0];
        #pragma unroll
        for (int j=1;j<16;j++) mt = fmaxf(mt, sr[j]);
        for (int off=1; off<4; off<<=1) mt = fmaxf(mt, __shfl_xor_sync(0xffffffffu, mt, off));
        float mnew = fmaxf(m, mt);
        float corrv = __expf(m - mnew);
        float ls = 0.f;
        #pragma unroll
        for (int j=0;j<16;j++){ sr[j] = __expf(sr[j] - mnew); ls += sr[j]; }
        for (int off=1; off<4; off<<=1) ls += __shfl_xor_sync(0xffffffffu, ls, off);
        l = l*corrv + ls;
        m = mnew;
        if (quad == 0) corr_s[row] = corrv;
        #pragma unroll
        for (int j=0;j<16;j+=2){
            int col = c0 + j;
            *(uint32_t*)(smc + SM_PHI + sw128(row, col)) =
                pack2(__float2half_rn(sr[j]), __float2half_rn(sr[j+1]));
        }
        __syncthreads();

        float cr0 = corr_s[warpM*16 + g], cr1 = corr_s[warpM*16 + g + 8];
        #pragma unroll
        for (int ni=0; ni<4; ni++){
            o[ni][0] *= cr0; o[ni][1] *= cr0;
            o[ni][2] *= cr1; o[ni][3] *= cr1;
        }
        #pragma unroll
        for (int k16 = 0; k16 < 4; k16++){
            uint32_t ph_[4];
            ldsm4(ph_, sb + SM_PHI + sw128(warpM*16 + lr, k16*16 + lc));
            #pragma unroll
            for (int nb=0; nb<2; nb++){
                uint32_t vh_[4];
                ldsm4(vh_, kvb + 8192 + sw128(warpN*32 + nb*16 + lr, k16*16 + lc));
                mma16816(o[nb*2+0], ph_, vh_[0], vh_[2]);
                mma16816(o[nb*2+1], ph_, vh_[1], vh_[3]);
            }
        }
    }

    if (quad == 0) linv[row] = 1.f/l;
    __syncthreads();
    float i0 = linv[warpM*16 + g], i1 = linv[warpM*16 + g + 8];
    #pragma unroll
    for (int ni=0; ni<4; ni++){
        int col = warpN*32 + ni*8 + t2;
        size_t base0 = ((((size_t)(b*Tv + q0 + warpM*16 + g))*NH + h) << 6) + col;
        size_t base1 = ((((size_t)(b*Tv + q0 + warpM*16 + g + 8))*NH + h) << 6) + col;
        *(uint32_t*)(yh + base0) = pack2(__float2half_rn(o[ni][0]*i0), __float2half_rn(o[ni][1]*i0));
        *(uint32_t*)(yh + base1) = pack2(__float2half_rn(o[ni][2]*i1), __float2half_rn(o[ni][3]*i1));
    }
}

// ---------------- CA conv + gelu ----------------
__global__ void caconv_kernel(const float* __restrict__ hin, const float* __restrict__ cw,
                              float* __restrict__ hout){
    int ch = blockIdx.x, b = blockIdx.y;
    __shared__ float s[Tv+2];
    for (int t = threadIdx.x; t < Tv; t += 256) s[1+t] = hin[((size_t)b*Tv + t)*32 + ch];
    if (threadIdx.x == 0){ s[0] = 0.f; s[Tv+1] = 0.f; }
    __syncthreads();
    float w0 = cw[ch*3], w1 = cw[ch*3+1], w2 = cw[ch*3+2];
    for (int t = threadIdx.x; t < Tv; t += 256){
        float vv = s[1+t] + 0.1f*(w0*s[t] + w1*s[1+t] + w2*s[2+t]);
        hout[((size_t)b*Tv + t)*32 + ch] = 0.5f*vv*(1.f + erff(vv*0.70710678118f));
    }
}

// ---------------- FFN conv x4 ----------------
#define FFNC_SMEM (2*16*1026*4)
__global__ void __launch_bounds__(256)
ffnconvT_kernel(const h16* __restrict__ hf, const float* __restrict__ cw,
                h16* __restrict__ hs){
    extern __shared__ float fs[];
    float (*buf0)[1026] = (float(*)[1026])fs;
    float (*buf1)[1026] = (float(*)[1026])(fs + 16*1026);
    int f0 = blockIdx.x << 4, b = blockIdx.y;
    for (int idx4 = threadIdx.x; idx4 < 16*256; idx4 += 256){
        int cch = idx4 >> 8, t4 = (idx4 & 255) << 2;
        size_t o = ((size_t)(b*FFH + f0 + cch))*Tv + t4;
        uint2 u = *(const uint2*)(hf + o);
        const h16* ph = (const h16*)&u;
        #pragma unroll
        for (int e=0;e<4;e++) buf0[cch][1+t4+e] = __half2float(ph[e]);
    }
    if (threadIdx.x < 16){
        buf0[threadIdx.x][0] = 0.f; buf0[threadIdx.x][1025] = 0.f;
        buf1[threadIdx.x][0] = 0.f; buf1[threadIdx.x][1025] = 0.f;
    }
    int cch = threadIdx.x >> 4, j = threadIdx.x & 15;
    float w0 = cw[(f0+cch)*3], w1 = cw[(f0+cch)*3+1], w2 = cw[(f0+cch)*3+2];
    float (*cur)[1026] = buf0; float (*nxt)[1026] = buf1;
    #pragma unroll
    for (int it=0; it<4; it++){
        __syncthreads();
        #pragma unroll 4
        for (int t = j*64; t < j*64 + 64; t++)
            nxt[cch][1+t] = cur[cch][1+t] + 0.1f*(w0*cur[cch][t] + w1*cur[cch][1+t] + w2*cur[cch][2+t]);
        float (*tmp)[1026] = cur; cur = nxt; nxt = tmp;
    }
    __syncthreads();
    for (int t = threadIdx.x; t < Tv; t += 256){
        uint32_t wv[8];
        #pragma unroll
        for (int cc = 0; cc < 16; cc += 2)
            wv[cc>>1] = pack2(__float2half_rn(cur[cc][1+t]), __float2half_rn(cur[cc+1][1+t]));
        size_t o = ((size_t)(b*Tv + t))*FFH + f0;
        *(uint4*)(hs + o)     = make_uint4(wv[0],wv[1],wv[2],wv[3]);
        *(uint4*)(hs + o + 8) = make_uint4(wv[4],wv[5],wv[6],wv[7]);
    }
}

// ---------------- elementwise ----------------
__global__ void vit2_kernel(const float* __restrict__ h32, const float* __restrict__ w2,
                            float* __restrict__ out){
    int row  = blockIdx.x*8 + (threadIdx.x >> 5);
    int lane = threadIdx.x & 31;
    float vv = h32[(size_t)row*32 + lane]*w2[lane];
    for (int off=16; off>0; off>>=1) vv += __shfl_xor_sync(0xffffffffu, vv, off);
    if (lane == 0) out[row] = 1.f/(1.f + expf(-vv));
}
__global__ void vitsmooth_kernel(const float* __restrict__ vin, float* __restrict__ vout){
    int b = blockIdx.x;
    __shared__ float s[Tv+4];
    for (int t = threadIdx.x; t < Tv; t += 256) s[2+t] = vin[b*Tv + t];
    if (threadIdx.x < 2){ s[threadIdx.x] = 0.f; s[Tv+2+threadIdx.x] = 0.f; }
    __syncthreads();
    for (int t = threadIdx.x; t < Tv; t += 256){
        float vs = (s[t] + s[t+1] + s[t+2] + s[t+3] + s[t+4])*0.2f;
        float vv = 0.7f*s[2+t] + 0.3f*vs;
        vout[b*Tv + t] = (vv > 0.3f) ? vv : 0.1f*vv;
    }
}

// ---------------- launch ----------------
extern "C" void kernel_launch(void* const* d_in, const int* in_sizes, int n_in,
                              void* d_out, int out_size){
    const float* x     = (const float*)d_in[0];
    const float* ve    = (const float*)d_in[1];
    const float* cosp  = (const float*)d_in[2];
    const float* sinp  = (const float*)d_in[3];
    const float* prev  = (const float*)d_in[4];
    const float* w_q   = (const float*)d_in[5];
    const float* w_k   = (const float*)d_in[6];
    const float* w_v   = (const float*)d_in[7];
    const float* w_o   = (const float*)d_in[8];
    const float* w_veg = (const float*)d_in[9];
    const float* rfw   = (const float*)d_in[10];
    const float* ralpha= (const float*)d_in[11];
    const float* ca_pi = (const float*)d_in[12];
    const float* ca_cw = (const float*)d_in[13];
    const float* ca_po = (const float*)d_in[14];
    const float* ffn_in= (const float*)d_in[15];
    const float* ffn_cw= (const float*)d_in[16];
    const float* ffn_outw=(const float*)d_in[17];
    const float* ffn_gt= (const float*)d_in[18];
    const float* vit_w1= (const float*)d_in[19];
    const float* vit_w2= (const float*)d_in[20];
    float* out = (float*)d_out;

    float *xn,*qkv,*attn,*ca,*cah,*cah2,*x1,*mlp,*vit32,*vitv,*vitf;
    h16 *xnh,*xmh,*yh,*qh,*kh,*vh,*hf,*hs;
    h16 *wqkv,*wo,*fin,*fout,*fgt;
    cudaGetSymbolAddress((void**)&xn, g_xn);     cudaGetSymbolAddress((void**)&qkv, g_qkv);
    cudaGetSymbolAddress((void**)&attn, g_attn); cudaGetSymbolAddress((void**)&ca, g_ca);
    cudaGetSymbolAddress((void**)&cah, g_cah);   cudaGetSymbolAddress((void**)&cah2, g_cah2);
    cudaGetSymbolAddress((void**)&x1, g_x1);
    cudaGetSymbolAddress((void**)&mlp, g_mlp);
    cudaGetSymbolAddress((void**)&vit32, g_vit32); cudaGetSymbolAddress((void**)&vitv, g_vitv);
    cudaGetSymbolAddress((void**)&vitf, g_vitf);
    cudaGetSymbolAddress((void**)&xnh, g_xn_h);
    cudaGetSymbolAddress((void**)&xmh, g_xm_h);
    cudaGetSymbolAddress((void**)&yh, g_y_h);
    cudaGetSymbolAddress((void**)&qh, g_q_h);
    cudaGetSymbolAddress((void**)&kh, g_k_h);
    cudaGetSymbolAddress((void**)&vh, g_v_h);
    cudaGetSymbolAddress((void**)&hf, g_hf);     cudaGetSymbolAddress((void**)&hs, g_hs);
    cudaGetSymbolAddress((void**)&wqkv, g_wqkv);
    cudaGetSymbolAddress((void**)&wo, g_wo);
    cudaGetSymbolAddress((void**)&fin, g_fin);
    cudaGetSymbolAddress((void**)&fout, g_fout);
    cudaGetSymbolAddress((void**)&fgt, g_fgt);

    cudaFuncSetAttribute(attn_kernel, cudaFuncAttributeMaxDynamicSharedMemorySize, ATTN_SMEM);
    cudaFuncSetAttribute(gemm_f16<0>, cudaFuncAttributeMaxDynamicSharedMemorySize, GEMM_SMEM);
    cudaFuncSetAttribute(gemm_f16<1>, cudaFuncAttributeMaxDynamicSharedMemorySize, GEMM_SMEM);
    cudaFuncSetAttribute(gemm_f16<2>, cudaFuncAttributeMaxDynamicSharedMemorySize, GEMM_SMEM);
    cudaFuncSetAttribute(ffnconvT_kernel, cudaFuncAttributeMaxDynamicSharedMemorySize, FFNC_SMEM);

    cvt_kernel<<<256,256>>>(w_q, wqkv, 262144);
    cvt_kernel<<<64,256>>>(w_k, wqkv + 1024*1024, 65536);
    cvt_kernel<<<64,256>>>(w_v, wqkv + 1280*1024, 65536);
    rms_kernel<1><<<MT,256>>>(x, xn, xnh);
    cvt_kernel<<<256,256>>>(w_o, wo, 262144);
    gemm_f16<0><<<dim3(12,32),256,GEMM_SMEM>>>(xnh, wqkv, qkv, 0, 0,0,0,0, 0, 1536, 1024);

    vgate_kernel<<<MT,256>>>(xn, ve, w_veg, qkv, vh);
    ropeRms_kernel<<<dim3(MT,4),128>>>(qkv, 1536, 0,    qh, cosp, sinp, NH);
    ropeRms_kernel<<<dim3(MT,1),128>>>(qkv, 1536, 1024, kh, cosp, sinp, NKV);

    attn_kernel<<<dim3(16,NH,Bv),256,ATTN_SMEM>>>(qh, kh, vh, prev, rfw, ralpha, yh);
    gemm_f16<0><<<dim3(8,32),256,GEMM_SMEM>>>(yh, wo, attn, 0, 0,0,0,0, 0, 1024, 1024);

    cvt_kernel<<<1024,256>>>(ffn_in, fin, 1048576);
    cvt_kernel<<<1024,256>>>(ffn_outw, fout, 1048576);
    cvt_kernel<<<256,256>>>(ffn_gt, fgt, 262144);

    gemm32_kernel<0><<<512,256>>>(x, ca_pi, cah);
    caconv_kernel<<<dim3(32,Bv),256>>>(cah, ca_cw, cah2);
    gemm_k32<<<dim3(8,32),256>>>(cah2, ca_po, ca, 1024);
    x1rms_kernel<<<MT,256>>>(x, attn, ca, x1, xmh);

    gemm_f16<1><<<dim3(32,32),256,GEMM_SMEM>>>(xmh, fin, 0, hf, 0,0,0,0, 0, FFH, 1024);
    ffnconvT_kernel<<<dim3(256,Bv),256,FFNC_SMEM>>>(hf, ffn_cw, hs);
    gemm_f16<0><<<dim3(8,32),256,GEMM_SMEM>>>(hs, fout, mlp, 0, 0,0,0,0, 0, 1024, 4096);

    // ca2 on x1, vit gate (before fused gate GEMM)
    gemm32_kernel<0><<<512,256>>>(x1, ca_pi, cah);
    caconv_kernel<<<dim3(32,Bv),256>>>(cah, ca_cw, cah2);
    gemm_k32<<<dim3(8,32),256>>>(cah2, ca_po, ca, 1024);

    gemm32_kernel<2><<<512,256>>>(x1, vit_w1, vit32);
    vit2_kernel<<<512,256>>>(vit32, vit_w2, vitv);
    vitsmooth_kernel<<<Bv,256>>>(vitv, vitf);

    // gate GEMM with fused final epilogue -> out
    gemm_f16<2><<<dim3(8,32),256,GEMM_SMEM>>>(xmh, fgt, 0, 0, x1, mlp, ca, vitf, out, 1024, 1024);
}

// round 11
// speedup vs baseline: 1.6518x; 1.0073x over previous
#include <cuda_runtime.h>
#include <cuda_fp16.h>
#include <math.h>
#include <stdint.h>

#define Bv  4
#define Tv  1024
#define Cv  1024
#define NH  16
#define NKV 4
#define HD  64
#define FFH 4096
#define MT  (Bv*Tv)

typedef __half h16;

// ---------------- fp32 scratch ----------------
__device__ float g_xn  [MT*Cv];
__device__ float g_qkv [MT*1536];
__device__ float g_attn[MT*Cv];
__device__ float g_ca  [MT*Cv];
__device__ float g_cah [MT*32];
__device__ float g_cah2[MT*32];
__device__ float g_x1  [MT*Cv];
__device__ float g_mlp [MT*Cv];
__device__ float g_vit32[MT*32];
__device__ float g_vitv[MT];
__device__ float g_vitf[MT];

// ---------------- fp16 scratch ----------------
__device__ h16 g_xn_h[MT*Cv];
__device__ h16 g_xm_h[MT*Cv];
__device__ h16 g_y_h [MT*Cv];
__device__ h16 g_q_h [MT*1024];                  // (b,t,h,d)
__device__ h16 g_k_h [MT*256];                   // (b,t,kv,d)
__device__ h16 g_v_h [MT*256];                   // (b,kv,d,t)
__device__ h16 g_hf  [(size_t)MT*FFH];           // (b,f,t)
__device__ h16 g_hs  [(size_t)MT*FFH];           // (b,t,f)
__device__ h16 g_wqkv[1536*1024];
__device__ h16 g_wo  [1024*1024];
__device__ h16 g_fin [FFH*1024];
__device__ h16 g_fout[1024*FFH];
__device__ h16 g_fgt [1024*1024];

// =================== helpers ===================
__device__ __forceinline__ uint32_t smem_u32(const void* p){
    uint32_t a;
    asm("{ .reg .u64 t; cvta.to.shared.u64 t, %1; cvt.u32.u64 %0, t; }" : "=r"(a) : "l"(p));
    return a;
}
__device__ __forceinline__ void mma16816(float* c, const uint32_t* a, uint32_t b0, uint32_t b1){
    asm volatile("mma.sync.aligned.m16n8k16.row.col.f32.f16.f16.f32 "
        "{%0,%1,%2,%3}, {%4,%5,%6,%7}, {%8,%9}, {%0,%1,%2,%3};"
        : "+f"(c[0]), "+f"(c[1]), "+f"(c[2]), "+f"(c[3])
        : "r"(a[0]), "r"(a[1]), "r"(a[2]), "r"(a[3]), "r"(b0), "r"(b1));
}
__device__ __forceinline__ void ldsm4(uint32_t* r, uint32_t addr){
    asm volatile("ldmatrix.sync.aligned.m8n8.x4.shared.b16 {%0,%1,%2,%3}, [%4];"
        : "=r"(r[0]), "=r"(r[1]), "=r"(r[2]), "=r"(r[3]) : "r"(addr));
}
__device__ __forceinline__ void cpa16(uint32_t saddr, const void* g){
    asm volatile("cp.async.cg.shared.global [%0], [%1], 16;" :: "r"(saddr), "l"(g));
}
__device__ __forceinline__ void cpa4z(uint32_t saddr, const void* g, int srcsz){
    asm volatile("cp.async.ca.shared.global [%0], [%1], 4, %2;" :: "r"(saddr), "l"(g), "r"(srcsz));
}
#define CPA_COMMIT() asm volatile("cp.async.commit_group;" ::: "memory")
#define CPA_WAIT(n)  asm volatile("cp.async.wait_group %0;" :: "n"(n) : "memory")

__device__ __forceinline__ uint32_t sw_off(int row, int k){
    int chunk = (k >> 3) ^ ((row >> 1) & 3);
    return (uint32_t)(row*64 + chunk*16 + (k & 7)*2);
}
__device__ __forceinline__ uint32_t sw128(int row, int k){
    return (uint32_t)(row*128 + ((((k>>3) ^ (row & 7)) << 4) | ((k & 7) << 1)));
}
__device__ __forceinline__ uint32_t pack2(h16 a, h16 b){
    return ((uint32_t)__half_as_ushort(b) << 16) | __half_as_ushort(a);
}
__device__ __forceinline__ float tanh_fast(float x){
    float y; asm("tanh.approx.f32 %0, %1;" : "=f"(y) : "f"(x)); return y;
}
__device__ __forceinline__ uint32_t ex2_f16x2(float a, float b){
    __half2 hx = __floats2half2_rn(a, b);
    uint32_t r;
    asm("ex2.approx.f16x2 %0, %1;" : "=r"(r) : "r"(*(uint32_t*)&hx));
    return r;
}

// ---------------- fp32 -> fp16 convert ----------------
__global__ void cvt_kernel(const float* __restrict__ src, h16* __restrict__ dst, int n4){
    int i0 = blockIdx.x*1024 + threadIdx.x;
    #pragma unroll
    for (int j = 0; j < 4; j++){
        int i = i0 + (j << 8);
        if (i < n4){
            float4 v = ((const float4*)src)[i];
            ((uint2*)dst)[i] = make_uint2(
                pack2(__float2half_rn(v.x), __float2half_rn(v.y)),
                pack2(__float2half_rn(v.z), __float2half_rn(v.w)));
        }
    }
}

// ---------------- rmsnorm (fp32 + fp16), vectorized ----------------
template<int WF32>
__global__ void rms_kernel(const float* __restrict__ x, float* __restrict__ o32,
                           h16* __restrict__ ohi){
    int row = blockIdx.x;
    const float4* xr = (const float4*)(x + (size_t)row*Cv);
    float4 v = xr[threadIdx.x];
    float ss = v.x*v.x + v.y*v.y + v.z*v.z + v.w*v.w;
    __shared__ float red[8];
    for (int off=16; off>0; off>>=1) ss += __shfl_xor_sync(0xffffffffu, ss, off);
    if ((threadIdx.x & 31) == 0) red[threadIdx.x>>5] = ss;
    __syncthreads();
    if (threadIdx.x < 8){
        float t = red[threadIdx.x];
        for (int off=4; off>0; off>>=1) t += __shfl_xor_sync(0x000000ffu, t, off);
        if (threadIdx.x == 0) red[0] = t;
    }
    __syncthreads();
    float r = rsqrtf(red[0]*(1.0f/Cv) + 1e-6f);
    float4 o = make_float4(v.x*r, v.y*r, v.z*r, v.w*r);
    if (WF32) ((float4*)(o32 + (size_t)row*Cv))[threadIdx.x] = o;
    ((uint2*)(ohi + (size_t)row*Cv))[threadIdx.x] = make_uint2(
        pack2(__float2half_rn(o.x), __float2half_rn(o.y)),
        pack2(__float2half_rn(o.z), __float2half_rn(o.w)));
}

// ---------------- fused x1 + rmsnorm, vectorized ----------------
__global__ void x1rms_kernel(const float* __restrict__ x, const float* __restrict__ attn,
                             const float* __restrict__ ca, float* __restrict__ x1,
                             h16* __restrict__ ohi){
    int row = blockIdx.x;
    size_t base = (size_t)row*Cv;
    float4 xv = ((const float4*)(x + base))[threadIdx.x];
    float4 av = ((const float4*)(attn + base))[threadIdx.x];
    float4 cv = ((const float4*)(ca + base))[threadIdx.x];
    float4 v;
    v.x = xv.x + av.x*(1.f + 0.1f*tanh_fast(cv.x));
    v.y = xv.y + av.y*(1.f + 0.1f*tanh_fast(cv.y));
    v.z = xv.z + av.z*(1.f + 0.1f*tanh_fast(cv.z));
    v.w = xv.w + av.w*(1.f + 0.1f*tanh_fast(cv.w));
    float ss = v.x*v.x + v.y*v.y + v.z*v.z + v.w*v.w;
    __shared__ float red[8];
    for (int off=16; off>0; off>>=1) ss += __shfl_xor_sync(0xffffffffu, ss, off);
    if ((threadIdx.x & 31) == 0) red[threadIdx.x>>5] = ss;
    __syncthreads();
    if (threadIdx.x < 8){
        float t = red[threadIdx.x];
        for (int off=4; off>0; off>>=1) t += __shfl_xor_sync(0x000000ffu, t, off);
        if (threadIdx.x == 0) red[0] = t;
    }
    __syncthreads();
    float r = rsqrtf(red[0]*(1.0f/Cv) + 1e-6f);
    ((float4*)(x1 + base))[threadIdx.x] = v;
    ((uint2*)(ohi + base))[threadIdx.x] = make_uint2(
        pack2(__float2half_rn(v.x*r), __float2half_rn(v.y*r)),
        pack2(__float2half_rn(v.z*r), __float2half_rn(v.w*r)));
}

// =================== fp16 GEMM: tile 128x128, 256 thr, 2 CTA/SM, 4-stage ===================
#define GSTG 16384
#define GEMM_SMEM (4*GSTG)
template<int EPI>
__global__ void __launch_bounds__(256,2)
gemm_f16(const h16* __restrict__ Ah, const h16* __restrict__ Bh,
         float* __restrict__ Cg, h16* __restrict__ Chf,
         const float* __restrict__ X1, const float* __restrict__ MLP,
         const float* __restrict__ CA, const float* __restrict__ VF,
         float* __restrict__ Og, int N, int K){
    extern __shared__ char smem[];
    const int tid = threadIdx.x, lane = tid & 31, wid = tid >> 5;
    const int warpM = wid & 3, warpN = wid >> 2;   // 4 x 2
    const int m0 = blockIdx.y << 7, n0 = blockIdx.x << 7;
    const int b = m0 >> 10, tb = m0 & 1023;
    uint32_t sb = smem_u32(smem);

    const int r = tid >> 2, kc = tid & 3;
    const h16* aP = Ah + (size_t)(m0+r)*K + (kc<<3);
    const h16* bP = Bh + (size_t)(n0+r)*K + (kc<<3);
    const uint32_t dA0 = sw_off(r, kc<<3);
    const uint32_t dA1 = sw_off(r+64, kc<<3);
    const size_t off64 = (size_t)64*K;

    auto ISSUE = [&](int c, int s){
        int k0 = c << 5;
        uint32_t st = sb + s*GSTG;
        cpa16(st + dA0,        aP + k0);
        cpa16(st + dA1,        aP + off64 + k0);
        cpa16(st + 8192 + dA0, bP + k0);
        cpa16(st + 8192 + dA1, bP + off64 + k0);
        CPA_COMMIT();
    };

    float acc[2][8][4];
    #pragma unroll
    for (int i=0;i<2;i++)
        #pragma unroll
        for (int j=0;j<8;j++)
            #pragma unroll
            for (int q=0;q<4;q++) acc[i][j][q]=0.f;

    const int NC = K >> 5;
    ISSUE(0,0); ISSUE(1,1); ISSUE(2,2);
    const int lr = lane & 15, lc = (lane < 16) ? 0 : 8;
    for (int c = 0; c < NC; c++){
        int rem = NC - 1 - c;
        if (rem >= 2) { CPA_WAIT(2); } else if (rem == 1) { CPA_WAIT(1); } else { CPA_WAIT(0); }
        __syncthreads();
        if (c + 3 < NC) ISSUE(c+3, (c+3)&3);
        uint32_t sA = sb + (c&3)*GSTG;
        #pragma unroll
        for (int kk = 0; kk < 32; kk += 16){
            uint32_t ah[2][4];
            #pragma unroll
            for (int mt=0; mt<2; mt++)
                ldsm4(ah[mt], sA + sw_off(warpM*32 + mt*16 + lr, kk + lc));
            #pragma unroll
            for (int nb=0; nb<4; nb++){
                uint32_t bh[4];
                ldsm4(bh, sA + 8192 + sw_off(warpN*64 + nb*16 + lr, kk + lc));
                #pragma unroll
                for (int mt=0; mt<2; mt++){
                    mma16816(acc[mt][nb*2+0], ah[mt], bh[0], bh[2]);
                    mma16816(acc[mt][nb*2+1], ah[mt], bh[1], bh[3]);
                }
            }
        }
    }

    const int g = lane >> 2, t2 = (lane & 3) << 1;
    if (EPI == 0){
        #pragma unroll
        for (int mt=0; mt<2; mt++){
            int m = m0 + warpM*32 + mt*16 + g;
            #pragma unroll
            for (int ni=0; ni<8; ni++){
                int n = n0 + warpN*64 + ni*8 + t2;
                *(float2*)(Cg + (size_t)m*N + n) = make_float2(acc[mt][ni][0], acc[mt][ni][1]);
                *(float2*)(Cg + (size_t)(m+8)*N + n) = make_float2(acc[mt][ni][2], acc[mt][ni][3]);
            }
        }
    } else if (EPI == 1){
        float* ep = (float*)smem;   // 64 x 136
        #pragma unroll
        for (int slab=0; slab<2; slab++){
            __syncthreads();
            if (warpN == slab){
                #pragma unroll
                for (int mt=0; mt<2; mt++){
                    int mloc = warpM*32 + mt*16 + g;
                    #pragma unroll
                    for (int ni=0; ni<8; ni++){
                        int nL = ni*8 + t2;
                        ep[nL*136 + mloc]         = acc[mt][ni][0];
                        ep[(nL+1)*136 + mloc]     = acc[mt][ni][1];
                        ep[nL*136 + mloc + 8]     = acc[mt][ni][2];
                        ep[(nL+1)*136 + mloc + 8] = acc[mt][ni][3];
                    }
                }
            }
            __syncthreads();
            #pragma unroll
            for (int i=0;i<8;i++){
                int idx = tid + (i << 8);
                int nr = idx >> 5, t4 = (idx & 31) << 2;
                float a0 = fmaxf(ep[nr*136 + t4 + 0], 0.f);
                float a1 = fmaxf(ep[nr*136 + t4 + 1], 0.f);
                float a2 = fmaxf(ep[nr*136 + t4 + 2], 0.f);
                float a3 = fmaxf(ep[nr*136 + t4 + 3], 0.f);
                int n = n0 + slab*64 + nr;
                size_t o = ((size_t)b*N + n)*1024 + tb + t4;
                *(uint2*)(Chf + o) = make_uint2(
                    pack2(__float2half_rn(a0*a0), __float2half_rn(a1*a1)),
                    pack2(__float2half_rn(a2*a2), __float2half_rn(a3*a3)));
            }
        }
    } else {
        // fused final: out = x1 + mlp*sigmoid(acc)*(1 + 0.1*tanh(ca))*vitf[row]
        #pragma unroll
        for (int mt=0; mt<2; mt++){
            int m = m0 + warpM*32 + mt*16 + g;
            float vf0 = VF[m], vf1 = VF[m+8];
            #pragma unroll
            for (int ni=0; ni<8; ni++){
                int n = n0 + warpN*64 + ni*8 + t2;
                size_t i0 = (size_t)m*1024 + n;
                size_t i1 = (size_t)(m+8)*1024 + n;
                float2 x0 = *(const float2*)(X1 + i0), x1v = *(const float2*)(X1 + i1);
                float2 m0v = *(const float2*)(MLP + i0), m1v = *(const float2*)(MLP + i1);
                float2 c0v = *(const float2*)(CA + i0),  c1v = *(const float2*)(CA + i1);
                float2 o0, o1;
                o0.x = x0.x + m0v.x*(0.5f + 0.5f*tanh_fast(0.5f*acc[mt][ni][0]))*(1.f + 0.1f*tanh_fast(c0v.x))*vf0;
                o0.y = x0.y + m0v.y*(0.5f + 0.5f*tanh_fast(0.5f*acc[mt][ni][1]))*(1.f + 0.1f*tanh_fast(c0v.y))*vf0;
                o1.x = x1v.x + m1v.x*(0.5f + 0.5f*tanh_fast(0.5f*acc[mt][ni][2]))*(1.f + 0.1f*tanh_fast(c1v.x))*vf1;
                o1.y = x1v.y + m1v.y*(0.5f + 0.5f*tanh_fast(0.5f*acc[mt][ni][3]))*(1.f + 0.1f*tanh_fast(c1v.y))*vf1;
                *(float2*)(Og + i0) = o0;
                *(float2*)(Og + i1) = o1;
            }
        }
    }
}

// ---------------- small-N (=32) GEMM ----------------
template<int EPI>
__global__ void __launch_bounds__(256)
gemm32_kernel(const float* __restrict__ A, const float* __restrict__ W, float* __restrict__ Cg){
    __shared__ float xs[8*1024];
    int row0 = blockIdx.x << 3;
    #pragma unroll
    for (int i = 0; i < 8; i++){
        int f4 = threadIdx.x + (i << 8);
        ((float4*)xs)[f4] = ((const float4*)(A + ((size_t)row0 << 10)))[f4];
    }
    __syncthreads();
    int w = threadIdx.x >> 5, n = threadIdx.x & 31;
    const float4* Wr = (const float4*)(W + (size_t)n*1024);
    const float4* xr = (const float4*)(xs + (w << 10));
    float acc = 0.f;
    #pragma unroll 4
    for (int k = 0; k < 256; k++){
        float4 a = xr[k], b = Wr[k];
        acc += a.x*b.x + a.y*b.y + a.z*b.z + a.w*b.w;
    }
    if (EPI == 2) acc = 0.5f*acc*(1.f + erff(acc*0.70710678118f));
    Cg[((size_t)(row0 + w) << 5) + n] = acc;
}

// ---------------- FFMA GEMM (ca_po, K=32) ----------------
__global__ void __launch_bounds__(256,2)
gemm_k32(const float* __restrict__ A, const float* __restrict__ W,
         float* __restrict__ Cg, int N){
    __shared__ float As[32*132];
    __shared__ float Ws[32*132];
    const int tx = threadIdx.x & 15, ty = threadIdx.x >> 4;
    const int m0 = blockIdx.y << 7, n0 = blockIdx.x << 7;
    float acc[8][8];
    #pragma unroll
    for (int i=0;i<8;i++)
        #pragma unroll
        for (int j=0;j<8;j++) acc[i][j]=0.f;
    const int r = threadIdx.x >> 1;
    const int c4 = (threadIdx.x & 1) << 4;
    #pragma unroll
    for (int q=0;q<4;q++){
        float4 a0 = *(const float4*)(A + (size_t)(m0+r)*32 + c4 + q*4);
        As[(c4+q*4+0)*132 + r] = a0.x; As[(c4+q*4+1)*132 + r] = a0.y;
        As[(c4+q*4+2)*132 + r] = a0.z; As[(c4+q*4+3)*132 + r] = a0.w;
        float4 w0 = *(const float4*)(W + (size_t)(n0+r)*32 + c4 + q*4);
        Ws[(c4+q*4+0)*132 + r] = w0.x; Ws[(c4+q*4+1)*132 + r] = w0.y;
        Ws[(c4+q*4+2)*132 + r] = w0.z; Ws[(c4+q*4+3)*132 + r] = w0.w;
    }
    __syncthreads();
    #pragma unroll
    for (int kk=0; kk<32; kk++){
        float av[8], bv[8];
        *(float4*)&av[0] = *(const float4*)(As + kk*132 + (ty<<3));
        *(float4*)&av[4] = *(const float4*)(As + kk*132 + (ty<<3) + 4);
        *(float4*)&bv[0] = *(const float4*)(Ws + kk*132 + (tx<<3));
        *(float4*)&bv[4] = *(const float4*)(Ws + kk*132 + (tx<<3) + 4);
        #pragma unroll
        for (int i=0;i<8;i++)
            #pragma unroll
            for (int j=0;j<8;j++) acc[i][j] += av[i]*bv[j];
    }
    #pragma unroll
    for (int i=0;i<8;i++){
        int mg = m0 + (ty<<3) + i;
        #pragma unroll
        for (int j=0;j<8;j++)
            Cg[(size_t)mg*N + n0 + (tx<<3) + j] = acc[i][j];
    }
}

// ---------------- VE gate + V -> transposed fp16 ----------------
__global__ void vgate_kernel(const float* __restrict__ xn, const float* __restrict__ ve,
                             const float* __restrict__ wg, const float* __restrict__ qkv,
                             h16* __restrict__ vhi){
    int row = blockIdx.x;
    __shared__ float gs[4];
    if (threadIdx.x < 4){
        float s = 0.f;
        #pragma unroll
        for (int c=0;c<12;c++) s += xn[(size_t)row*Cv + c]*wg[threadIdx.x*12 + c];
        gs[threadIdx.x] = 3.f/(1.f + expf(-s));
    }
    __syncthreads();
    int i = threadIdx.x;
    int kv = i >> 6, d = i & 63;
    float vv = qkv[(size_t)row*1536 + 1280 + i] + gs[kv]*ve[(size_t)row*256 + i];
    size_t o = ((size_t)((row>>10)*4 + kv)*64 + d)*1024 + (row & 1023);
    vhi[o] = __float2half_rn(vv);
}

// ---------------- rope + per-head rmsnorm*1.2 -> fp16 ----------------
__global__ void ropeRms_kernel(const float* __restrict__ src, int srcStride, int srcOff,
                               h16* __restrict__ dhi,
                               const float* __restrict__ cosb, const float* __restrict__ sinb,
                               int nheads){
    int row  = blockIdx.x;
    int t    = row & (Tv-1);
    int head = blockIdx.y*4 + (threadIdx.x >> 5);
    if (head >= nheads) return;
    int lane = threadIdx.x & 31;
    const float* p = src + (size_t)row*srcStride + srcOff + head*HD;
    float x1 = p[lane], x2 = p[lane+32];
    float cc = cosb[t*32 + lane], sn = sinb[t*32 + lane];
    float o1 =  x1*cc + x2*sn;
    float o2 = -x1*sn + x2*cc;
    float ss = o1*o1 + o2*o2;
    for (int off=16; off>0; off>>=1) ss += __shfl_xor_sync(0xffffffffu, ss, off);
    float rr = rsqrtf(ss*(1.0f/HD) + 1e-6f)*1.2f;
    size_t base = ((size_t)row*nheads + head)*HD;
    dhi[base+lane]    = __float2half_rn(o1*rr);
    dhi[base+lane+32] = __float2half_rn(o2*rr);
}

// =================== flash attention: f16x2-exp softmax ===================
#define SM_Q    0
#define SM_KV0  8192
#define SM_KV1  24576
#define SM_PP0  40960
#define SM_PP1  58752
#define SM_S    76544
#define SM_PHI  95488
#define SM_CORR 103680
#define SM_LINV 103936
#define ATTN_SMEM 104192

__global__ void __launch_bounds__(256)
attn_kernel(const h16* __restrict__ qhi,
            const h16* __restrict__ khi, const h16* __restrict__ vhi,
            const float* __restrict__ prev, const float* __restrict__ rw,
            const float* __restrict__ alphap,
            h16* __restrict__ yh){
    extern __shared__ char smc[];
    uint32_t sb = smem_u32(smc);
    float* S      = (float*)(smc + SM_S);
    float* corr_s = (float*)(smc + SM_CORR);
    float* linv   = (float*)(smc + SM_LINV);

    const int tid = threadIdx.x, lane = tid & 31, wid = tid >> 5;
    const int warpM = wid & 3, warpN = wid >> 2;
    const int row = tid >> 2, quad = tid & 3, c0 = quad << 4;
    const int qt = (int)gridDim.x - 1 - (int)blockIdx.x;   // long CTAs first
    const int h = blockIdx.y, b = blockIdx.z;
    const int q0 = qt << 6;
    const int kvh = h >> 2;
    const int lr = lane & 15, lc = (lane < 16) ? 0 : 8;
    const int g = lane >> 2, t2 = (lane & 3) << 1;
    const float LOG2E = 1.4426950408889634f;

    const float alpha = alphap[0];
    float w9[9];
    #pragma unroll
    for (int i=0;i<9;i++) w9[i] = alpha*rw[h*9 + i];

    const float* prevB = prev + ((size_t)(b*NH + h))*Tv*Tv;

    auto issueKV = [&](int kt, int s){
        int k0 = kt << 6;
        uint32_t kvb = sb + SM_KV0 + s*16384;
        #pragma unroll
        for (int i=0;i<4;i++){
            int idx = tid + (i << 8);
            int arr = idx >> 9, rr = (idx >> 3) & 63, kc = idx & 7;
            const h16* src;
            if (arr == 0) src = khi + ((((size_t)(b*Tv + k0 + rr))*NKV + kvh) << 6) + (kc << 3);
            else          src = vhi + (((size_t)((b*NKV + kvh)*64 + rr)) << 10) + k0 + (kc << 3);
            cpa16(kvb + arr*8192 + sw128(rr, kc << 3), src);
        }
    };
    auto issuePP = [&](int kt, int s){
        int k0 = kt << 6;
        uint32_t ppb = sb + SM_PP0 + s*17792;
        for (int idx = tid; idx < 66*66; idx += 256){
            int i = idx/66, j = idx - i*66;
            int rr = q0 - 1 + i, cg = k0 - 1 + j;
            int ok = (rr >= 0 && rr < Tv && cg >= 0 && cg < Tv) ? 4 : 0;
            int rrc = rr < 0 ? 0 : (rr > 1023 ? 1023 : rr);
            int cgc = cg < 0 ? 0 : (cg > 1023 ? 1023 : cg);
            cpa4z(ppb + (uint32_t)(i*67 + j)*4, prevB + (size_t)rrc*Tv + cgc, ok);
        }
    };

    {
        #pragma unroll
        for (int i=0;i<2;i++){
            int idx = tid + (i << 8);
            int rr = idx >> 3, kc = idx & 7;
            const h16* src = qhi + ((((size_t)(b*Tv + q0 + rr))*NH + h) << 6) + (kc << 3);
            cpa16(sb + SM_Q + sw128(rr, kc << 3), src);
        }
        CPA_COMMIT();
        issueKV(0,0); issuePP(0,0);
        CPA_COMMIT();
    }

    float o[4][4];
    #pragma unroll
    for (int i=0;i<4;i++)
        #pragma unroll
        for (int j=0;j<4;j++) o[i][j]=0.f;
    float m = -1e30f, l = 0.f;

    for (int kt = 0; kt <= qt; kt++){
        int s = kt & 1;
        CPA_WAIT(0);
        __syncthreads();
        if (kt < qt){ issueKV(kt+1, s^1); issuePP(kt+1, s^1); CPA_COMMIT(); }
        uint32_t kvb = sb + SM_KV0 + s*16384;
        float* PP = (float*)(smc + SM_PP0 + s*17792);

        float c[4][4];
        #pragma unroll
        for (int i=0;i<4;i++)
            #pragma unroll
            for (int j=0;j<4;j++) c[i][j]=0.f;
        #pragma unroll
        for (int k16 = 0; k16 < 4; k16++){
            uint32_t qh_[4];
            ldsm4(qh_, sb + SM_Q + sw128(warpM*16 + lr, k16*16 + lc));
            #pragma unroll
            for (int nb=0; nb<2; nb++){
                uint32_t kh_[4];
                ldsm4(kh_, kvb + sw128(warpN*32 + nb*16 + lr, k16*16 + lc));
                mma16816(c[nb*2+0], qh_, kh_[0], kh_[2]);
                mma16816(c[nb*2+1], qh_, kh_[1], kh_[3]);
            }
        }
        #pragma unroll
        for (int ni=0; ni<4; ni++){
            int col = warpN*32 + ni*8 + t2;
            int r0 = warpM*16 + g;
            *(float2*)(S + r0*74 + col)     = make_float2(c[ni][0], c[ni][1]);
            *(float2*)(S + (r0+8)*74 + col) = make_float2(c[ni][2], c[ni][3]);
        }
        __syncthreads();

        float p[3][18];
        #pragma unroll
        for (int i=0;i<3;i++)
            #pragma unroll
            for (int e=0;e<18;e++) p[i][e] = PP[(row+i)*67 + c0 + e];
        float sr[16];
        #pragma unroll
        for (int j=0;j<16;j++){
            float cv = w9[0]*p[0][j] + w9[1]*p[0][j+1] + w9[2]*p[0][j+2]
                     + w9[3]*p[1][j] + w9[4]*p[1][j+1] + w9[5]*p[1][j+2]
                     + w9[6]*p[2][j] + w9[7]*p[2][j+1] + w9[8]*p[2][j+2];
            int col = c0 + j;
            sr[j] = S[row*74 + col]*0.125f + cv;
            if (kt == qt && col > row) sr[j] = -1e30f;
        }
        float mt = sr[0];
        #pragma unroll
        for (int j=1;j<16;j++) mt = fmaxf(mt, sr[j]);
        for (int off=1; off<4; off<<=1) mt = fmaxf(mt, __shfl_xor_sync(0xffffffffu, mt, off));
        float mnew = fmaxf(m, mt);
        float corrv = __expf(m - mnew);
        // f16x2 exp: one MUFU per 2 elements; writes P in packed fp16 directly
        float ls = 0.f;
        #pragma unroll
        for (int j=0;j<16;j+=2){
            uint32_t pe = ex2_f16x2((sr[j] - mnew)*LOG2E, (sr[j+1] - mnew)*LOG2E);
            *(uint32_t*)(smc + SM_PHI + sw128(row, c0 + j)) = pe;
            float2 fe = __half22float2(*(__half2*)&pe);
            ls += fe.x + fe.y;
        }
        for (int off=1; off<4; off<<=1) ls += __shfl_xor_sync(0xffffffffu, ls, off);
        l = l*corrv + ls;
        m = mnew;
        if (quad == 0) corr_s[row] = corrv;
        __syncthreads();

        float cr0 = corr_s[warpM*16 + g], cr1 = corr_s[warpM*16 + g + 8];
        #pragma unroll
        for (int ni=0; ni<4; ni++){
            o[ni][0] *= cr0; o[ni][1] *= cr0;
            o[ni][2] *= cr1; o[ni][3] *= cr1;
        }
        #pragma unroll
        for (int k16 = 0; k16 < 4; k16++){
            uint32_t ph_[4];
            ldsm4(ph_, sb + SM_PHI + sw128(warpM*16 + lr, k16*16 + lc));
            #pragma unroll
            for (int nb=0; nb<2; nb++){
                uint32_t vh_[4];
                ldsm4(vh_, kvb + 8192 + sw128(warpN*32 + nb*16 + lr, k16*16 + lc));
                mma16816(o[nb*2+0], ph_, vh_[0], vh_[2]);
                mma16816(o[nb*2+1], ph_, vh_[1], vh_[3]);
            }
        }
    }

    if (quad == 0) linv[row] = 1.f/l;
    __syncthreads();
    float i0 = linv[warpM*16 + g], i1 = linv[warpM*16 + g + 8];
    #pragma unroll
    for (int ni=0; ni<4; ni++){
        int col = warpN*32 + ni*8 + t2;
        size_t base0 = ((((size_t)(b*Tv + q0 + warpM*16 + g))*NH + h) << 6) + col;
        size_t base1 = ((((size_t)(b*Tv + q0 + warpM*16 + g + 8))*NH + h) << 6) + col;
        *(uint32_t*)(yh + base0) = pack2(__float2half_rn(o[ni][0]*i0), __float2half_rn(o[ni][1]*i0));
        *(uint32_t*)(yh + base1) = pack2(__float2half_rn(o[ni][2]*i1), __float2half_rn(o[ni][3]*i1));
    }
}

// ---------------- CA conv + gelu ----------------
__global__ void caconv_kernel(const float* __restrict__ hin, const float* __restrict__ cw,
                              float* __restrict__ hout){
    int ch = blockIdx.x, b = blockIdx.y;
    __shared__ float s[Tv+2];
    for (int t = threadIdx.x; t < Tv; t += 256) s[1+t] = hin[((size_t)b*Tv + t)*32 + ch];
    if (threadIdx.x == 0){ s[0] = 0.f; s[Tv+1] = 0.f; }
    __syncthreads();
    float w0 = cw[ch*3], w1 = cw[ch*3+1], w2 = cw[ch*3+2];
    for (int t = threadIdx.x; t < Tv; t += 256){
        float vv = s[1+t] + 0.1f*(w0*s[t] + w1*s[1+t] + w2*s[2+t]);
        hout[((size_t)b*Tv + t)*32 + ch] = 0.5f*vv*(1.f + erff(vv*0.70710678118f));
    }
}

// ---------------- FFN conv x4 ----------------
#define FFNC_SMEM (2*16*1026*4)
__global__ void __launch_bounds__(256)
ffnconvT_kernel(const h16* __restrict__ hf, const float* __restrict__ cw,
                h16* __restrict__ hs){
    extern __shared__ float fs[];
    float (*buf0)[1026] = (float(*)[1026])fs;
    float (*buf1)[1026] = (float(*)[1026])(fs + 16*1026);
    int f0 = blockIdx.x << 4, b = blockIdx.y;
    for (int idx4 = threadIdx.x; idx4 < 16*256; idx4 += 256){
        int cch = idx4 >> 8, t4 = (idx4 & 255) << 2;
        size_t o = ((size_t)(b*FFH + f0 + cch))*Tv + t4;
        uint2 u = *(const uint2*)(hf + o);
        const h16* ph = (const h16*)&u;
        #pragma unroll
        for (int e=0;e<4;e++) buf0[cch][1+t4+e] = __half2float(ph[e]);
    }
    if (threadIdx.x < 16){
        buf0[threadIdx.x][0] = 0.f; buf0[threadIdx.x][1025] = 0.f;
        buf1[threadIdx.x][0] = 0.f; buf1[threadIdx.x][1025] = 0.f;
    }
    int cch = threadIdx.x >> 4, j = threadIdx.x & 15;
    float w0 = cw[(f0+cch)*3], w1 = cw[(f0+cch)*3+1], w2 = cw[(f0+cch)*3+2];
    float (*cur)[1026] = buf0; float (*nxt)[1026] = buf1;
    #pragma unroll
    for (int it=0; it<4; it++){
        __syncthreads();
        #pragma unroll 4
        for (int t = j*64; t < j*64 + 64; t++)
            nxt[cch][1+t] = cur[cch][1+t] + 0.1f*(w0*cur[cch][t] + w1*cur[cch][1+t] + w2*cur[cch][2+t]);
        float (*tmp)[1026] = cur; cur = nxt; nxt = tmp;
    }
    __syncthreads();
    for (int t = threadIdx.x; t < Tv; t += 256){
        uint32_t wv[8];
        #pragma unroll
        for (int cc = 0; cc < 16; cc += 2)
            wv[cc>>1] = pack2(__float2half_rn(cur[cc][1+t]), __float2half_rn(cur[cc+1][1+t]));
        size_t o = ((size_t)(b*Tv + t))*FFH + f0;
        *(uint4*)(hs + o)     = make_uint4(wv[0],wv[1],wv[2],wv[3]);
        *(uint4*)(hs + o + 8) = make_uint4(wv[4],wv[5],wv[6],wv[7]);
    }
}

// ---------------- elementwise ----------------
__global__ void vit2_kernel(const float* __restrict__ h32, const float* __restrict__ w2,
                            float* __restrict__ out){
    int row  = blockIdx.x*8 + (threadIdx.x >> 5);
    int lane = threadIdx.x & 31;
    float vv = h32[(size_t)row*32 + lane]*w2[lane];
    for (int off=16; off>0; off>>=1) vv += __shfl_xor_sync(0xffffffffu, vv, off);
    if (lane == 0) out[row] = 1.f/(1.f + expf(-vv));
}
__global__ void vitsmooth_kernel(const float* __restrict__ vin, float* __restrict__ vout){
    int b = blockIdx.x;
    __shared__ float s[Tv+4];
    for (int t = threadIdx.x; t < Tv; t += 256) s[2+t] = vin[b*Tv + t];
    if (threadIdx.x < 2){ s[threadIdx.x] = 0.f; s[Tv+2+threadIdx.x] = 0.f; }
    __syncthreads();
    for (int t = threadIdx.x; t < Tv; t += 256){
        float vs = (s[t] + s[t+1] + s[t+2] + s[t+3] + s[t+4])*0.2f;
        float vv = 0.7f*s[2+t] + 0.3f*vs;
        vout[b*Tv + t] = (vv > 0.3f) ? vv : 0.1f*vv;
    }
}

// ---------------- launch ----------------
extern "C" void kernel_launch(void* const* d_in, const int* in_sizes, int n_in,
                              void* d_out, int out_size){
    const float* x     = (const float*)d_in[0];
    const float* ve    = (const float*)d_in[1];
    const float* cosp  = (const float*)d_in[2];
    const float* sinp  = (const float*)d_in[3];
    const float* prev  = (const float*)d_in[4];
    const float* w_q   = (const float*)d_in[5];
    const float* w_k   = (const float*)d_in[6];
    const float* w_v   = (const float*)d_in[7];
    const float* w_o   = (const float*)d_in[8];
    const float* w_veg = (const float*)d_in[9];
    const float* rfw   = (const float*)d_in[10];
    const float* ralpha= (const float*)d_in[11];
    const float* ca_pi = (const float*)d_in[12];
    const float* ca_cw = (const float*)d_in[13];
    const float* ca_po = (const float*)d_in[14];
    const float* ffn_in= (const float*)d_in[15];
    const float* ffn_cw= (const float*)d_in[16];
    const float* ffn_outw=(const float*)d_in[17];
    const float* ffn_gt= (const float*)d_in[18];
    const float* vit_w1= (const float*)d_in[19];
    const float* vit_w2= (const float*)d_in[20];
    float* out = (float*)d_out;

    float *xn,*qkv,*attn,*ca,*cah,*cah2,*x1,*mlp,*vit32,*vitv,*vitf;
    h16 *xnh,*xmh,*yh,*qh,*kh,*vh,*hf,*hs;
    h16 *wqkv,*wo,*fin,*fout,*fgt;
    cudaGetSymbolAddress((void**)&xn, g_xn);     cudaGetSymbolAddress((void**)&qkv, g_qkv);
    cudaGetSymbolAddress((void**)&attn, g_attn); cudaGetSymbolAddress((void**)&ca, g_ca);
    cudaGetSymbolAddress((void**)&cah, g_cah);   cudaGetSymbolAddress((void**)&cah2, g_cah2);
    cudaGetSymbolAddress((void**)&x1, g_x1);
    cudaGetSymbolAddress((void**)&mlp, g_mlp);
    cudaGetSymbolAddress((void**)&vit32, g_vit32); cudaGetSymbolAddress((void**)&vitv, g_vitv);
    cudaGetSymbolAddress((void**)&vitf, g_vitf);
    cudaGetSymbolAddress((void**)&xnh, g_xn_h);
    cudaGetSymbolAddress((void**)&xmh, g_xm_h);
    cudaGetSymbolAddress((void**)&yh, g_y_h);
    cudaGetSymbolAddress((void**)&qh, g_q_h);
    cudaGetSymbolAddress((void**)&kh, g_k_h);
    cudaGetSymbolAddress((void**)&vh, g_v_h);
    cudaGetSymbolAddress((void**)&hf, g_hf);     cudaGetSymbolAddress((void**)&hs, g_hs);
    cudaGetSymbolAddress((void**)&wqkv, g_wqkv);
    cudaGetSymbolAddress((void**)&wo, g_wo);
    cudaGetSymbolAddress((void**)&fin, g_fin);
    cudaGetSymbolAddress((void**)&fout, g_fout);
    cudaGetSymbolAddress((void**)&fgt, g_fgt);

    cudaFuncSetAttribute(attn_kernel, cudaFuncAttributeMaxDynamicSharedMemorySize, ATTN_SMEM);
    cudaFuncSetAttribute(gemm_f16<0>, cudaFuncAttributeMaxDynamicSharedMemorySize, GEMM_SMEM);
    cudaFuncSetAttribute(gemm_f16<1>, cudaFuncAttributeMaxDynamicSharedMemorySize, GEMM_SMEM);
    cudaFuncSetAttribute(gemm_f16<2>, cudaFuncAttributeMaxDynamicSharedMemorySize, GEMM_SMEM);
    cudaFuncSetAttribute(ffnconvT_kernel, cudaFuncAttributeMaxDynamicSharedMemorySize, FFNC_SMEM);

    cvt_kernel<<<256,256>>>(w_q, wqkv, 262144);
    cvt_kernel<<<64,256>>>(w_k, wqkv + 1024*1024, 65536);
    cvt_kernel<<<64,256>>>(w_v, wqkv + 1280*1024, 65536);
    rms_kernel<1><<<MT,256>>>(x, xn, xnh);
    cvt_kernel<<<256,256>>>(w_o, wo, 262144);
    gemm_f16<0><<<dim3(12,32),256,GEMM_SMEM>>>(xnh, wqkv, qkv, 0, 0,0,0,0, 0, 1536, 1024);

    vgate_kernel<<<MT,256>>>(xn, ve, w_veg, qkv, vh);
    ropeRms_kernel<<<dim3(MT,4),128>>>(qkv, 1536, 0,    qh, cosp, sinp, NH);
    ropeRms_kernel<<<dim3(MT,1),128>>>(qkv, 1536, 1024, kh, cosp, sinp, NKV);

    attn_kernel<<<dim3(16,NH,Bv),256,ATTN_SMEM>>>(qh, kh, vh, prev, rfw, ralpha, yh);
    gemm_f16<0><<<dim3(8,32),256,GEMM_SMEM>>>(yh, wo, attn, 0, 0,0,0,0, 0, 1024, 1024);

    cvt_kernel<<<1024,256>>>(ffn_in, fin, 1048576);
    cvt_kernel<<<1024,256>>>(ffn_outw, fout, 1048576);
    cvt_kernel<<<256,256>>>(ffn_gt, fgt, 262144);

    gemm32_kernel<0><<<512,256>>>(x, ca_pi, cah);
    caconv_kernel<<<dim3(32,Bv),256>>>(cah, ca_cw, cah2);
    gemm_k32<<<dim3(8,32),256>>>(cah2, ca_po, ca, 1024);
    x1rms_kernel<<<MT,256>>>(x, attn, ca, x1, xmh);

    gemm_f16<1><<<dim3(32,32),256,GEMM_SMEM>>>(xmh, fin, 0, hf, 0,0,0,0, 0, FFH, 1024);
    ffnconvT_kernel<<<dim3(256,Bv),256,FFNC_SMEM>>>(hf, ffn_cw, hs);
    gemm_f16<0><<<dim3(8,32),256,GEMM_SMEM>>>(hs, fout, mlp, 0, 0,0,0,0, 0, 1024, 4096);

    gemm32_kernel<0><<<512,256>>>(x1, ca_pi, cah);
    caconv_kernel<<<dim3(32,Bv),256>>>(cah, ca_cw, cah2);
    gemm_k32<<<dim3(8,32),256>>>(cah2, ca_po, ca, 1024);

    gemm32_kernel<2><<<512,256>>>(x1, vit_w1, vit32);
    vit2_kernel<<<512,256>>>(vit32, vit_w2, vitv);
    vitsmooth_kernel<<<Bv,256>>>(vitv, vitf);

    gemm_f16<2><<<dim3(8,32),256,GEMM_SMEM>>>(xmh, fgt, 0, 0, x1, mlp, ca, vitf, out, 1024, 1024);
}

// round 12
// speedup vs baseline: 1.6919x; 1.0242x over previous
#include <cuda_runtime.h>
#include <cuda_fp16.h>
#include <math.h>
#include <stdint.h>

#define Bv  4
#define Tv  1024
#define Cv  1024
#define NH  16
#define NKV 4
#define HD  64
#define FFH 4096
#define MT  (Bv*Tv)

typedef __half h16;

// ---------------- fp32 scratch ----------------
__device__ float g_xn  [MT*Cv];
__device__ float g_qkv [MT*1536];
__device__ float g_cah [MT*32];
__device__ float g_cah2[MT*32];
__device__ float g_x1  [MT*Cv];
__device__ float g_vit32[MT*32];
__device__ float g_vitf[MT];

// ---------------- fp16 scratch ----------------
__device__ h16 g_xn_h[MT*Cv];
__device__ h16 g_xm_h[MT*Cv];
__device__ h16 g_x1_h[MT*Cv];
__device__ h16 g_attn_h[MT*Cv];
__device__ h16 g_ca_h[MT*Cv];
__device__ h16 g_mlp_h[MT*Cv];
__device__ h16 g_y_h [MT*Cv];
__device__ h16 g_q_h [MT*1024];                  // (b,t,h,d)
__device__ h16 g_k_h [MT*256];                   // (b,t,kv,d)
__device__ h16 g_v_h [MT*256];                   // (b,kv,d,t)
__device__ h16 g_hf  [(size_t)MT*FFH];           // (b,f,t)
__device__ h16 g_hs  [(size_t)MT*FFH];           // (b,t,f)
__device__ h16 g_wqkv[1536*1024];
__device__ h16 g_wo  [1024*1024];
__device__ h16 g_fin [FFH*1024];
__device__ h16 g_fout[1024*FFH];
__device__ h16 g_fgt [1024*1024];

// =================== helpers ===================
__device__ __forceinline__ uint32_t smem_u32(const void* p){
    uint32_t a;
    asm("{ .reg .u64 t; cvta.to.shared.u64 t, %1; cvt.u32.u64 %0, t; }" : "=r"(a) : "l"(p));
    return a;
}
__device__ __forceinline__ void mma16816(float* c, const uint32_t* a, uint32_t b0, uint32_t b1){
    asm volatile("mma.sync.aligned.m16n8k16.row.col.f32.f16.f16.f32 "
        "{%0,%1,%2,%3}, {%4,%5,%6,%7}, {%8,%9}, {%0,%1,%2,%3};"
        : "+f"(c[0]), "+f"(c[1]), "+f"(c[2]), "+f"(c[3])
        : "r"(a[0]), "r"(a[1]), "r"(a[2]), "r"(a[3]), "r"(b0), "r"(b1));
}
__device__ __forceinline__ void ldsm4(uint32_t* r, uint32_t addr){
    asm volatile("ldmatrix.sync.aligned.m8n8.x4.shared.b16 {%0,%1,%2,%3}, [%4];"
        : "=r"(r[0]), "=r"(r[1]), "=r"(r[2]), "=r"(r[3]) : "r"(addr));
}
__device__ __forceinline__ void cpa16(uint32_t saddr, const void* g){
    asm volatile("cp.async.cg.shared.global [%0], [%1], 16;" :: "r"(saddr), "l"(g));
}
__device__ __forceinline__ void cpa4z(uint32_t saddr, const void* g, int srcsz){
    asm volatile("cp.async.ca.shared.global [%0], [%1], 4, %2;" :: "r"(saddr), "l"(g), "r"(srcsz));
}
#define CPA_COMMIT() asm volatile("cp.async.commit_group;" ::: "memory")
#define CPA_WAIT(n)  asm volatile("cp.async.wait_group %0;" :: "n"(n) : "memory")

__device__ __forceinline__ uint32_t sw_off(int row, int k){
    int chunk = (k >> 3) ^ ((row >> 1) & 3);
    return (uint32_t)(row*64 + chunk*16 + (k & 7)*2);
}
__device__ __forceinline__ uint32_t sw128(int row, int k){
    return (uint32_t)(row*128 + ((((k>>3) ^ (row & 7)) << 4) | ((k & 7) << 1)));
}
__device__ __forceinline__ uint32_t pack2(h16 a, h16 b){
    return ((uint32_t)__half_as_ushort(b) << 16) | __half_as_ushort(a);
}
__device__ __forceinline__ float tanh_fast(float x){
    float y; asm("tanh.approx.f32 %0, %1;" : "=f"(y) : "f"(x)); return y;
}
__device__ __forceinline__ uint32_t ex2_f16x2(float a, float b){
    __half2 hx = __floats2half2_rn(a, b);
    uint32_t r;
    asm("ex2.approx.f16x2 %0, %1;" : "=r"(r) : "r"(*(uint32_t*)&hx));
    return r;
}

// ---------------- fp32 -> fp16 convert ----------------
__global__ void cvt_kernel(const float* __restrict__ src, h16* __restrict__ dst, int n4){
    int i0 = blockIdx.x*1024 + threadIdx.x;
    #pragma unroll
    for (int j = 0; j < 4; j++){
        int i = i0 + (j << 8);
        if (i < n4){
            float4 v = ((const float4*)src)[i];
            ((uint2*)dst)[i] = make_uint2(
                pack2(__float2half_rn(v.x), __float2half_rn(v.y)),
                pack2(__float2half_rn(v.z), __float2half_rn(v.w)));
        }
    }
}

// fused QKV weight convert (wq 262144 f4, wk 65536, wv 65536 -> contiguous dst)
__global__ void cvt3_kernel(const float* __restrict__ s0, const float* __restrict__ s1,
                            const float* __restrict__ s2, h16* __restrict__ dst){
    int i0 = blockIdx.x*1024 + threadIdx.x;
    #pragma unroll
    for (int j = 0; j < 4; j++){
        int i = i0 + (j << 8);
        if (i < 393216){
            const float4* src = (i < 262144) ? ((const float4*)s0 + i)
                               : (i < 327680) ? ((const float4*)s1 + (i - 262144))
                               : ((const float4*)s2 + (i - 327680));
            float4 v = *src;
            ((uint2*)dst)[i] = make_uint2(
                pack2(__float2half_rn(v.x), __float2half_rn(v.y)),
                pack2(__float2half_rn(v.z), __float2half_rn(v.w)));
        }
    }
}

// ---------------- rmsnorm (fp32 + fp16) ----------------
template<int WF32>
__global__ void rms_kernel(const float* __restrict__ x, float* __restrict__ o32,
                           h16* __restrict__ ohi){
    int row = blockIdx.x;
    const float4* xr = (const float4*)(x + (size_t)row*Cv);
    float4 v = xr[threadIdx.x];
    float ss = v.x*v.x + v.y*v.y + v.z*v.z + v.w*v.w;
    __shared__ float red[8];
    for (int off=16; off>0; off>>=1) ss += __shfl_xor_sync(0xffffffffu, ss, off);
    if ((threadIdx.x & 31) == 0) red[threadIdx.x>>5] = ss;
    __syncthreads();
    if (threadIdx.x < 8){
        float t = red[threadIdx.x];
        for (int off=4; off>0; off>>=1) t += __shfl_xor_sync(0x000000ffu, t, off);
        if (threadIdx.x == 0) red[0] = t;
    }
    __syncthreads();
    float r = rsqrtf(red[0]*(1.0f/Cv) + 1e-6f);
    float4 o = make_float4(v.x*r, v.y*r, v.z*r, v.w*r);
    if (WF32) ((float4*)(o32 + (size_t)row*Cv))[threadIdx.x] = o;
    ((uint2*)(ohi + (size_t)row*Cv))[threadIdx.x] = make_uint2(
        pack2(__float2half_rn(o.x), __float2half_rn(o.y)),
        pack2(__float2half_rn(o.z), __float2half_rn(o.w)));
}

// ---------------- fused x1 + rmsnorm (fp16 attn/ca in; x1 fp32+fp16 out) ----------------
__global__ void x1rms_kernel(const float* __restrict__ x, const h16* __restrict__ attnh,
                             const h16* __restrict__ cah, float* __restrict__ x1,
                             h16* __restrict__ ox1h, h16* __restrict__ oxmh){
    int row = blockIdx.x;
    size_t base = (size_t)row*Cv;
    float4 xv = ((const float4*)(x + base))[threadIdx.x];
    uint2 ua = ((const uint2*)(attnh + base))[threadIdx.x];
    uint2 uc = ((const uint2*)(cah + base))[threadIdx.x];
    float2 a01 = __half22float2(*(__half2*)&ua.x), a23 = __half22float2(*(__half2*)&ua.y);
    float2 c01 = __half22float2(*(__half2*)&uc.x), c23 = __half22float2(*(__half2*)&uc.y);
    float4 v;
    v.x = xv.x + a01.x*(1.f + 0.1f*tanh_fast(c01.x));
    v.y = xv.y + a01.y*(1.f + 0.1f*tanh_fast(c01.y));
    v.z = xv.z + a23.x*(1.f + 0.1f*tanh_fast(c23.x));
    v.w = xv.w + a23.y*(1.f + 0.1f*tanh_fast(c23.y));
    float ss = v.x*v.x + v.y*v.y + v.z*v.z + v.w*v.w;
    __shared__ float red[8];
    for (int off=16; off>0; off>>=1) ss += __shfl_xor_sync(0xffffffffu, ss, off);
    if ((threadIdx.x & 31) == 0) red[threadIdx.x>>5] = ss;
    __syncthreads();
    if (threadIdx.x < 8){
        float t = red[threadIdx.x];
        for (int off=4; off>0; off>>=1) t += __shfl_xor_sync(0x000000ffu, t, off);
        if (threadIdx.x == 0) red[0] = t;
    }
    __syncthreads();
    float r = rsqrtf(red[0]*(1.0f/Cv) + 1e-6f);
    ((float4*)(x1 + base))[threadIdx.x] = v;
    ((uint2*)(ox1h + base))[threadIdx.x] = make_uint2(
        pack2(__float2half_rn(v.x), __float2half_rn(v.y)),
        pack2(__float2half_rn(v.z), __float2half_rn(v.w)));
    ((uint2*)(oxmh + base))[threadIdx.x] = make_uint2(
        pack2(__float2half_rn(v.x*r), __float2half_rn(v.y*r)),
        pack2(__float2half_rn(v.z*r), __float2half_rn(v.w*r)));
}

// =================== fp16 GEMM: tile 128x128, 256 thr, 2 CTA/SM, 4-stage ===================
// EPI 0: fp32 out. EPI 1: relu^2 -> fp16 (B,N,T). EPI 2: fused final. EPI 3: fp16 row-major out.
#define GSTG 16384
#define GEMM_SMEM (4*GSTG)
template<int EPI>
__global__ void __launch_bounds__(256,2)
gemm_f16(const h16* __restrict__ Ah, const h16* __restrict__ Bh,
         float* __restrict__ Cg, h16* __restrict__ Chf,
         const float* __restrict__ X1, const h16* __restrict__ MLPh,
         const h16* __restrict__ CAh, const float* __restrict__ VF,
         float* __restrict__ Og, int N, int K){
    extern __shared__ char smem[];
    const int tid = threadIdx.x, lane = tid & 31, wid = tid >> 5;
    const int warpM = wid & 3, warpN = wid >> 2;   // 4 x 2
    const int m0 = blockIdx.y << 7, n0 = blockIdx.x << 7;
    const int b = m0 >> 10, tb = m0 & 1023;
    uint32_t sb = smem_u32(smem);

    const int r = tid >> 2, kc = tid & 3;
    const h16* aP = Ah + (size_t)(m0+r)*K + (kc<<3);
    const h16* bP = Bh + (size_t)(n0+r)*K + (kc<<3);
    const uint32_t dA0 = sw_off(r, kc<<3);
    const uint32_t dA1 = sw_off(r+64, kc<<3);
    const size_t off64 = (size_t)64*K;

    auto ISSUE = [&](int c, int s){
        int k0 = c << 5;
        uint32_t st = sb + s*GSTG;
        cpa16(st + dA0,        aP + k0);
        cpa16(st + dA1,        aP + off64 + k0);
        cpa16(st + 8192 + dA0, bP + k0);
        cpa16(st + 8192 + dA1, bP + off64 + k0);
        CPA_COMMIT();
    };

    float acc[2][8][4];
    #pragma unroll
    for (int i=0;i<2;i++)
        #pragma unroll
        for (int j=0;j<8;j++)
            #pragma unroll
            for (int q=0;q<4;q++) acc[i][j][q]=0.f;

    const int NC = K >> 5;
    ISSUE(0,0); ISSUE(1,1); ISSUE(2,2);
    const int lr = lane & 15, lc = (lane < 16) ? 0 : 8;
    for (int c = 0; c < NC; c++){
        int rem = NC - 1 - c;
        if (rem >= 2) { CPA_WAIT(2); } else if (rem == 1) { CPA_WAIT(1); } else { CPA_WAIT(0); }
        __syncthreads();
        if (c + 3 < NC) ISSUE(c+3, (c+3)&3);
        uint32_t sA = sb + (c&3)*GSTG;
        #pragma unroll
        for (int kk = 0; kk < 32; kk += 16){
            uint32_t ah[2][4];
            #pragma unroll
            for (int mt=0; mt<2; mt++)
                ldsm4(ah[mt], sA + sw_off(warpM*32 + mt*16 + lr, kk + lc));
            #pragma unroll
            for (int nb=0; nb<4; nb++){
                uint32_t bh[4];
                ldsm4(bh, sA + 8192 + sw_off(warpN*64 + nb*16 + lr, kk + lc));
                #pragma unroll
                for (int mt=0; mt<2; mt++){
                    mma16816(acc[mt][nb*2+0], ah[mt], bh[0], bh[2]);
                    mma16816(acc[mt][nb*2+1], ah[mt], bh[1], bh[3]);
                }
            }
        }
    }

    const int g = lane >> 2, t2 = (lane & 3) << 1;
    if (EPI == 0){
        #pragma unroll
        for (int mt=0; mt<2; mt++){
            int m = m0 + warpM*32 + mt*16 + g;
            #pragma unroll
            for (int ni=0; ni<8; ni++){
                int n = n0 + warpN*64 + ni*8 + t2;
                *(float2*)(Cg + (size_t)m*N + n) = make_float2(acc[mt][ni][0], acc[mt][ni][1]);
                *(float2*)(Cg + (size_t)(m+8)*N + n) = make_float2(acc[mt][ni][2], acc[mt][ni][3]);
            }
        }
    } else if (EPI == 3){
        #pragma unroll
        for (int mt=0; mt<2; mt++){
            int m = m0 + warpM*32 + mt*16 + g;
            #pragma unroll
            for (int ni=0; ni<8; ni++){
                int n = n0 + warpN*64 + ni*8 + t2;
                *(uint32_t*)(Chf + (size_t)m*N + n) =
                    pack2(__float2half_rn(acc[mt][ni][0]), __float2half_rn(acc[mt][ni][1]));
                *(uint32_t*)(Chf + (size_t)(m+8)*N + n) =
                    pack2(__float2half_rn(acc[mt][ni][2]), __float2half_rn(acc[mt][ni][3]));
            }
        }
    } else if (EPI == 1){
        float* ep = (float*)smem;   // 64 x 136
        #pragma unroll
        for (int slab=0; slab<2; slab++){
            __syncthreads();
            if (warpN == slab){
                #pragma unroll
                for (int mt=0; mt<2; mt++){
                    int mloc = warpM*32 + mt*16 + g;
                    #pragma unroll
                    for (int ni=0; ni<8; ni++){
                        int nL = ni*8 + t2;
                        ep[nL*136 + mloc]         = acc[mt][ni][0];
                        ep[(nL+1)*136 + mloc]     = acc[mt][ni][1];
                        ep[nL*136 + mloc + 8]     = acc[mt][ni][2];
                        ep[(nL+1)*136 + mloc + 8] = acc[mt][ni][3];
                    }
                }
            }
            __syncthreads();
            #pragma unroll
            for (int i=0;i<8;i++){
                int idx = tid + (i << 8);
                int nr = idx >> 5, t4 = (idx & 31) << 2;
                float a0 = fmaxf(ep[nr*136 + t4 + 0], 0.f);
                float a1 = fmaxf(ep[nr*136 + t4 + 1], 0.f);
                float a2 = fmaxf(ep[nr*136 + t4 + 2], 0.f);
                float a3 = fmaxf(ep[nr*136 + t4 + 3], 0.f);
                int n = n0 + slab*64 + nr;
                size_t o = ((size_t)b*N + n)*1024 + tb + t4;
                *(uint2*)(Chf + o) = make_uint2(
                    pack2(__float2half_rn(a0*a0), __float2half_rn(a1*a1)),
                    pack2(__float2half_rn(a2*a2), __float2half_rn(a3*a3)));
            }
        }
    } else {
        // fused final: out = x1 + mlp*sigmoid(acc)*(1 + 0.1*tanh(ca))*vitf[row]
        #pragma unroll
        for (int mt=0; mt<2; mt++){
            int m = m0 + warpM*32 + mt*16 + g;
            float vf0 = VF[m], vf1 = VF[m+8];
            #pragma unroll
            for (int ni=0; ni<8; ni++){
                int n = n0 + warpN*64 + ni*8 + t2;
                size_t i0 = (size_t)m*1024 + n;
                size_t i1 = (size_t)(m+8)*1024 + n;
                float2 x0 = *(const float2*)(X1 + i0), x1v = *(const float2*)(X1 + i1);
                uint32_t um0 = *(const uint32_t*)(MLPh + i0), um1 = *(const uint32_t*)(MLPh + i1);
                uint32_t uc0 = *(const uint32_t*)(CAh + i0),  uc1 = *(const uint32_t*)(CAh + i1);
                float2 m0v = __half22float2(*(__half2*)&um0), m1v = __half22float2(*(__half2*)&um1);
                float2 c0v = __half22float2(*(__half2*)&uc0), c1v = __half22float2(*(__half2*)&uc1);
                float2 o0, o1;
                o0.x = x0.x + m0v.x*(0.5f + 0.5f*tanh_fast(0.5f*acc[mt][ni][0]))*(1.f + 0.1f*tanh_fast(c0v.x))*vf0;
                o0.y = x0.y + m0v.y*(0.5f + 0.5f*tanh_fast(0.5f*acc[mt][ni][1]))*(1.f + 0.1f*tanh_fast(c0v.y))*vf0;
                o1.x = x1v.x + m1v.x*(0.5f + 0.5f*tanh_fast(0.5f*acc[mt][ni][2]))*(1.f + 0.1f*tanh_fast(c1v.x))*vf1;
                o1.y = x1v.y + m1v.y*(0.5f + 0.5f*tanh_fast(0.5f*acc[mt][ni][3]))*(1.f + 0.1f*tanh_fast(c1v.y))*vf1;
                *(float2*)(Og + i0) = o0;
                *(float2*)(Og + i1) = o1;
            }
        }
    }
}

// ---------------- small-N (=32) GEMM, fp32 A ----------------
template<int EPI>
__global__ void __launch_bounds__(256)
gemm32_kernel(const float* __restrict__ A, const float* __restrict__ W, float* __restrict__ Cg){
    __shared__ float xs[8*1024];
    int row0 = blockIdx.x << 3;
    #pragma unroll
    for (int i = 0; i < 8; i++){
        int f4 = threadIdx.x + (i << 8);
        ((float4*)xs)[f4] = ((const float4*)(A + ((size_t)row0 << 10)))[f4];
    }
    __syncthreads();
    int w = threadIdx.x >> 5, n = threadIdx.x & 31;
    const float4* Wr = (const float4*)(W + (size_t)n*1024);
    const float4* xr = (const float4*)(xs + (w << 10));
    float acc = 0.f;
    #pragma unroll 4
    for (int k = 0; k < 256; k++){
        float4 a = xr[k], b = Wr[k];
        acc += a.x*b.x + a.y*b.y + a.z*b.z + a.w*b.w;
    }
    if (EPI == 2) acc = 0.5f*acc*(1.f + erff(acc*0.70710678118f));
    Cg[((size_t)(row0 + w) << 5) + n] = acc;
}

// ---------------- small-N (=32) GEMM, fp16 A ----------------
template<int EPI>
__global__ void __launch_bounds__(256)
gemm32h_kernel(const h16* __restrict__ A, const float* __restrict__ W, float* __restrict__ Cg){
    __shared__ float xs[8*1024];
    int row0 = blockIdx.x << 3;
    const uint32_t* ap = (const uint32_t*)(A + ((size_t)row0 << 10));
    #pragma unroll
    for (int i = 0; i < 16; i++){
        int k = threadIdx.x + (i << 8);
        uint32_t u = ap[k];
        float2 f = __half22float2(*(__half2*)&u);
        xs[2*k] = f.x; xs[2*k+1] = f.y;
    }
    __syncthreads();
    int w = threadIdx.x >> 5, n = threadIdx.x & 31;
    const float4* Wr = (const float4*)(W + (size_t)n*1024);
    const float4* xr = (const float4*)(xs + (w << 10));
    float acc = 0.f;
    #pragma unroll 4
    for (int k = 0; k < 256; k++){
        float4 a = xr[k], b = Wr[k];
        acc += a.x*b.x + a.y*b.y + a.z*b.z + a.w*b.w;
    }
    if (EPI == 2) acc = 0.5f*acc*(1.f + erff(acc*0.70710678118f));
    Cg[((size_t)(row0 + w) << 5) + n] = acc;
}

// ---------------- FFMA GEMM (ca_po, K=32) -> fp16 out ----------------
__global__ void __launch_bounds__(256,2)
gemm_k32(const float* __restrict__ A, const float* __restrict__ W,
         h16* __restrict__ Cgh, int N){
    __shared__ float As[32*132];
    __shared__ float Ws[32*132];
    const int tx = threadIdx.x & 15, ty = threadIdx.x >> 4;
    const int m0 = blockIdx.y << 7, n0 = blockIdx.x << 7;
    float acc[8][8];
    #pragma unroll
    for (int i=0;i<8;i++)
        #pragma unroll
        for (int j=0;j<8;j++) acc[i][j]=0.f;
    const int r = threadIdx.x >> 1;
    const int c4 = (threadIdx.x & 1) << 4;
    #pragma unroll
    for (int q=0;q<4;q++){
        float4 a0 = *(const float4*)(A + (size_t)(m0+r)*32 + c4 + q*4);
        As[(c4+q*4+0)*132 + r] = a0.x; As[(c4+q*4+1)*132 + r] = a0.y;
        As[(c4+q*4+2)*132 + r] = a0.z; As[(c4+q*4+3)*132 + r] = a0.w;
        float4 w0 = *(const float4*)(W + (size_t)(n0+r)*32 + c4 + q*4);
        Ws[(c4+q*4+0)*132 + r] = w0.x; Ws[(c4+q*4+1)*132 + r] = w0.y;
        Ws[(c4+q*4+2)*132 + r] = w0.z; Ws[(c4+q*4+3)*132 + r] = w0.w;
    }
    __syncthreads();
    #pragma unroll
    for (int kk=0; kk<32; kk++){
        float av[8], bv[8];
        *(float4*)&av[0] = *(const float4*)(As + kk*132 + (ty<<3));
        *(float4*)&av[4] = *(const float4*)(As + kk*132 + (ty<<3) + 4);
        *(float4*)&bv[0] = *(const float4*)(Ws + kk*132 + (tx<<3));
        *(float4*)&bv[4] = *(const float4*)(Ws + kk*132 + (tx<<3) + 4);
        #pragma unroll
        for (int i=0;i<8;i++)
            #pragma unroll
            for (int j=0;j<8;j++) acc[i][j] += av[i]*bv[j];
    }
    #pragma unroll
    for (int i=0;i<8;i++){
        int mg = m0 + (ty<<3) + i;
        uint4 wv;
        wv.x = pack2(__float2half_rn(acc[i][0]), __float2half_rn(acc[i][1]));
        wv.y = pack2(__float2half_rn(acc[i][2]), __float2half_rn(acc[i][3]));
        wv.z = pack2(__float2half_rn(acc[i][4]), __float2half_rn(acc[i][5]));
        wv.w = pack2(__float2half_rn(acc[i][6]), __float2half_rn(acc[i][7]));
        *(uint4*)(Cgh + (size_t)mg*N + n0 + (tx<<3)) = wv;
    }
}

// ---------------- VE gate + V -> transposed fp16 ----------------
__global__ void vgate_kernel(const float* __restrict__ xn, const float* __restrict__ ve,
                             const float* __restrict__ wg, const float* __restrict__ qkv,
                             h16* __restrict__ vhi){
    int row = blockIdx.x;
    __shared__ float gs[4];
    if (threadIdx.x < 4){
        float s = 0.f;
        #pragma unroll
        for (int c=0;c<12;c++) s += xn[(size_t)row*Cv + c]*wg[threadIdx.x*12 + c];
        gs[threadIdx.x] = 3.f/(1.f + expf(-s));
    }
    __syncthreads();
    int i = threadIdx.x;
    int kv = i >> 6, d = i & 63;
    float vv = qkv[(size_t)row*1536 + 1280 + i] + gs[kv]*ve[(size_t)row*256 + i];
    size_t o = ((size_t)((row>>10)*4 + kv)*64 + d)*1024 + (row & 1023);
    vhi[o] = __float2half_rn(vv);
}

// ---------------- rope + per-head rmsnorm*1.2 -> fp16 ----------------
__global__ void ropeRms_kernel(const float* __restrict__ src, int srcStride, int srcOff,
                               h16* __restrict__ dhi,
                               const float* __restrict__ cosb, const float* __restrict__ sinb,
                               int nheads){
    int row  = blockIdx.x;
    int t    = row & (Tv-1);
    int head = blockIdx.y*4 + (threadIdx.x >> 5);
    if (head >= nheads) return;
    int lane = threadIdx.x & 31;
    const float* p = src + (size_t)row*srcStride + srcOff + head*HD;
    float x1 = p[lane], x2 = p[lane+32];
    float cc = cosb[t*32 + lane], sn = sinb[t*32 + lane];
    float o1 =  x1*cc + x2*sn;
    float o2 = -x1*sn + x2*cc;
    float ss = o1*o1 + o2*o2;
    for (int off=16; off>0; off>>=1) ss += __shfl_xor_sync(0xffffffffu, ss, off);
    float rr = rsqrtf(ss*(1.0f/HD) + 1e-6f)*1.2f;
    size_t base = ((size_t)row*nheads + head)*HD;
    dhi[base+lane]    = __float2half_rn(o1*rr);
    dhi[base+lane+32] = __float2half_rn(o2*rr);
}

// =================== flash attention: f16x2-exp softmax ===================
#define SM_Q    0
#define SM_KV0  8192
#define SM_KV1  24576
#define SM_PP0  40960
#define SM_PP1  58752
#define SM_S    76544
#define SM_PHI  95488
#define SM_CORR 103680
#define SM_LINV 103936
#define ATTN_SMEM 104192

__global__ void __launch_bounds__(256)
attn_kernel(const h16* __restrict__ qhi,
            const h16* __restrict__ khi, const h16* __restrict__ vhi,
            const float* __restrict__ prev, const float* __restrict__ rw,
            const float* __restrict__ alphap,
            h16* __restrict__ yh){
    extern __shared__ char smc[];
    uint32_t sb = smem_u32(smc);
    float* S      = (float*)(smc + SM_S);
    float* corr_s = (float*)(smc + SM_CORR);
    float* linv   = (float*)(smc + SM_LINV);

    const int tid = threadIdx.x, lane = tid & 31, wid = tid >> 5;
    const int warpM = wid & 3, warpN = wid >> 2;
    const int row = tid >> 2, quad = tid & 3, c0 = quad << 4;
    const int qt = (int)gridDim.x - 1 - (int)blockIdx.x;
    const int h = blockIdx.y, b = blockIdx.z;
    const int q0 = qt << 6;
    const int kvh = h >> 2;
    const int lr = lane & 15, lc = (lane < 16) ? 0 : 8;
    const int g = lane >> 2, t2 = (lane & 3) << 1;
    const float LOG2E = 1.4426950408889634f;

    const float alpha = alphap[0];
    float w9[9];
    #pragma unroll
    for (int i=0;i<9;i++) w9[i] = alpha*rw[h*9 + i];

    const float* prevB = prev + ((size_t)(b*NH + h))*Tv*Tv;

    auto issueKV = [&](int kt, int s){
        int k0 = kt << 6;
        uint32_t kvb = sb + SM_KV0 + s*16384;
        #pragma unroll
        for (int i=0;i<4;i++){
            int idx = tid + (i << 8);
            int arr = idx >> 9, rr = (idx >> 3) & 63, kc = idx & 7;
            const h16* src;
            if (arr == 0) src = khi + ((((size_t)(b*Tv + k0 + rr))*NKV + kvh) << 6) + (kc << 3);
            else          src = vhi + (((size_t)((b*NKV + kvh)*64 + rr)) << 10) + k0 + (kc << 3);
            cpa16(kvb + arr*8192 + sw128(rr, kc << 3), src);
        }
    };
    auto issuePP = [&](int kt, int s){
        int k0 = kt << 6;
        uint32_t ppb = sb + SM_PP0 + s*17792;
        for (int idx = tid; idx < 66*66; idx += 256){
            int i = idx/66, j = idx - i*66;
            int rr = q0 - 1 + i, cg = k0 - 1 + j;
            int ok = (rr >= 0 && rr < Tv && cg >= 0 && cg < Tv) ? 4 : 0;
            int rrc = rr < 0 ? 0 : (rr > 1023 ? 1023 : rr);
            int cgc = cg < 0 ? 0 : (cg > 1023 ? 1023 : cg);
            cpa4z(ppb + (uint32_t)(i*67 + j)*4, prevB + (size_t)rrc*Tv + cgc, ok);
        }
    };

    {
        #pragma unroll
        for (int i=0;i<2;i++){
            int idx = tid + (i << 8);
            int rr = idx >> 3, kc = idx & 7;
            const h16* src = qhi + ((((size_t)(b*Tv + q0 + rr))*NH + h) << 6) + (kc << 3);
            cpa16(sb + SM_Q + sw128(rr, kc << 3), src);
        }
        CPA_COMMIT();
        issueKV(0,0); issuePP(0,0);
        CPA_COMMIT();
    }

    float o[4][4];
    #pragma unroll
    for (int i=0;i<4;i++)
        #pragma unroll
        for (int j=0;j<4;j++) o[i][j]=0.f;
    float m = -1e30f, l = 0.f;

    for (int kt = 0; kt <= qt; kt++){
        int s = kt & 1;
        CPA_WAIT(0);
        __syncthreads();
        if (kt < qt){ issueKV(kt+1, s^1); issuePP(kt+1, s^1); CPA_COMMIT(); }
        uint32_t kvb = sb + SM_KV0 + s*16384;
        float* PP = (float*)(smc + SM_PP0 + s*17792);

        float c[4][4];
        #pragma unroll
        for (int i=0;i<4;i++)
            #pragma unroll
            for (int j=0;j<4;j++) c[i][j]=0.f;
        #pragma unroll
        for (int k16 = 0; k16 < 4; k16++){
            uint32_t qh_[4];
            ldsm4(qh_, sb + SM_Q + sw128(warpM*16 + lr, k16*16 + lc));
            #pragma unroll
            for (int nb=0; nb<2; nb++){
                uint32_t kh_[4];
                ldsm4(kh_, kvb + sw128(warpN*32 + nb*16 + lr, k16*16 + lc));
                mma16816(c[nb*2+0], qh_, kh_[0], kh_[2]);
                mma16816(c[nb*2+1], qh_, kh_[1], kh_[3]);
            }
        }
        #pragma unroll
        for (int ni=0; ni<4; ni++){
            int col = warpN*32 + ni*8 + t2;
            int r0 = warpM*16 + g;
            *(float2*)(S + r0*74 + col)     = make_float2(c[ni][0], c[ni][1]);
            *(float2*)(S + (r0+8)*74 + col) = make_float2(c[ni][2], c[ni][3]);
        }
        __syncthreads();

        float p[3][18];
        #pragma unroll
        for (int i=0;i<3;i++)
            #pragma unroll
            for (int e=0;e<18;e++) p[i][e] = PP[(row+i)*67 + c0 + e];
        float sr[16];
        #pragma unroll
        for (int j=0;j<16;j++){
            float cv = w9[0]*p[0][j] + w9[1]*p[0][j+1] + w9[2]*p[0][j+2]
                     + w9[3]*p[1][j] + w9[4]*p[1][j+1] + w9[5]*p[1][j+2]
                     + w9[6]*p[2][j] + w9[7]*p[2][j+1] + w9[8]*p[2][j+2];
            int col = c0 + j;
            sr[j] = S[row*74 + col]*0.125f + cv;
            if (kt == qt && col > row) sr[j] = -1e30f;
        }
        float mt = sr[0];
        #pragma unroll
        for (int j=1;j<16;j++) mt = fmaxf(mt, sr[j]);
        for (int off=1; off<4; off<<=1) mt = fmaxf(mt, __shfl_xor_sync(0xffffffffu, mt, off));
        float mnew = fmaxf(m, mt);
        float corrv = __expf(m - mnew);
        float ls = 0.f;
        #pragma unroll
        for (int j=0;j<16;j+=2){
            uint32_t pe = ex2_f16x2((sr[j] - mnew)*LOG2E, (sr[j+1] - mnew)*LOG2E);
            *(uint32_t*)(smc + SM_PHI + sw128(row, c0 + j)) = pe;
            float2 fe = __half22float2(*(__half2*)&pe);
            ls += fe.x + fe.y;
        }
        for (int off=1; off<4; off<<=1) ls += __shfl_xor_sync(0xffffffffu, ls, off);
        l = l*corrv + ls;
        m = mnew;
        if (quad == 0) corr_s[row] = corrv;
        __syncthreads();

        float cr0 = corr_s[warpM*16 + g], cr1 = corr_s[warpM*16 + g + 8];
        #pragma unroll
        for (int ni=0; ni<4; ni++){
            o[ni][0] *= cr0; o[ni][1] *= cr0;
            o[ni][2] *= cr1; o[ni][3] *= cr1;
        }
        #pragma unroll
        for (int k16 = 0; k16 < 4; k16++){
            uint32_t ph_[4];
            ldsm4(ph_, sb + SM_PHI + sw128(warpM*16 + lr, k16*16 + lc));
            #pragma unroll
            for (int nb=0; nb<2; nb++){
                uint32_t vh_[4];
                ldsm4(vh_, kvb + 8192 + sw128(warpN*32 + nb*16 + lr, k16*16 + lc));
                mma16816(o[nb*2+0], ph_, vh_[0], vh_[2]);
                mma16816(o[nb*2+1], ph_, vh_[1], vh_[3]);
            }
        }
    }

    if (quad == 0) linv[row] = 1.f/l;
    __syncthreads();
    float i0 = linv[warpM*16 + g], i1 = linv[warpM*16 + g + 8];
    #pragma unroll
    for (int ni=0; ni<4; ni++){
        int col = warpN*32 + ni*8 + t2;
        size_t base0 = ((((size_t)(b*Tv + q0 + warpM*16 + g))*NH + h) << 6) + col;
        size_t base1 = ((((size_t)(b*Tv + q0 + warpM*16 + g + 8))*NH + h) << 6) + col;
        *(uint32_t*)(yh + base0) = pack2(__float2half_rn(o[ni][0]*i0), __float2half_rn(o[ni][1]*i0));
        *(uint32_t*)(yh + base1) = pack2(__float2half_rn(o[ni][2]*i1), __float2half_rn(o[ni][3]*i1));
    }
}

// ---------------- CA conv + gelu ----------------
__global__ void caconv_kernel(const float* __restrict__ hin, const float* __restrict__ cw,
                              float* __restrict__ hout){
    int ch = blockIdx.x, b = blockIdx.y;
    __shared__ float s[Tv+2];
    for (int t = threadIdx.x; t < Tv; t += 256) s[1+t] = hin[((size_t)b*Tv + t)*32 + ch];
    if (threadIdx.x == 0){ s[0] = 0.f; s[Tv+1] = 0.f; }
    __syncthreads();
    float w0 = cw[ch*3], w1 = cw[ch*3+1], w2 = cw[ch*3+2];
    for (int t = threadIdx.x; t < Tv; t += 256){
        float vv = s[1+t] + 0.1f*(w0*s[t] + w1*s[1+t] + w2*s[2+t]);
        hout[((size_t)b*Tv + t)*32 + ch] = 0.5f*vv*(1.f + erff(vv*0.70710678118f));
    }
}

// ---------------- FFN conv x4 ----------------
#define FFNC_SMEM (2*16*1026*4)
__global__ void __launch_bounds__(256)
ffnconvT_kernel(const h16* __restrict__ hf, const float* __restrict__ cw,
                h16* __restrict__ hs){
    extern __shared__ float fs[];
    float (*buf0)[1026] = (float(*)[1026])fs;
    float (*buf1)[1026] = (float(*)[1026])(fs + 16*1026);
    int f0 = blockIdx.x << 4, b = blockIdx.y;
    for (int idx4 = threadIdx.x; idx4 < 16*256; idx4 += 256){
        int cch = idx4 >> 8, t4 = (idx4 & 255) << 2;
        size_t o = ((size_t)(b*FFH + f0 + cch))*Tv + t4;
        uint2 u = *(const uint2*)(hf + o);
        const h16* ph = (const h16*)&u;
        #pragma unroll
        for (int e=0;e<4;e++) buf0[cch][1+t4+e] = __half2float(ph[e]);
    }
    if (threadIdx.x < 16){
        buf0[threadIdx.x][0] = 0.f; buf0[threadIdx.x][1025] = 0.f;
        buf1[threadIdx.x][0] = 0.f; buf1[threadIdx.x][1025] = 0.f;
    }
    int cch = threadIdx.x >> 4, j = threadIdx.x & 15;
    float w0 = cw[(f0+cch)*3], w1 = cw[(f0+cch)*3+1], w2 = cw[(f0+cch)*3+2];
    float (*cur)[1026] = buf0; float (*nxt)[1026] = buf1;
    #pragma unroll
    for (int it=0; it<4; it++){
        __syncthreads();
        #pragma unroll 4
        for (int t = j*64; t < j*64 + 64; t++)
            nxt[cch][1+t] = cur[cch][1+t] + 0.1f*(w0*cur[cch][t] + w1*cur[cch][1+t] + w2*cur[cch][2+t]);
        float (*tmp)[1026] = cur; cur = nxt; nxt = tmp;
    }
    __syncthreads();
    for (int t = threadIdx.x; t < Tv; t += 256){
        uint32_t wv[8];
        #pragma unroll
        for (int cc = 0; cc < 16; cc += 2)
            wv[cc>>1] = pack2(__float2half_rn(cur[cc][1+t]), __float2half_rn(cur[cc+1][1+t]));
        size_t o = ((size_t)(b*Tv + t))*FFH + f0;
        *(uint4*)(hs + o)     = make_uint4(wv[0],wv[1],wv[2],wv[3]);
        *(uint4*)(hs + o + 8) = make_uint4(wv[4],wv[5],wv[6],wv[7]);
    }
}

// ---------------- fused vit2 + vitsmooth ----------------
__global__ void vitfuse_kernel(const float* __restrict__ h32, const float* __restrict__ w2,
                               float* __restrict__ vitf){
    int b = blockIdx.x;
    __shared__ float s[Tv+4];
    __shared__ float w2s[32];
    if (threadIdx.x < 32) w2s[threadIdx.x] = w2[threadIdx.x];
    if (threadIdx.x < 2){ s[threadIdx.x] = 0.f; s[Tv+2+threadIdx.x] = 0.f; }
    __syncthreads();
    for (int t = threadIdx.x; t < Tv; t += 256){
        const float4* hr = (const float4*)(h32 + ((size_t)(b*Tv + t) << 5));
        float acc = 0.f;
        #pragma unroll
        for (int c = 0; c < 8; c++){
            float4 hv = hr[c];
            acc += hv.x*w2s[c*4] + hv.y*w2s[c*4+1] + hv.z*w2s[c*4+2] + hv.w*w2s[c*4+3];
        }
        s[2+t] = 1.f/(1.f + expf(-acc));
    }
    __syncthreads();
    for (int t = threadIdx.x; t < Tv; t += 256){
        float vs = (s[t] + s[t+1] + s[t+2] + s[t+3] + s[t+4])*0.2f;
        float vv = 0.7f*s[2+t] + 0.3f*vs;
        vitf[b*Tv + t] = (vv > 0.3f) ? vv : 0.1f*vv;
    }
}

// ---------------- launch ----------------
extern "C" void kernel_launch(void* const* d_in, const int* in_sizes, int n_in,
                              void* d_out, int out_size){
    const float* x     = (const float*)d_in[0];
    const float* ve    = (const float*)d_in[1];
    const float* cosp  = (const float*)d_in[2];
    const float* sinp  = (const float*)d_in[3];
    const float* prev  = (const float*)d_in[4];
    const float* w_q   = (const float*)d_in[5];
    const float* w_k   = (const float*)d_in[6];
    const float* w_v   = (const float*)d_in[7];
    const float* w_o   = (const float*)d_in[8];
    const float* w_veg = (const float*)d_in[9];
    const float* rfw   = (const float*)d_in[10];
    const float* ralpha= (const float*)d_in[11];
    const float* ca_pi = (const float*)d_in[12];
    const float* ca_cw = (const float*)d_in[13];
    const float* ca_po = (const float*)d_in[14];
    const float* ffn_in= (const float*)d_in[15];
    const float* ffn_cw= (const float*)d_in[16];
    const float* ffn_outw=(const float*)d_in[17];
    const float* ffn_gt= (const float*)d_in[18];
    const float* vit_w1= (const float*)d_in[19];
    const float* vit_w2= (const float*)d_in[20];
    float* out = (float*)d_out;

    float *xn,*qkv,*cah,*cah2,*x1,*vit32,*vitf;
    h16 *xnh,*xmh,*x1h,*attnh,*cah16,*mlph,*yh,*qh,*kh,*vh,*hf,*hs;
    h16 *wqkv,*wo,*fin,*fout,*fgt;
    cudaGetSymbolAddress((void**)&xn, g_xn);     cudaGetSymbolAddress((void**)&qkv, g_qkv);
    cudaGetSymbolAddress((void**)&cah, g_cah);   cudaGetSymbolAddress((void**)&cah2, g_cah2);
    cudaGetSymbolAddress((void**)&x1, g_x1);
    cudaGetSymbolAddress((void**)&vit32, g_vit32);
    cudaGetSymbolAddress((void**)&vitf, g_vitf);
    cudaGetSymbolAddress((void**)&xnh, g_xn_h);
    cudaGetSymbolAddress((void**)&xmh, g_xm_h);
    cudaGetSymbolAddress((void**)&x1h, g_x1_h);
    cudaGetSymbolAddress((void**)&attnh, g_attn_h);
    cudaGetSymbolAddress((void**)&cah16, g_ca_h);
    cudaGetSymbolAddress((void**)&mlph, g_mlp_h);
    cudaGetSymbolAddress((void**)&yh, g_y_h);
    cudaGetSymbolAddress((void**)&qh, g_q_h);
    cudaGetSymbolAddress((void**)&kh, g_k_h);
    cudaGetSymbolAddress((void**)&vh, g_v_h);
    cudaGetSymbolAddress((void**)&hf, g_hf);     cudaGetSymbolAddress((void**)&hs, g_hs);
    cudaGetSymbolAddress((void**)&wqkv, g_wqkv);
    cudaGetSymbolAddress((void**)&wo, g_wo);
    cudaGetSymbolAddress((void**)&fin, g_fin);
    cudaGetSymbolAddress((void**)&fout, g_fout);
    cudaGetSymbolAddress((void**)&fgt, g_fgt);

    cudaFuncSetAttribute(attn_kernel, cudaFuncAttributeMaxDynamicSharedMemorySize, ATTN_SMEM);
    cudaFuncSetAttribute(gemm_f16<0>, cudaFuncAttributeMaxDynamicSharedMemorySize, GEMM_SMEM);
    cudaFuncSetAttribute(gemm_f16<1>, cudaFuncAttributeMaxDynamicSharedMemorySize, GEMM_SMEM);
    cudaFuncSetAttribute(gemm_f16<2>, cudaFuncAttributeMaxDynamicSharedMemorySize, GEMM_SMEM);
    cudaFuncSetAttribute(gemm_f16<3>, cudaFuncAttributeMaxDynamicSharedMemorySize, GEMM_SMEM);
    cudaFuncSetAttribute(ffnconvT_kernel, cudaFuncAttributeMaxDynamicSharedMemorySize, FFNC_SMEM);

    // positions 0-3: rms, cvt3, cvt, gemmQKV (ncu -s 5 lands on position 3)
    rms_kernel<1><<<MT,256>>>(x, xn, xnh);
    cvt3_kernel<<<384,256>>>(w_q, w_k, w_v, wqkv);
    cvt_kernel<<<256,256>>>(w_o, wo, 262144);
    gemm_f16<0><<<dim3(12,32),256,GEMM_SMEM>>>(xnh, wqkv, qkv, 0, 0,0,0,0, 0, 1536, 1024);

    vgate_kernel<<<MT,256>>>(xn, ve, w_veg, qkv, vh);
    ropeRms_kernel<<<dim3(MT,4),128>>>(qkv, 1536, 0,    qh, cosp, sinp, NH);
    ropeRms_kernel<<<dim3(MT,1),128>>>(qkv, 1536, 1024, kh, cosp, sinp, NKV);

    attn_kernel<<<dim3(16,NH,Bv),256,ATTN_SMEM>>>(qh, kh, vh, prev, rfw, ralpha, yh);
    gemm_f16<3><<<dim3(8,32),256,GEMM_SMEM>>>(yh, wo, 0, attnh, 0,0,0,0, 0, 1024, 1024);

    cvt_kernel<<<1024,256>>>(ffn_in, fin, 1048576);
    cvt_kernel<<<1024,256>>>(ffn_outw, fout, 1048576);
    cvt_kernel<<<256,256>>>(ffn_gt, fgt, 262144);

    // ca1 on x
    gemm32_kernel<0><<<512,256>>>(x, ca_pi, cah);
    caconv_kernel<<<dim3(32,Bv),256>>>(cah, ca_cw, cah2);
    gemm_k32<<<dim3(8,32),256>>>(cah2, ca_po, cah16, 1024);
    x1rms_kernel<<<MT,256>>>(x, attnh, cah16, x1, x1h, xmh);

    // FFN
    gemm_f16<1><<<dim3(32,32),256,GEMM_SMEM>>>(xmh, fin, 0, hf, 0,0,0,0, 0, FFH, 1024);
    ffnconvT_kernel<<<dim3(256,Bv),256,FFNC_SMEM>>>(hf, ffn_cw, hs);
    gemm_f16<3><<<dim3(8,32),256,GEMM_SMEM>>>(hs, fout, 0, mlph, 0,0,0,0, 0, 1024, 4096);

    // ca2 on x1 (fp16 A)
    gemm32h_kernel<0><<<512,256>>>(x1h, ca_pi, cah);
    caconv_kernel<<<dim3(32,Bv),256>>>(cah, ca_cw, cah2);
    gemm_k32<<<dim3(8,32),256>>>(cah2, ca_po, cah16, 1024);

    // vit gate (fp16 A + fused smooth)
    gemm32h_kernel<2><<<512,256>>>(x1h, vit_w1, vit32);
    vitfuse_kernel<<<Bv,256>>>(vit32, vit_w2, vitf);

    // gate GEMM with fused final epilogue -> out
    gemm_f16<2><<<dim3(8,32),256,GEMM_SMEM>>>(xmh, fgt, 0, 0, x1, mlph, cah16, vitf, out, 1024, 1024);
}

// round 13
// speedup vs baseline: 1.6999x; 1.0047x over previous
#include <cuda_runtime.h>
#include <cuda_fp16.h>
#include <math.h>
#include <stdint.h>

#define Bv  4
#define Tv  1024
#define Cv  1024
#define NH  16
#define NKV 4
#define HD  64
#define FFH 4096
#define MT  (Bv*Tv)

typedef __half h16;

// ---------------- fp32 scratch ----------------
__device__ float g_xn  [MT*Cv];
__device__ float g_qkv [MT*1536];
__device__ float g_cah [MT*32];
__device__ float g_cah2[MT*32];
__device__ float g_x1  [MT*Cv];
__device__ float g_vit32[MT*32];
__device__ float g_vitf[MT];

// ---------------- fp16 scratch ----------------
__device__ h16 g_xn_h[MT*Cv];
__device__ h16 g_xm_h[MT*Cv];
__device__ h16 g_x1_h[MT*Cv];
__device__ h16 g_attn_h[MT*Cv];
__device__ h16 g_ca_h[MT*Cv];
__device__ h16 g_mlp_h[MT*Cv];
__device__ h16 g_y_h [MT*Cv];
__device__ h16 g_q_h [MT*1024];
__device__ h16 g_k_h [MT*256];
__device__ h16 g_v_h [MT*256];
__device__ h16 g_hf  [(size_t)MT*FFH];
__device__ h16 g_hs  [(size_t)MT*FFH];
__device__ h16 g_wqkv[1536*1024];
__device__ h16 g_wo  [1024*1024];
__device__ h16 g_fin [FFH*1024];
__device__ h16 g_fout[1024*FFH];
__device__ h16 g_fgt [1024*1024];

// =================== helpers ===================
__device__ __forceinline__ uint32_t smem_u32(const void* p){
    uint32_t a;
    asm("{ .reg .u64 t; cvta.to.shared.u64 t, %1; cvt.u32.u64 %0, t; }" : "=r"(a) : "l"(p));
    return a;
}
__device__ __forceinline__ void mma16816(float* c, const uint32_t* a, uint32_t b0, uint32_t b1){
    asm volatile("mma.sync.aligned.m16n8k16.row.col.f32.f16.f16.f32 "
        "{%0,%1,%2,%3}, {%4,%5,%6,%7}, {%8,%9}, {%0,%1,%2,%3};"
        : "+f"(c[0]), "+f"(c[1]), "+f"(c[2]), "+f"(c[3])
        : "r"(a[0]), "r"(a[1]), "r"(a[2]), "r"(a[3]), "r"(b0), "r"(b1));
}
__device__ __forceinline__ void ldsm4(uint32_t* r, uint32_t addr){
    asm volatile("ldmatrix.sync.aligned.m8n8.x4.shared.b16 {%0,%1,%2,%3}, [%4];"
        : "=r"(r[0]), "=r"(r[1]), "=r"(r[2]), "=r"(r[3]) : "r"(addr));
}
__device__ __forceinline__ void cpa16(uint32_t saddr, const void* g){
    asm volatile("cp.async.cg.shared.global [%0], [%1], 16;" :: "r"(saddr), "l"(g));
}
__device__ __forceinline__ void cpa4z(uint32_t saddr, const void* g, int srcsz){
    asm volatile("cp.async.ca.shared.global [%0], [%1], 4, %2;" :: "r"(saddr), "l"(g), "r"(srcsz));
}
#define CPA_COMMIT() asm volatile("cp.async.commit_group;" ::: "memory")
#define CPA_WAIT(n)  asm volatile("cp.async.wait_group %0;" :: "n"(n) : "memory")

__device__ __forceinline__ uint32_t sw_off(int row, int k){
    int chunk = (k >> 3) ^ ((row >> 1) & 3);
    return (uint32_t)(row*64 + chunk*16 + (k & 7)*2);
}
__device__ __forceinline__ uint32_t sw128(int row, int k){
    return (uint32_t)(row*128 + ((((k>>3) ^ (row & 7)) << 4) | ((k & 7) << 1)));
}
__device__ __forceinline__ uint32_t pack2(h16 a, h16 b){
    return ((uint32_t)__half_as_ushort(b) << 16) | __half_as_ushort(a);
}
__device__ __forceinline__ float tanh_fast(float x){
    float y; asm("tanh.approx.f32 %0, %1;" : "=f"(y) : "f"(x)); return y;
}
__device__ __forceinline__ uint32_t ex2_f16x2(float a, float b){
    __half2 hx = __floats2half2_rn(a, b);
    uint32_t r;
    asm("ex2.approx.f16x2 %0, %1;" : "=r"(r) : "r"(*(uint32_t*)&hx));
    return r;
}

// ---------------- fp32 -> fp16 convert ----------------
__global__ void cvt_kernel(const float* __restrict__ src, h16* __restrict__ dst, int n4){
    int i0 = blockIdx.x*1024 + threadIdx.x;
    #pragma unroll
    for (int j = 0; j < 4; j++){
        int i = i0 + (j << 8);
        if (i < n4){
            float4 v = ((const float4*)src)[i];
            ((uint2*)dst)[i] = make_uint2(
                pack2(__float2half_rn(v.x), __float2half_rn(v.y)),
                pack2(__float2half_rn(v.z), __float2half_rn(v.w)));
        }
    }
}

// fused 3-way converts
__global__ void cvt3_kernel(const float* __restrict__ s0, int n0,
                            const float* __restrict__ s1, int n1,
                            const float* __restrict__ s2, int n2,
                            h16* __restrict__ d0, h16* __restrict__ d1, h16* __restrict__ d2){
    int total = n0 + n1 + n2;
    int i0 = blockIdx.x*1024 + threadIdx.x;
    #pragma unroll
    for (int j = 0; j < 4; j++){
        int i = i0 + (j << 8);
        if (i < total){
            const float4* src; uint2* dst; int k;
            if (i < n0){ src = (const float4*)s0; dst = (uint2*)d0; k = i; }
            else if (i < n0+n1){ src = (const float4*)s1; dst = (uint2*)d1; k = i - n0; }
            else { src = (const float4*)s2; dst = (uint2*)d2; k = i - n0 - n1; }
            float4 v = src[k];
            dst[k] = make_uint2(
                pack2(__float2half_rn(v.x), __float2half_rn(v.y)),
                pack2(__float2half_rn(v.z), __float2half_rn(v.w)));
        }
    }
}

// ---------------- rmsnorm (fp32 + fp16) ----------------
template<int WF32>
__global__ void rms_kernel(const float* __restrict__ x, float* __restrict__ o32,
                           h16* __restrict__ ohi){
    int row = blockIdx.x;
    const float4* xr = (const float4*)(x + (size_t)row*Cv);
    float4 v = xr[threadIdx.x];
    float ss = v.x*v.x + v.y*v.y + v.z*v.z + v.w*v.w;
    __shared__ float red[8];
    for (int off=16; off>0; off>>=1) ss += __shfl_xor_sync(0xffffffffu, ss, off);
    if ((threadIdx.x & 31) == 0) red[threadIdx.x>>5] = ss;
    __syncthreads();
    if (threadIdx.x < 8){
        float t = red[threadIdx.x];
        for (int off=4; off>0; off>>=1) t += __shfl_xor_sync(0x000000ffu, t, off);
        if (threadIdx.x == 0) red[0] = t;
    }
    __syncthreads();
    float r = rsqrtf(red[0]*(1.0f/Cv) + 1e-6f);
    float4 o = make_float4(v.x*r, v.y*r, v.z*r, v.w*r);
    if (WF32) ((float4*)(o32 + (size_t)row*Cv))[threadIdx.x] = o;
    ((uint2*)(ohi + (size_t)row*Cv))[threadIdx.x] = make_uint2(
        pack2(__float2half_rn(o.x), __float2half_rn(o.y)),
        pack2(__float2half_rn(o.z), __float2half_rn(o.w)));
}

// ---------------- fused x1 + rmsnorm ----------------
__global__ void x1rms_kernel(const float* __restrict__ x, const h16* __restrict__ attnh,
                             const h16* __restrict__ cah, float* __restrict__ x1,
                             h16* __restrict__ ox1h, h16* __restrict__ oxmh){
    int row = blockIdx.x;
    size_t base = (size_t)row*Cv;
    float4 xv = ((const float4*)(x + base))[threadIdx.x];
    uint2 ua = ((const uint2*)(attnh + base))[threadIdx.x];
    uint2 uc = ((const uint2*)(cah + base))[threadIdx.x];
    float2 a01 = __half22float2(*(__half2*)&ua.x), a23 = __half22float2(*(__half2*)&ua.y);
    float2 c01 = __half22float2(*(__half2*)&uc.x), c23 = __half22float2(*(__half2*)&uc.y);
    float4 v;
    v.x = xv.x + a01.x*(1.f + 0.1f*tanh_fast(c01.x));
    v.y = xv.y + a01.y*(1.f + 0.1f*tanh_fast(c01.y));
    v.z = xv.z + a23.x*(1.f + 0.1f*tanh_fast(c23.x));
    v.w = xv.w + a23.y*(1.f + 0.1f*tanh_fast(c23.y));
    float ss = v.x*v.x + v.y*v.y + v.z*v.z + v.w*v.w;
    __shared__ float red[8];
    for (int off=16; off>0; off>>=1) ss += __shfl_xor_sync(0xffffffffu, ss, off);
    if ((threadIdx.x & 31) == 0) red[threadIdx.x>>5] = ss;
    __syncthreads();
    if (threadIdx.x < 8){
        float t = red[threadIdx.x];
        for (int off=4; off>0; off>>=1) t += __shfl_xor_sync(0x000000ffu, t, off);
        if (threadIdx.x == 0) red[0] = t;
    }
    __syncthreads();
    float r = rsqrtf(red[0]*(1.0f/Cv) + 1e-6f);
    ((float4*)(x1 + base))[threadIdx.x] = v;
    ((uint2*)(ox1h + base))[threadIdx.x] = make_uint2(
        pack2(__float2half_rn(v.x), __float2half_rn(v.y)),
        pack2(__float2half_rn(v.z), __float2half_rn(v.w)));
    ((uint2*)(oxmh + base))[threadIdx.x] = make_uint2(
        pack2(__float2half_rn(v.x*r), __float2half_rn(v.y*r)),
        pack2(__float2half_rn(v.z*r), __float2half_rn(v.w*r)));
}

// =================== fp16 GEMM: tile 128x128, supertile rasterization ===================
#define GSTG 16384
#define GEMM_SMEM (4*GSTG)
template<int EPI>
__global__ void __launch_bounds__(256,2)
gemm_f16(const h16* __restrict__ Ah, const h16* __restrict__ Bh,
         float* __restrict__ Cg, h16* __restrict__ Chf,
         const float* __restrict__ X1, const h16* __restrict__ MLPh,
         const h16* __restrict__ CAh, const float* __restrict__ VF,
         float* __restrict__ Og, int N, int K){
    extern __shared__ char smem[];
    const int tid = threadIdx.x, lane = tid & 31, wid = tid >> 5;
    const int warpM = wid & 3, warpN = wid >> 2;   // 4 x 2

    // supertile rasterization: GROUP=8 M-tiles per N-column band
    const int nbx = gridDim.x, nby = gridDim.y;
    int tile = blockIdx.y*nbx + blockIdx.x;
    const int GROUP = 8;
    int band = GROUP*nbx;
    int bandId = tile / band;
    int inb = tile - bandId*band;
    int grp = min(GROUP, nby - bandId*GROUP);
    int by = bandId*GROUP + (inb % grp);
    int bx = inb / grp;

    const int m0 = by << 7, n0 = bx << 7;
    const int b = m0 >> 10, tb = m0 & 1023;
    uint32_t sb = smem_u32(smem);

    const int r = tid >> 2, kc = tid & 3;
    const h16* aP = Ah + (size_t)(m0+r)*K + (kc<<3);
    const h16* bP = Bh + (size_t)(n0+r)*K + (kc<<3);
    const uint32_t dA0 = sw_off(r, kc<<3);
    const uint32_t dA1 = sw_off(r+64, kc<<3);
    const size_t off64 = (size_t)64*K;

    auto ISSUE = [&](int c, int s){
        int k0 = c << 5;
        uint32_t st = sb + s*GSTG;
        cpa16(st + dA0,        aP + k0);
        cpa16(st + dA1,        aP + off64 + k0);
        cpa16(st + 8192 + dA0, bP + k0);
        cpa16(st + 8192 + dA1, bP + off64 + k0);
        CPA_COMMIT();
    };

    float acc[2][8][4];
    #pragma unroll
    for (int i=0;i<2;i++)
        #pragma unroll
        for (int j=0;j<8;j++)
            #pragma unroll
            for (int q=0;q<4;q++) acc[i][j][q]=0.f;

    const int NC = K >> 5;
    ISSUE(0,0); ISSUE(1,1); ISSUE(2,2);
    const int lr = lane & 15, lc = (lane < 16) ? 0 : 8;
    for (int c = 0; c < NC; c++){
        int rem = NC - 1 - c;
        if (rem >= 2) { CPA_WAIT(2); } else if (rem == 1) { CPA_WAIT(1); } else { CPA_WAIT(0); }
        __syncthreads();
        if (c + 3 < NC) ISSUE(c+3, (c+3)&3);
        uint32_t sA = sb + (c&3)*GSTG;
        #pragma unroll
        for (int kk = 0; kk < 32; kk += 16){
            uint32_t ah[2][4];
            #pragma unroll
            for (int mt=0; mt<2; mt++)
                ldsm4(ah[mt], sA + sw_off(warpM*32 + mt*16 + lr, kk + lc));
            #pragma unroll
            for (int nb=0; nb<4; nb++){
                uint32_t bh[4];
                ldsm4(bh, sA + 8192 + sw_off(warpN*64 + nb*16 + lr, kk + lc));
                #pragma unroll
                for (int mt=0; mt<2; mt++){
                    mma16816(acc[mt][nb*2+0], ah[mt], bh[0], bh[2]);
                    mma16816(acc[mt][nb*2+1], ah[mt], bh[1], bh[3]);
                }
            }
        }
    }

    const int g = lane >> 2, t2 = (lane & 3) << 1;
    if (EPI == 0){
        #pragma unroll
        for (int mt=0; mt<2; mt++){
            int m = m0 + warpM*32 + mt*16 + g;
            #pragma unroll
            for (int ni=0; ni<8; ni++){
                int n = n0 + warpN*64 + ni*8 + t2;
                *(float2*)(Cg + (size_t)m*N + n) = make_float2(acc[mt][ni][0], acc[mt][ni][1]);
                *(float2*)(Cg + (size_t)(m+8)*N + n) = make_float2(acc[mt][ni][2], acc[mt][ni][3]);
            }
        }
    } else if (EPI == 3){
        #pragma unroll
        for (int mt=0; mt<2; mt++){
            int m = m0 + warpM*32 + mt*16 + g;
            #pragma unroll
            for (int ni=0; ni<8; ni++){
                int n = n0 + warpN*64 + ni*8 + t2;
                *(uint32_t*)(Chf + (size_t)m*N + n) =
                    pack2(__float2half_rn(acc[mt][ni][0]), __float2half_rn(acc[mt][ni][1]));
                *(uint32_t*)(Chf + (size_t)(m+8)*N + n) =
                    pack2(__float2half_rn(acc[mt][ni][2]), __float2half_rn(acc[mt][ni][3]));
            }
        }
    } else if (EPI == 1){
        float* ep = (float*)smem;   // 64 x 136
        #pragma unroll
        for (int slab=0; slab<2; slab++){
            __syncthreads();
            if (warpN == slab){
                #pragma unroll
                for (int mt=0; mt<2; mt++){
                    int mloc = warpM*32 + mt*16 + g;
                    #pragma unroll
                    for (int ni=0; ni<8; ni++){
                        int nL = ni*8 + t2;
                        ep[nL*136 + mloc]         = acc[mt][ni][0];
                        ep[(nL+1)*136 + mloc]     = acc[mt][ni][1];
                        ep[nL*136 + mloc + 8]     = acc[mt][ni][2];
                        ep[(nL+1)*136 + mloc + 8] = acc[mt][ni][3];
                    }
                }
            }
            __syncthreads();
            #pragma unroll
            for (int i=0;i<8;i++){
                int idx = tid + (i << 8);
                int nr = idx >> 5, t4 = (idx & 31) << 2;
                float a0 = fmaxf(ep[nr*136 + t4 + 0], 0.f);
                float a1 = fmaxf(ep[nr*136 + t4 + 1], 0.f);
                float a2 = fmaxf(ep[nr*136 + t4 + 2], 0.f);
                float a3 = fmaxf(ep[nr*136 + t4 + 3], 0.f);
                int n = n0 + slab*64 + nr;
                size_t o = ((size_t)b*N + n)*1024 + tb + t4;
                *(uint2*)(Chf + o) = make_uint2(
                    pack2(__float2half_rn(a0*a0), __float2half_rn(a1*a1)),
                    pack2(__float2half_rn(a2*a2), __float2half_rn(a3*a3)));
            }
        }
    } else {
        #pragma unroll
        for (int mt=0; mt<2; mt++){
            int m = m0 + warpM*32 + mt*16 + g;
            float vf0 = VF[m], vf1 = VF[m+8];
            #pragma unroll
            for (int ni=0; ni<8; ni++){
                int n = n0 + warpN*64 + ni*8 + t2;
                size_t i0 = (size_t)m*1024 + n;
                size_t i1 = (size_t)(m+8)*1024 + n;
                float2 x0 = *(const float2*)(X1 + i0), x1v = *(const float2*)(X1 + i1);
                uint32_t um0 = *(const uint32_t*)(MLPh + i0), um1 = *(const uint32_t*)(MLPh + i1);
                uint32_t uc0 = *(const uint32_t*)(CAh + i0),  uc1 = *(const uint32_t*)(CAh + i1);
                float2 m0v = __half22float2(*(__half2*)&um0), m1v = __half22float2(*(__half2*)&um1);
                float2 c0v = __half22float2(*(__half2*)&uc0), c1v = __half22float2(*(__half2*)&uc1);
                float2 o0, o1;
                o0.x = x0.x + m0v.x*(0.5f + 0.5f*tanh_fast(0.5f*acc[mt][ni][0]))*(1.f + 0.1f*tanh_fast(c0v.x))*vf0;
                o0.y = x0.y + m0v.y*(0.5f + 0.5f*tanh_fast(0.5f*acc[mt][ni][1]))*(1.f + 0.1f*tanh_fast(c0v.y))*vf0;
                o1.x = x1v.x + m1v.x*(0.5f + 0.5f*tanh_fast(0.5f*acc[mt][ni][2]))*(1.f + 0.1f*tanh_fast(c1v.x))*vf1;
                o1.y = x1v.y + m1v.y*(0.5f + 0.5f*tanh_fast(0.5f*acc[mt][ni][3]))*(1.f + 0.1f*tanh_fast(c1v.y))*vf1;
                *(float2*)(Og + i0) = o0;
                *(float2*)(Og + i1) = o1;
            }
        }
    }
}

// ---------------- small-N (=32) GEMM, fp32 A ----------------
template<int EPI>
__global__ void __launch_bounds__(256)
gemm32_kernel(const float* __restrict__ A, const float* __restrict__ W, float* __restrict__ Cg){
    __shared__ float xs[8*1024];
    int row0 = blockIdx.x << 3;
    #pragma unroll
    for (int i = 0; i < 8; i++){
        int f4 = threadIdx.x + (i << 8);
        ((float4*)xs)[f4] = ((const float4*)(A + ((size_t)row0 << 10)))[f4];
    }
    __syncthreads();
    int w = threadIdx.x >> 5, n = threadIdx.x & 31;
    const float4* Wr = (const float4*)(W + (size_t)n*1024);
    const float4* xr = (const float4*)(xs + (w << 10));
    float acc = 0.f;
    #pragma unroll 4
    for (int k = 0; k < 256; k++){
        float4 a = xr[k], b = Wr[k];
        acc += a.x*b.x + a.y*b.y + a.z*b.z + a.w*b.w;
    }
    if (EPI == 2) acc = 0.5f*acc*(1.f + erff(acc*0.70710678118f));
    Cg[((size_t)(row0 + w) << 5) + n] = acc;
}

// ---------------- small-N (=32) GEMM, fp16 A ----------------
template<int EPI>
__global__ void __launch_bounds__(256)
gemm32h_kernel(const h16* __restrict__ A, const float* __restrict__ W, float* __restrict__ Cg){
    __shared__ float xs[8*1024];
    int row0 = blockIdx.x << 3;
    const uint32_t* ap = (const uint32_t*)(A + ((size_t)row0 << 10));
    #pragma unroll
    for (int i = 0; i < 16; i++){
        int k = threadIdx.x + (i << 8);
        uint32_t u = ap[k];
        float2 f = __half22float2(*(__half2*)&u);
        xs[2*k] = f.x; xs[2*k+1] = f.y;
    }
    __syncthreads();
    int w = threadIdx.x >> 5, n = threadIdx.x & 31;
    const float4* Wr = (const float4*)(W + (size_t)n*1024);
    const float4* xr = (const float4*)(xs + (w << 10));
    float acc = 0.f;
    #pragma unroll 4
    for (int k = 0; k < 256; k++){
        float4 a = xr[k], b = Wr[k];
        acc += a.x*b.x + a.y*b.y + a.z*b.z + a.w*b.w;
    }
    if (EPI == 2) acc = 0.5f*acc*(1.f + erff(acc*0.70710678118f));
    Cg[((size_t)(row0 + w) << 5) + n] = acc;
}

// ---------------- FFMA GEMM (ca_po, K=32) -> fp16 out ----------------
__global__ void __launch_bounds__(256,2)
gemm_k32(const float* __restrict__ A, const float* __restrict__ W,
         h16* __restrict__ Cgh, int N){
    __shared__ float As[32*132];
    __shared__ float Ws[32*132];
    const int tx = threadIdx.x & 15, ty = threadIdx.x >> 4;
    const int m0 = blockIdx.y << 7, n0 = blockIdx.x << 7;
    float acc[8][8];
    #pragma unroll
    for (int i=0;i<8;i++)
        #pragma unroll
        for (int j=0;j<8;j++) acc[i][j]=0.f;
    const int r = threadIdx.x >> 1;
    const int c4 = (threadIdx.x & 1) << 4;
    #pragma unroll
    for (int q=0;q<4;q++){
        float4 a0 = *(const float4*)(A + (size_t)(m0+r)*32 + c4 + q*4);
        As[(c4+q*4+0)*132 + r] = a0.x; As[(c4+q*4+1)*132 + r] = a0.y;
        As[(c4+q*4+2)*132 + r] = a0.z; As[(c4+q*4+3)*132 + r] = a0.w;
        float4 w0 = *(const float4*)(W + (size_t)(n0+r)*32 + c4 + q*4);
        Ws[(c4+q*4+0)*132 + r] = w0.x; Ws[(c4+q*4+1)*132 + r] = w0.y;
        Ws[(c4+q*4+2)*132 + r] = w0.z; Ws[(c4+q*4+3)*132 + r] = w0.w;
    }
    __syncthreads();
    #pragma unroll
    for (int kk=0; kk<32; kk++){
        float av[8], bv[8];
        *(float4*)&av[0] = *(const float4*)(As + kk*132 + (ty<<3));
        *(float4*)&av[4] = *(const float4*)(As + kk*132 + (ty<<3) + 4);
        *(float4*)&bv[0] = *(const float4*)(Ws + kk*132 + (tx<<3));
        *(float4*)&bv[4] = *(const float4*)(Ws + kk*132 + (tx<<3) + 4);
        #pragma unroll
        for (int i=0;i<8;i++)
            #pragma unroll
            for (int j=0;j<8;j++) acc[i][j] += av[i]*bv[j];
    }
    #pragma unroll
    for (int i=0;i<8;i++){
        int mg = m0 + (ty<<3) + i;
        uint4 wv;
        wv.x = pack2(__float2half_rn(acc[i][0]), __float2half_rn(acc[i][1]));
        wv.y = pack2(__float2half_rn(acc[i][2]), __float2half_rn(acc[i][3]));
        wv.z = pack2(__float2half_rn(acc[i][4]), __float2half_rn(acc[i][5]));
        wv.w = pack2(__float2half_rn(acc[i][6]), __float2half_rn(acc[i][7]));
        *(uint4*)(Cgh + (size_t)mg*N + n0 + (tx<<3)) = wv;
    }
}

// ---------------- VE gate + V -> transposed fp16 ----------------
__global__ void vgate_kernel(const float* __restrict__ xn, const float* __restrict__ ve,
                             const float* __restrict__ wg, const float* __restrict__ qkv,
                             h16* __restrict__ vhi){
    int row = blockIdx.x;
    __shared__ float gs[4];
    if (threadIdx.x < 4){
        float s = 0.f;
        #pragma unroll
        for (int c=0;c<12;c++) s += xn[(size_t)row*Cv + c]*wg[threadIdx.x*12 + c];
        gs[threadIdx.x] = 3.f/(1.f + expf(-s));
    }
    __syncthreads();
    int i = threadIdx.x;
    int kv = i >> 6, d = i & 63;
    float vv = qkv[(size_t)row*1536 + 1280 + i] + gs[kv]*ve[(size_t)row*256 + i];
    size_t o = ((size_t)((row>>10)*4 + kv)*64 + d)*1024 + (row & 1023);
    vhi[o] = __float2half_rn(vv);
}

// ---------------- rope + per-head rmsnorm*1.2 -> fp16 ----------------
__global__ void ropeRms_kernel(const float* __restrict__ src, int srcStride, int srcOff,
                               h16* __restrict__ dhi,
                               const float* __restrict__ cosb, const float* __restrict__ sinb,
                               int nheads){
    int row  = blockIdx.x;
    int t    = row & (Tv-1);
    int head = blockIdx.y*4 + (threadIdx.x >> 5);
    if (head >= nheads) return;
    int lane = threadIdx.x & 31;
    const float* p = src + (size_t)row*srcStride + srcOff + head*HD;
    float x1 = p[lane], x2 = p[lane+32];
    float cc = cosb[t*32 + lane], sn = sinb[t*32 + lane];
    float o1 =  x1*cc + x2*sn;
    float o2 = -x1*sn + x2*cc;
    float ss = o1*o1 + o2*o2;
    for (int off=16; off>0; off>>=1) ss += __shfl_xor_sync(0xffffffffu, ss, off);
    float rr = rsqrtf(ss*(1.0f/HD) + 1e-6f)*1.2f;
    size_t base = ((size_t)row*nheads + head)*HD;
    dhi[base+lane]    = __float2half_rn(o1*rr);
    dhi[base+lane+32] = __float2half_rn(o2*rr);
}

// =================== flash attention ===================
#define SM_Q    0
#define SM_KV0  8192
#define SM_KV1  24576
#define SM_PP0  40960
#define SM_PP1  58752
#define SM_S    76544
#define SM_PHI  95488
#define SM_CORR 103680
#define SM_LINV 103936
#define ATTN_SMEM 104192

__global__ void __launch_bounds__(256)
attn_kernel(const h16* __restrict__ qhi,
            const h16* __restrict__ khi, const h16* __restrict__ vhi,
            const float* __restrict__ prev, const float* __restrict__ rw,
            const float* __restrict__ alphap,
            h16* __restrict__ yh){
    extern __shared__ char smc[];
    uint32_t sb = smem_u32(smc);
    float* S      = (float*)(smc + SM_S);
    float* corr_s = (float*)(smc + SM_CORR);
    float* linv   = (float*)(smc + SM_LINV);

    const int tid = threadIdx.x, lane = tid & 31, wid = tid >> 5;
    const int warpM = wid & 3, warpN = wid >> 2;
    const int row = tid >> 2, quad = tid & 3, c0 = quad << 4;
    const int qt = (int)gridDim.x - 1 - (int)blockIdx.x;
    const int h = blockIdx.y, b = blockIdx.z;
    const int q0 = qt << 6;
    const int kvh = h >> 2;
    const int lr = lane & 15, lc = (lane < 16) ? 0 : 8;
    const int g = lane >> 2, t2 = (lane & 3) << 1;
    const float LOG2E = 1.4426950408889634f;

    const float alpha = alphap[0];
    float w9[9];
    #pragma unroll
    for (int i=0;i<9;i++) w9[i] = alpha*rw[h*9 + i];

    const float* prevB = prev + ((size_t)(b*NH + h))*Tv*Tv;

    auto issueKV = [&](int kt, int s){
        int k0 = kt << 6;
        uint32_t kvb = sb + SM_KV0 + s*16384;
        #pragma unroll
        for (int i=0;i<4;i++){
            int idx = tid + (i << 8);
            int arr = idx >> 9, rr = (idx >> 3) & 63, kc = idx & 7;
            const h16* src;
            if (arr == 0) src = khi + ((((size_t)(b*Tv + k0 + rr))*NKV + kvh) << 6) + (kc << 3);
            else          src = vhi + (((size_t)((b*NKV + kvh)*64 + rr)) << 10) + k0 + (kc << 3);
            cpa16(kvb + arr*8192 + sw128(rr, kc << 3), src);
        }
    };
    auto issuePP = [&](int kt, int s){
        int k0 = kt << 6;
        uint32_t ppb = sb + SM_PP0 + s*17792;
        for (int idx = tid; idx < 66*66; idx += 256){
            int i = idx/66, j = idx - i*66;
            int rr = q0 - 1 + i, cg = k0 - 1 + j;
            int ok = (rr >= 0 && rr < Tv && cg >= 0 && cg < Tv) ? 4 : 0;
            int rrc = rr < 0 ? 0 : (rr > 1023 ? 1023 : rr);
            int cgc = cg < 0 ? 0 : (cg > 1023 ? 1023 : cg);
            cpa4z(ppb + (uint32_t)(i*67 + j)*4, prevB + (size_t)rrc*Tv + cgc, ok);
        }
    };

    {
        #pragma unroll
        for (int i=0;i<2;i++){
            int idx = tid + (i << 8);
            int rr = idx >> 3, kc = idx & 7;
            const h16* src = qhi + ((((size_t)(b*Tv + q0 + rr))*NH + h) << 6) + (kc << 3);
            cpa16(sb + SM_Q + sw128(rr, kc << 3), src);
        }
        CPA_COMMIT();
        issueKV(0,0); issuePP(0,0);
        CPA_COMMIT();
    }

    float o[4][4];
    #pragma unroll
    for (int i=0;i<4;i++)
        #pragma unroll
        for (int j=0;j<4;j++) o[i][j]=0.f;
    float m = -1e30f, l = 0.f;

    for (int kt = 0; kt <= qt; kt++){
        int s = kt & 1;
        CPA_WAIT(0);
        __syncthreads();
        if (kt < qt){ issueKV(kt+1, s^1); issuePP(kt+1, s^1); CPA_COMMIT(); }
        uint32_t kvb = sb + SM_KV0 + s*16384;
        float* PP = (float*)(smc + SM_PP0 + s*17792);

        float c[4][4];
        #pragma unroll
        for (int i=0;i<4;i++)
            #pragma unroll
            for (int j=0;j<4;j++) c[i][j]=0.f;
        #pragma unroll
        for (int k16 = 0; k16 < 4; k16++){
            uint32_t qh_[4];
            ldsm4(qh_, sb + SM_Q + sw128(warpM*16 + lr, k16*16 + lc));
            #pragma unroll
            for (int nb=0; nb<2; nb++){
                uint32_t kh_[4];
                ldsm4(kh_, kvb + sw128(warpN*32 + nb*16 + lr, k16*16 + lc));
                mma16816(c[nb*2+0], qh_, kh_[0], kh_[2]);
                mma16816(c[nb*2+1], qh_, kh_[1], kh_[3]);
            }
        }
        #pragma unroll
        for (int ni=0; ni<4; ni++){
            int col = warpN*32 + ni*8 + t2;
            int r0 = warpM*16 + g;
            *(float2*)(S + r0*74 + col)     = make_float2(c[ni][0], c[ni][1]);
            *(float2*)(S + (r0+8)*74 + col) = make_float2(c[ni][2], c[ni][3]);
        }
        __syncthreads();

        float p[3][18];
        #pragma unroll
        for (int i=0;i<3;i++)
            #pragma unroll
            for (int e=0;e<18;e++) p[i][e] = PP[(row+i)*67 + c0 + e];
        float sr[16];
        #pragma unroll
        for (int j=0;j<16;j++){
            float cv = w9[0]*p[0][j] + w9[1]*p[0][j+1] + w9[2]*p[0][j+2]
                     + w9[3]*p[1][j] + w9[4]*p[1][j+1] + w9[5]*p[1][j+2]
                     + w9[6]*p[2][j] + w9[7]*p[2][j+1] + w9[8]*p[2][j+2];
            int col = c0 + j;
            sr[j] = S[row*74 + col]*0.125f + cv;
            if (kt == qt && col > row) sr[j] = -1e30f;
        }
        float mt = sr[0];
        #pragma unroll
        for (int j=1;j<16;j++) mt = fmaxf(mt, sr[j]);
        for (int off=1; off<4; off<<=1) mt = fmaxf(mt, __shfl_xor_sync(0xffffffffu, mt, off));
        float mnew = fmaxf(m, mt);
        float corrv = __expf(m - mnew);
        float ls = 0.f;
        #pragma unroll
        for (int j=0;j<16;j+=2){
            uint32_t pe = ex2_f16x2((sr[j] - mnew)*LOG2E, (sr[j+1] - mnew)*LOG2E);
            *(uint32_t*)(smc + SM_PHI + sw128(row, c0 + j)) = pe;
            float2 fe = __half22float2(*(__half2*)&pe);
            ls += fe.x + fe.y;
        }
        for (int off=1; off<4; off<<=1) ls += __shfl_xor_sync(0xffffffffu, ls, off);
        l = l*corrv + ls;
        m = mnew;
        if (quad == 0) corr_s[row] = corrv;
        __syncthreads();

        float cr0 = corr_s[warpM*16 + g], cr1 = corr_s[warpM*16 + g + 8];
        #pragma unroll
        for (int ni=0; ni<4; ni++){
            o[ni][0] *= cr0; o[ni][1] *= cr0;
            o[ni][2] *= cr1; o[ni][3] *= cr1;
        }
        #pragma unroll
        for (int k16 = 0; k16 < 4; k16++){
            uint32_t ph_[4];
            ldsm4(ph_, sb + SM_PHI + sw128(warpM*16 + lr, k16*16 + lc));
            #pragma unroll
            for (int nb=0; nb<2; nb++){
                uint32_t vh_[4];
                ldsm4(vh_, kvb + 8192 + sw128(warpN*32 + nb*16 + lr, k16*16 + lc));
                mma16816(o[nb*2+0], ph_, vh_[0], vh_[2]);
                mma16816(o[nb*2+1], ph_, vh_[1], vh_[3]);
            }
        }
    }

    if (quad == 0) linv[row] = 1.f/l;
    __syncthreads();
    float i0 = linv[warpM*16 + g], i1 = linv[warpM*16 + g + 8];
    #pragma unroll
    for (int ni=0; ni<4; ni++){
        int col = warpN*32 + ni*8 + t2;
        size_t base0 = ((((size_t)(b*Tv + q0 + warpM*16 + g))*NH + h) << 6) + col;
        size_t base1 = ((((size_t)(b*Tv + q0 + warpM*16 + g + 8))*NH + h) << 6) + col;
        *(uint32_t*)(yh + base0) = pack2(__float2half_rn(o[ni][0]*i0), __float2half_rn(o[ni][1]*i0));
        *(uint32_t*)(yh + base1) = pack2(__float2half_rn(o[ni][2]*i1), __float2half_rn(o[ni][3]*i1));
    }
}

// ---------------- CA conv + gelu ----------------
__global__ void caconv_kernel(const float* __restrict__ hin, const float* __restrict__ cw,
                              float* __restrict__ hout){
    int ch = blockIdx.x, b = blockIdx.y;
    __shared__ float s[Tv+2];
    for (int t = threadIdx.x; t < Tv; t += 256) s[1+t] = hin[((size_t)b*Tv + t)*32 + ch];
    if (threadIdx.x == 0){ s[0] = 0.f; s[Tv+1] = 0.f; }
    __syncthreads();
    float w0 = cw[ch*3], w1 = cw[ch*3+1], w2 = cw[ch*3+2];
    for (int t = threadIdx.x; t < Tv; t += 256){
        float vv = s[1+t] + 0.1f*(w0*s[t] + w1*s[1+t] + w2*s[2+t]);
        hout[((size_t)b*Tv + t)*32 + ch] = 0.5f*vv*(1.f + erff(vv*0.70710678118f));
    }
}

// ---------------- FFN conv x4 ----------------
#define FFNC_SMEM (2*16*1026*4)
__global__ void __launch_bounds__(256)
ffnconvT_kernel(const h16* __restrict__ hf, const float* __restrict__ cw,
                h16* __restrict__ hs){
    extern __shared__ float fs[];
    float (*buf0)[1026] = (float(*)[1026])fs;
    float (*buf1)[1026] = (float(*)[1026])(fs + 16*1026);
    int f0 = blockIdx.x << 4, b = blockIdx.y;
    for (int idx4 = threadIdx.x; idx4 < 16*256; idx4 += 256){
        int cch = idx4 >> 8, t4 = (idx4 & 255) << 2;
        size_t o = ((size_t)(b*FFH + f0 + cch))*Tv + t4;
        uint2 u = *(const uint2*)(hf + o);
        const h16* ph = (const h16*)&u;
        #pragma unroll
        for (int e=0;e<4;e++) buf0[cch][1+t4+e] = __half2float(ph[e]);
    }
    if (threadIdx.x < 16){
        buf0[threadIdx.x][0] = 0.f; buf0[threadIdx.x][1025] = 0.f;
        buf1[threadIdx.x][0] = 0.f; buf1[threadIdx.x][1025] = 0.f;
    }
    int cch = threadIdx.x >> 4, j = threadIdx.x & 15;
    float w0 = cw[(f0+cch)*3], w1 = cw[(f0+cch)*3+1], w2 = cw[(f0+cch)*3+2];
    float (*cur)[1026] = buf0; float (*nxt)[1026] = buf1;
    #pragma unroll
    for (int it=0; it<4; it++){
        __syncthreads();
        #pragma unroll 4
        for (int t = j*64; t < j*64 + 64; t++)
            nxt[cch][1+t] = cur[cch][1+t] + 0.1f*(w0*cur[cch][t] + w1*cur[cch][1+t] + w2*cur[cch][2+t]);
        float (*tmp)[1026] = cur; cur = nxt; nxt = tmp;
    }
    __syncthreads();
    for (int t = threadIdx.x; t < Tv; t += 256){
        uint32_t wv[8];
        #pragma unroll
        for (int cc = 0; cc < 16; cc += 2)
            wv[cc>>1] = pack2(__float2half_rn(cur[cc][1+t]), __float2half_rn(cur[cc+1][1+t]));
        size_t o = ((size_t)(b*Tv + t))*FFH + f0;
        *(uint4*)(hs + o)     = make_uint4(wv[0],wv[1],wv[2],wv[3]);
        *(uint4*)(hs + o + 8) = make_uint4(wv[4],wv[5],wv[6],wv[7]);
    }
}

// ---------------- fused vit2 + vitsmooth ----------------
__global__ void vitfuse_kernel(const float* __restrict__ h32, const float* __restrict__ w2,
                               float* __restrict__ vitf){
    int b = blockIdx.x;
    __shared__ float s[Tv+4];
    __shared__ float w2s[32];
    if (threadIdx.x < 32) w2s[threadIdx.x] = w2[threadIdx.x];
    if (threadIdx.x < 2){ s[threadIdx.x] = 0.f; s[Tv+2+threadIdx.x] = 0.f; }
    __syncthreads();
    for (int t = threadIdx.x; t < Tv; t += 256){
        const float4* hr = (const float4*)(h32 + ((size_t)(b*Tv + t) << 5));
        float acc = 0.f;
        #pragma unroll
        for (int c = 0; c < 8; c++){
            float4 hv = hr[c];
            acc += hv.x*w2s[c*4] + hv.y*w2s[c*4+1] + hv.z*w2s[c*4+2] + hv.w*w2s[c*4+3];
        }
        s[2+t] = 1.f/(1.f + expf(-acc));
    }
    __syncthreads();
    for (int t = threadIdx.x; t < Tv; t += 256){
        float vs = (s[t] + s[t+1] + s[t+2] + s[t+3] + s[t+4])*0.2f;
        float vv = 0.7f*s[2+t] + 0.3f*vs;
        vitf[b*Tv + t] = (vv > 0.3f) ? vv : 0.1f*vv;
    }
}

// ---------------- launch ----------------
extern "C" void kernel_launch(void* const* d_in, const int* in_sizes, int n_in,
                              void* d_out, int out_size){
    const float* x     = (const float*)d_in[0];
    const float* ve    = (const float*)d_in[1];
    const float* cosp  = (const float*)d_in[2];
    const float* sinp  = (const float*)d_in[3];
    const float* prev  = (const float*)d_in[4];
    const float* w_q   = (const float*)d_in[5];
    const float* w_k   = (const float*)d_in[6];
    const float* w_v   = (const float*)d_in[7];
    const float* w_o   = (const float*)d_in[8];
    const float* w_veg = (const float*)d_in[9];
    const float* rfw   = (const float*)d_in[10];
    const float* ralpha= (const float*)d_in[11];
    const float* ca_pi = (const float*)d_in[12];
    const float* ca_cw = (const float*)d_in[13];
    const float* ca_po = (const float*)d_in[14];
    const float* ffn_in= (const float*)d_in[15];
    const float* ffn_cw= (const float*)d_in[16];
    const float* ffn_outw=(const float*)d_in[17];
    const float* ffn_gt= (const float*)d_in[18];
    const float* vit_w1= (const float*)d_in[19];
    const float* vit_w2= (const float*)d_in[20];
    float* out = (float*)d_out;

    float *xn,*qkv,*cah,*cah2,*x1,*vit32,*vitf;
    h16 *xnh,*xmh,*x1h,*attnh,*cah16,*mlph,*yh,*qh,*kh,*vh,*hf,*hs;
    h16 *wqkv,*wo,*fin,*fout,*fgt;
    cudaGetSymbolAddress((void**)&xn, g_xn);     cudaGetSymbolAddress((void**)&qkv, g_qkv);
    cudaGetSymbolAddress((void**)&cah, g_cah);   cudaGetSymbolAddress((void**)&cah2, g_cah2);
    cudaGetSymbolAddress((void**)&x1, g_x1);
    cudaGetSymbolAddress((void**)&vit32, g_vit32);
    cudaGetSymbolAddress((void**)&vitf, g_vitf);
    cudaGetSymbolAddress((void**)&xnh, g_xn_h);
    cudaGetSymbolAddress((void**)&xmh, g_xm_h);
    cudaGetSymbolAddress((void**)&x1h, g_x1_h);
    cudaGetSymbolAddress((void**)&attnh, g_attn_h);
    cudaGetSymbolAddress((void**)&cah16, g_ca_h);
    cudaGetSymbolAddress((void**)&mlph, g_mlp_h);
    cudaGetSymbolAddress((void**)&yh, g_y_h);
    cudaGetSymbolAddress((void**)&qh, g_q_h);
    cudaGetSymbolAddress((void**)&kh, g_k_h);
    cudaGetSymbolAddress((void**)&vh, g_v_h);
    cudaGetSymbolAddress((void**)&hf, g_hf);     cudaGetSymbolAddress((void**)&hs, g_hs);
    cudaGetSymbolAddress((void**)&wqkv, g_wqkv);
    cudaGetSymbolAddress((void**)&wo, g_wo);
    cudaGetSymbolAddress((void**)&fin, g_fin);
    cudaGetSymbolAddress((void**)&fout, g_fout);
    cudaGetSymbolAddress((void**)&fgt, g_fgt);

    cudaFuncSetAttribute(attn_kernel, cudaFuncAttributeMaxDynamicSharedMemorySize, ATTN_SMEM);
    cudaFuncSetAttribute(gemm_f16<0>, cudaFuncAttributeMaxDynamicSharedMemorySize, GEMM_SMEM);
    cudaFuncSetAttribute(gemm_f16<1>, cudaFuncAttributeMaxDynamicSharedMemorySize, GEMM_SMEM);
    cudaFuncSetAttribute(gemm_f16<2>, cudaFuncAttributeMaxDynamicSharedMemorySize, GEMM_SMEM);
    cudaFuncSetAttribute(gemm_f16<3>, cudaFuncAttributeMaxDynamicSharedMemorySize, GEMM_SMEM);
    cudaFuncSetAttribute(ffnconvT_kernel, cudaFuncAttributeMaxDynamicSharedMemorySize, FFNC_SMEM);

    // positions 0-3: rms, cvt3(QKV), cvt(w_o), gemmQKV
    rms_kernel<1><<<MT,256>>>(x, xn, xnh);
    cvt3_kernel<<<384,256>>>(w_q, 262144, w_k, 65536, w_v, 65536,
                             wqkv, wqkv + 1024*1024, wqkv + 1280*1024);
    cvt_kernel<<<256,256>>>(w_o, wo, 262144);
    gemm_f16<0><<<dim3(12,32),256,GEMM_SMEM>>>(xnh, wqkv, qkv, 0, 0,0,0,0, 0, 1536, 1024);

    vgate_kernel<<<MT,256>>>(xn, ve, w_veg, qkv, vh);
    ropeRms_kernel<<<dim3(MT,4),128>>>(qkv, 1536, 0,    qh, cosp, sinp, NH);
    ropeRms_kernel<<<dim3(MT,1),128>>>(qkv, 1536, 1024, kh, cosp, sinp, NKV);

    attn_kernel<<<dim3(16,NH,Bv),256,ATTN_SMEM>>>(qh, kh, vh, prev, rfw, ralpha, yh);
    gemm_f16<3><<<dim3(8,32),256,GEMM_SMEM>>>(yh, wo, 0, attnh, 0,0,0,0, 0, 1024, 1024);

    // fused FFN weight converts
    cvt3_kernel<<<2304,256>>>(ffn_in, 1048576, ffn_outw, 1048576, ffn_gt, 262144,
                              fin, fout, fgt);

    // ca1 on x
    gemm32_kernel<0><<<512,256>>>(x, ca_pi, cah);
    caconv_kernel<<<dim3(32,Bv),256>>>(cah, ca_cw, cah2);
    gemm_k32<<<dim3(8,32),256>>>(cah2, ca_po, cah16, 1024);
    x1rms_kernel<<<MT,256>>>(x, attnh, cah16, x1, x1h, xmh);

    // FFN
    gemm_f16<1><<<dim3(32,32),256,GEMM_SMEM>>>(xmh, fin, 0, hf, 0,0,0,0, 0, FFH, 1024);
    ffnconvT_kernel<<<dim3(256,Bv),256,FFNC_SMEM>>>(hf, ffn_cw, hs);
    gemm_f16<3><<<dim3(8,32),256,GEMM_SMEM>>>(hs, fout, 0, mlph, 0,0,0,0, 0, 1024, 4096);

    // ca2 on x1 (fp16 A)
    gemm32h_kernel<0><<<512,256>>>(x1h, ca_pi, cah);
    caconv_kernel<<<dim3(32,Bv),256>>>(cah, ca_cw, cah2);
    gemm_k32<<<dim3(8,32),256>>>(cah2, ca_po, cah16, 1024);

    // vit gate
    gemm32h_kernel<2><<<512,256>>>(x1h, vit_w1, vit32);
    vitfuse_kernel<<<Bv,256>>>(vit32, vit_w2, vitf);

    // gate GEMM with fused final epilogue -> out
    gemm_f16<2><<<dim3(8,32),256,GEMM_SMEM>>>(xmh, fgt, 0, 0, x1, mlph, cah16, vitf, out, 1024, 1024);
}